// round 2
// baseline (speedup 1.0000x reference)
#include <cuda_runtime.h>
#include <math.h>

#define BB 4
#define TT 4
#define HH 16
#define WW 16
#define SS 1024
#define CC 576
#define NH 8
#define DK 72
#define LL 4
#define PD 192
#define FF 2304

// ---------------- scratch (device globals; no runtime allocation) ----------------
__device__ float g_xf[BB*SS*CC];
__device__ float g_h [BB*SS*CC];
__device__ float g_q [BB*SS*CC];
__device__ float g_k [BB*SS*CC];
__device__ float g_v [BB*SS*CC];
__device__ float g_kt[BB*SS*CC];
__device__ float g_a [BB*SS*CC];
__device__ float g_att[(long)BB*NH*SS*SS];
__device__ float g_ffn[(long)BB*SS*FF];

// ---------------- shift + positional embedding ----------------
__global__ void shiftpos_kernel(const float* __restrict__ x,
                                const float* __restrict__ p0,
                                const float* __restrict__ p1,
                                const float* __restrict__ p2,
                                float* __restrict__ xf) {
    long idx = (long)blockIdx.x * blockDim.x + threadIdx.x;
    if (idx >= (long)BB*SS*CC) return;
    int c = (int)(idx % CC);
    long bs = idx / CC;
    int s = (int)(bs % SS);
    float v = (s == 0) ? 0.f : x[idx - CC];
    int t = s >> 8, hh = (s >> 4) & 15, w = s & 15;
    float p;
    if (c < PD)          p = p0[t * PD + c];
    else if (c < 2 * PD) p = p1[hh * PD + (c - PD)];
    else                 p = p2[w * PD + (c - 2 * PD)];
    xf[idx] = v + p;
}

// ---------------- layernorm (two-pass, matches reference eps placement) ----------------
__device__ __forceinline__ float block_reduce_sum(float v, float* sh) {
    int lane = threadIdx.x & 31, warp = threadIdx.x >> 5;
    #pragma unroll
    for (int o = 16; o; o >>= 1) v += __shfl_down_sync(0xffffffffu, v, o);
    if (lane == 0) sh[warp] = v;
    __syncthreads();
    if (warp == 0) {
        v = (lane < (int)(blockDim.x >> 5)) ? sh[lane] : 0.f;
        #pragma unroll
        for (int o = 16; o; o >>= 1) v += __shfl_down_sync(0xffffffffu, v, o);
        if (lane == 0) sh[0] = v;
    }
    __syncthreads();
    float r = sh[0];
    __syncthreads();
    return r;
}

__global__ void layernorm_kernel(const float* __restrict__ x,
                                 const float* __restrict__ g,
                                 const float* __restrict__ b,
                                 float* __restrict__ y) {
    __shared__ float sh[32];
    long row = blockIdx.x;
    const float* xr = x + row * CC;
    float* yr = y + row * CC;
    float s = 0.f;
    for (int c = threadIdx.x; c < CC; c += blockDim.x) s += xr[c];
    float mu = block_reduce_sum(s, sh) * (1.0f / CC);
    float s2 = 0.f;
    for (int c = threadIdx.x; c < CC; c += blockDim.x) {
        float d = xr[c] - mu;
        s2 += d * d;
    }
    float var = block_reduce_sum(s2, sh) * (1.0f / CC);
    float mult = 1e-5f + rsqrtf(var);
    for (int c = threadIdx.x; c < CC; c += blockDim.x)
        yr[c] = (xr[c] - mu) * mult * g[c] + b[c];
}

// ---------------- repack K -> [B, NH, DK, S] ----------------
__global__ void repack_kt_kernel(const float* __restrict__ k, float* __restrict__ kt) {
    long idx = (long)blockIdx.x * blockDim.x + threadIdx.x;
    if (idx >= (long)BB*SS*CC) return;
    int s = (int)(idx % SS);
    long r = idx / SS;
    int d = (int)(r % DK);
    long r2 = r / DK;
    int h = (int)(r2 % NH);
    int b = (int)(r2 / NH);
    kt[idx] = k[((long)b * SS + s) * CC + h * DK + d];
}

// ---------------- causal softmax (row-wise, zero-fills masked tail) ----------------
__global__ void softmax_kernel(float* __restrict__ att) {
    __shared__ float sh[32];
    int i = blockIdx.x;            // query index
    long z = blockIdx.y;           // b*NH + h
    float* row = att + (z * SS + i) * (long)SS;
    int len = i + 1;

    float m = -INFINITY;
    for (int j = threadIdx.x; j < len; j += blockDim.x) m = fmaxf(m, row[j]);
    // block max reduce
    {
        int lane = threadIdx.x & 31, warp = threadIdx.x >> 5;
        #pragma unroll
        for (int o = 16; o; o >>= 1) m = fmaxf(m, __shfl_down_sync(0xffffffffu, m, o));
        if (lane == 0) sh[warp] = m;
        __syncthreads();
        if (warp == 0) {
            m = (lane < (int)(blockDim.x >> 5)) ? sh[lane] : -INFINITY;
            #pragma unroll
            for (int o = 16; o; o >>= 1) m = fmaxf(m, __shfl_down_sync(0xffffffffu, m, o));
            if (lane == 0) sh[0] = m;
        }
        __syncthreads();
        m = sh[0];
        __syncthreads();
    }
    float sum = 0.f;
    for (int j = threadIdx.x; j < len; j += blockDim.x) {
        float e = expf(row[j] - m);
        row[j] = e;
        sum += e;
    }
    sum = block_reduce_sum(sum, sh);
    float inv = 1.0f / sum;
    for (int j = threadIdx.x; j < len; j += blockDim.x) row[j] *= inv;
    for (int j = len + threadIdx.x; j < SS; j += blockDim.x) row[j] = 0.f;
}

// ---------------- generic tiled GEMM ----------------
// C[z] = alpha * A[z] @ B[z]  (+ epilogue)
// z = blockIdx.z -> (b = z/NH, h = z%NH); operand base += b*offB + h*offH
// EPI: 0 none, 1 +bias, 2 +bias then GeLU2, 3 +bias +resid
#define GBM 64
#define GBN 64
template<int EPI, int BKT>
__global__ void gemm_kernel(const float* __restrict__ A, int lda, long aOffB, long aOffH,
                            const float* __restrict__ Bm, int ldb, long bOffB, long bOffH,
                            float* __restrict__ C, int ldc, long cOffB, long cOffH,
                            const float* __restrict__ bias,
                            const float* __restrict__ resid,
                            int M, int N, int K, float alpha) {
    int z = blockIdx.z;
    int zb = z / NH, zh = z % NH;
    A  += (long)zb * aOffB + (long)zh * aOffH;
    Bm += (long)zb * bOffB + (long)zh * bOffH;
    C  += (long)zb * cOffB + (long)zh * cOffH;
    const float* R = (EPI == 3) ? (resid + (long)zb * cOffB + (long)zh * cOffH) : nullptr;

    __shared__ float As[BKT][GBM + 1];   // +1 pad: conflict-free transposed stores
    __shared__ float Bs[BKT][GBN];

    int tid = threadIdx.x;               // 256 threads
    int tx = tid & 15, ty = tid >> 4;    // 16x16 thread grid, 4x4 microtile
    int m0 = blockIdx.y * GBM, n0 = blockIdx.x * GBN;

    float acc[4][4] = {};

    for (int k0 = 0; k0 < K; k0 += BKT) {
        // load A tile (coalesced in 16/8-wide row chunks), store transposed
        #pragma unroll
        for (int e = tid; e < GBM * BKT; e += 256) {
            int r = e / BKT, c = e % BKT;
            int gm = m0 + r, gk = k0 + c;
            float v = (gm < M && gk < K) ? A[(long)gm * lda + gk] : 0.f;
            As[c][r] = v;
        }
        // load B tile (coalesced)
        #pragma unroll
        for (int e = tid; e < BKT * GBN; e += 256) {
            int r = e / GBN, c = e % GBN;
            int gk = k0 + r, gn = n0 + c;
            float v = (gk < K && gn < N) ? Bm[(long)gk * ldb + gn] : 0.f;
            Bs[r][c] = v;
        }
        __syncthreads();
        #pragma unroll
        for (int k = 0; k < BKT; k++) {
            float a[4], b[4];
            #pragma unroll
            for (int i = 0; i < 4; i++) a[i] = As[k][ty * 4 + i];
            float4 bv = *reinterpret_cast<const float4*>(&Bs[k][tx * 4]);
            b[0] = bv.x; b[1] = bv.y; b[2] = bv.z; b[3] = bv.w;
            #pragma unroll
            for (int i = 0; i < 4; i++)
                #pragma unroll
                for (int j = 0; j < 4; j++)
                    acc[i][j] += a[i] * b[j];
        }
        __syncthreads();
    }

    #pragma unroll
    for (int i = 0; i < 4; i++) {
        int gm = m0 + ty * 4 + i;
        if (gm >= M) continue;
        #pragma unroll
        for (int j = 0; j < 4; j++) {
            int gn = n0 + tx * 4 + j;
            if (gn >= N) continue;
            float v = acc[i][j] * alpha;
            if (EPI == 1) {
                v += bias[gn];
            } else if (EPI == 2) {
                v += bias[gn];
                v = v / (1.0f + expf(-1.702f * v));
            } else if (EPI == 3) {
                v += bias[gn] + R[(long)gm * ldc + gn];
            }
            C[(long)gm * ldc + gn] = v;
        }
    }
}

// ---------------- host orchestration ----------------
extern "C" void kernel_launch(void* const* d_in, const int* in_sizes, int n_in,
                              void* d_out, int out_size) {
    (void)in_sizes; (void)n_in; (void)out_size;
    const float* x     = (const float*)d_in[0];
    const float* pos0  = (const float*)d_in[1];
    const float* pos1  = (const float*)d_in[2];
    const float* pos2  = (const float*)d_in[3];
    const float* ln1_g = (const float*)d_in[4];
    const float* ln1_b = (const float*)d_in[5];
    const float* wq    = (const float*)d_in[6];
    const float* wk    = (const float*)d_in[7];
    const float* wv    = (const float*)d_in[8];
    const float* wo    = (const float*)d_in[9];
    const float* wo_b  = (const float*)d_in[10];
    const float* ln2_g = (const float*)d_in[11];
    const float* ln2_b = (const float*)d_in[12];
    const float* w1    = (const float*)d_in[13];
    const float* b1    = (const float*)d_in[14];
    const float* w2    = (const float*)d_in[15];
    const float* b2    = (const float*)d_in[16];

    float *xf, *h, *q, *k, *v, *kt, *a, *att, *ffn;
    cudaGetSymbolAddress((void**)&xf,  g_xf);
    cudaGetSymbolAddress((void**)&h,   g_h);
    cudaGetSymbolAddress((void**)&q,   g_q);
    cudaGetSymbolAddress((void**)&k,   g_k);
    cudaGetSymbolAddress((void**)&v,   g_v);
    cudaGetSymbolAddress((void**)&kt,  g_kt);
    cudaGetSymbolAddress((void**)&a,   g_a);
    cudaGetSymbolAddress((void**)&att, g_att);
    cudaGetSymbolAddress((void**)&ffn, g_ffn);

    const int M = BB * SS;                       // 4096
    const float scale = 1.0f / sqrtf((float)DK);

    long n_elem = (long)BB * SS * CC;
    int nb = (int)((n_elem + 255) / 256);
    shiftpos_kernel<<<nb, 256>>>(x, pos0, pos1, pos2, xf);

    dim3 gProj(CC / GBN, M / GBM, 1);            // (9, 64)
    dim3 gF1(FF / GBN, M / GBM, 1);              // (36, 64)
    dim3 gScores(SS / GBN, SS / GBM, BB * NH);   // (16, 16, 32)
    dim3 gAV((DK + GBN - 1) / GBN, SS / GBM, BB * NH); // (2, 16, 32)

    for (int l = 0; l < LL; l++) {
        const float* wq_l = wq + (long)l * CC * CC;
        const float* wk_l = wk + (long)l * CC * CC;
        const float* wv_l = wv + (long)l * CC * CC;
        const float* wo_l = wo + (long)l * CC * CC;
        const float* w1_l = w1 + (long)l * CC * FF;
        const float* w2_l = w2 + (long)l * FF * CC;

        // --- attention ---
        layernorm_kernel<<<M, 256>>>(xf, ln1_g + l * CC, ln1_b + l * CC, h);
        gemm_kernel<0,16><<<gProj, 256>>>(h, CC, 0, 0, wq_l, CC, 0, 0,
                                          q, CC, 0, 0, nullptr, nullptr,
                                          M, CC, CC, 1.f);
        gemm_kernel<0,16><<<gProj, 256>>>(h, CC, 0, 0, wk_l, CC, 0, 0,
                                          k, CC, 0, 0, nullptr, nullptr,
                                          M, CC, CC, 1.f);
        gemm_kernel<0,16><<<gProj, 256>>>(h, CC, 0, 0, wv_l, CC, 0, 0,
                                          v, CC, 0, 0, nullptr, nullptr,
                                          M, CC, CC, 1.f);
        repack_kt_kernel<<<nb, 256>>>(k, kt);
        // scores = scale * q @ k^T  (batched over b,h)
        gemm_kernel<0,8><<<gScores, 256>>>(
            q,  CC, (long)SS * CC,       DK,
            kt, SS, (long)NH * DK * SS,  (long)DK * SS,
            att, SS, (long)NH * SS * SS, (long)SS * SS,
            nullptr, nullptr, SS, SS, DK, scale);
        softmax_kernel<<<dim3(SS, BB * NH), 256>>>(att);
        // a = att @ v
        gemm_kernel<0,16><<<gAV, 256>>>(
            att, SS, (long)NH * SS * SS, (long)SS * SS,
            v,   CC, (long)SS * CC,      DK,
            a,   CC, (long)SS * CC,      DK,
            nullptr, nullptr, SS, DK, SS, 1.f);
        // xf = xf + a @ wo + wo_b
        gemm_kernel<3,16><<<gProj, 256>>>(a, CC, 0, 0, wo_l, CC, 0, 0,
                                          xf, CC, 0, 0, wo_b + l * CC, xf,
                                          M, CC, CC, 1.f);

        // --- FFN ---
        layernorm_kernel<<<M, 256>>>(xf, ln2_g + l * CC, ln2_b + l * CC, h);
        gemm_kernel<2,16><<<gF1, 256>>>(h, CC, 0, 0, w1_l, FF, 0, 0,
                                        ffn, FF, 0, 0, b1 + (long)l * FF, nullptr,
                                        M, FF, CC, 1.f);
        float* outp = (l == LL - 1) ? (float*)d_out : xf;
        gemm_kernel<3,16><<<gProj, 256>>>(ffn, FF, 0, 0, w2_l, CC, 0, 0,
                                          outp, CC, 0, 0, b2 + (long)l * CC, xf,
                                          M, CC, FF, 1.f);
    }
}

// round 4
// speedup vs baseline: 3.7651x; 3.7651x over previous
#include <cuda_runtime.h>
#include <cuda_bf16.h>
#include <math.h>
#include <stdint.h>

#define BB 4
#define SS 1024
#define CC 576
#define NH 8
#define DK 72
#define LL 4
#define PD 192
#define FF 2304
#define MM (BB*SS)

#define BM 128
#define BN 128
#define BK 32
#define STAGES 3
#define OPBYTES 8192                 // 128 rows x 64 bytes
#define STAGE_BYTES (4*OPBYTES)      // Ah Al Bh Bl
#define SMEM_DYN (STAGES*STAGE_BYTES)

// ---------------- scratch (device globals; no runtime allocation) ----------------
__device__ __align__(16) float g_xf[MM*CC];
__device__ __align__(16) float g_v [MM*CC];
__device__ __align__(16) float g_att[(long)BB*NH*SS*SS];

__device__ __align__(16) __nv_bfloat16 g_hh[MM*CC],  g_hl[MM*CC];
__device__ __align__(16) __nv_bfloat16 g_qh[MM*CC],  g_ql[MM*CC];
__device__ __align__(16) __nv_bfloat16 g_kh[MM*CC],  g_kl[MM*CC];
__device__ __align__(16) __nv_bfloat16 g_ah[MM*CC],  g_al[MM*CC];
__device__ __align__(16) __nv_bfloat16 g_vth[BB*NH*DK*SS], g_vtl[BB*NH*DK*SS];
__device__ __align__(16) __nv_bfloat16 g_atth[(long)BB*NH*SS*SS], g_attl[(long)BB*NH*SS*SS];
__device__ __align__(16) __nv_bfloat16 g_ffnh[(long)MM*FF], g_ffnl[(long)MM*FF];

// transposed weights [N][K] bf16 hi/lo
#define WQT_OFF 0
#define WKT_OFF (CC*CC)
#define WVT_OFF (2*CC*CC)
#define WOT_OFF (3*CC*CC)
#define W1T_OFF (4*CC*CC)
#define W2T_OFF (4*CC*CC + CC*FF)
#define WLAYER  (4*CC*CC + 2*CC*FF)
__device__ __align__(16) __nv_bfloat16 g_wth[(long)LL*WLAYER];
__device__ __align__(16) __nv_bfloat16 g_wtl[(long)LL*WLAYER];

// ================= PTX helpers =================
__device__ __forceinline__ uint32_t smem_u32(const void* p) {
    uint32_t a;
    asm("{ .reg .u64 t; cvta.to.shared.u64 t, %1; cvt.u32.u64 %0, t; }" : "=r"(a) : "l"(p));
    return a;
}
__device__ __forceinline__ void cpasync16(uint32_t dst, const void* src, int sz) {
    asm volatile("cp.async.cg.shared.global [%0], [%1], 16, %2;"
                 :: "r"(dst), "l"(src), "r"(sz) : "memory");
}
#define CP_COMMIT() asm volatile("cp.async.commit_group;" ::: "memory")
#define CP_WAIT(n)  asm volatile("cp.async.wait_group %0;" :: "n"(n) : "memory")

__device__ __forceinline__ void ldsm4(uint32_t (&r)[4], uint32_t addr) {
    asm volatile("ldmatrix.sync.aligned.m8n8.x4.shared.b16 {%0,%1,%2,%3}, [%4];"
        : "=r"(r[0]), "=r"(r[1]), "=r"(r[2]), "=r"(r[3]) : "r"(addr));
}
__device__ __forceinline__ void mma16816(float (&d)[4], const uint32_t (&a)[4],
                                         uint32_t b0, uint32_t b1) {
    asm volatile("mma.sync.aligned.m16n8k16.row.col.f32.bf16.bf16.f32 "
        "{%0,%1,%2,%3}, {%4,%5,%6,%7}, {%8,%9}, {%0,%1,%2,%3};"
        : "+f"(d[0]), "+f"(d[1]), "+f"(d[2]), "+f"(d[3])
        : "r"(a[0]), "r"(a[1]), "r"(a[2]), "r"(a[3]), "r"(b0), "r"(b1));
}
__device__ __forceinline__ uint32_t swz64(uint32_t o) { return o ^ ((o >> 3) & 0x30); }

// ---------------- shift + positional embedding ----------------
__global__ void shiftpos_kernel(const float* __restrict__ x,
                                const float* __restrict__ p0,
                                const float* __restrict__ p1,
                                const float* __restrict__ p2,
                                float* __restrict__ xf) {
    long idx = (long)blockIdx.x * blockDim.x + threadIdx.x;
    if (idx >= (long)MM*CC) return;
    int c = (int)(idx % CC);
    long bs = idx / CC;
    int s = (int)(bs % SS);
    float v = (s == 0) ? 0.f : x[idx - CC];
    int t = s >> 8, hh = (s >> 4) & 15, w = s & 15;
    float p;
    if (c < PD)          p = p0[t * PD + c];
    else if (c < 2 * PD) p = p1[hh * PD + (c - PD)];
    else                 p = p2[w * PD + (c - 2 * PD)];
    xf[idx] = v + p;
}

// ---------------- reductions ----------------
__device__ __forceinline__ float block_reduce_sum(float v, float* sh) {
    int lane = threadIdx.x & 31, warp = threadIdx.x >> 5;
    #pragma unroll
    for (int o = 16; o; o >>= 1) v += __shfl_down_sync(0xffffffffu, v, o);
    if (lane == 0) sh[warp] = v;
    __syncthreads();
    if (warp == 0) {
        v = (lane < (int)(blockDim.x >> 5)) ? sh[lane] : 0.f;
        #pragma unroll
        for (int o = 16; o; o >>= 1) v += __shfl_down_sync(0xffffffffu, v, o);
        if (lane == 0) sh[0] = v;
    }
    __syncthreads();
    float r = sh[0];
    __syncthreads();
    return r;
}

// ---------------- layernorm -> split bf16 ----------------
__global__ void layernorm_split_kernel(const float* __restrict__ x,
                                       const float* __restrict__ g,
                                       const float* __restrict__ b,
                                       __nv_bfloat16* __restrict__ yh,
                                       __nv_bfloat16* __restrict__ yl) {
    __shared__ float sh[32];
    long row = blockIdx.x;
    const float* xr = x + row * CC;
    float s = 0.f;
    for (int c = threadIdx.x; c < CC; c += blockDim.x) s += xr[c];
    float mu = block_reduce_sum(s, sh) * (1.0f / CC);
    float s2 = 0.f;
    for (int c = threadIdx.x; c < CC; c += blockDim.x) { float d = xr[c] - mu; s2 += d * d; }
    float var = block_reduce_sum(s2, sh) * (1.0f / CC);
    float mult = 1e-5f + rsqrtf(var);
    for (int c = threadIdx.x; c < CC; c += blockDim.x) {
        float y = (xr[c] - mu) * mult * g[c] + b[c];
        __nv_bfloat16 h = __float2bfloat16_rn(y);
        yh[row * CC + c] = h;
        yl[row * CC + c] = __float2bfloat16_rn(y - __bfloat162float(h));
    }
}

// ---------------- causal softmax fp32 -> split bf16 ----------------
__global__ void softmax_split_kernel(const float* __restrict__ att,
                                     __nv_bfloat16* __restrict__ ph,
                                     __nv_bfloat16* __restrict__ pl) {
    __shared__ float sh[32];
    int i = blockIdx.x;
    long z = blockIdx.y;
    const float* row = att + (z * SS + i) * (long)SS;
    __nv_bfloat16* rh = ph + (z * SS + i) * (long)SS;
    __nv_bfloat16* rl = pl + (z * SS + i) * (long)SS;
    int len = i + 1;
    float m = -INFINITY;
    for (int j = threadIdx.x; j < len; j += blockDim.x) m = fmaxf(m, row[j]);
    {
        int lane = threadIdx.x & 31, warp = threadIdx.x >> 5;
        #pragma unroll
        for (int o = 16; o; o >>= 1) m = fmaxf(m, __shfl_down_sync(0xffffffffu, m, o));
        if (lane == 0) sh[warp] = m;
        __syncthreads();
        if (warp == 0) {
            m = (lane < (int)(blockDim.x >> 5)) ? sh[lane] : -INFINITY;
            #pragma unroll
            for (int o = 16; o; o >>= 1) m = fmaxf(m, __shfl_down_sync(0xffffffffu, m, o));
            if (lane == 0) sh[0] = m;
        }
        __syncthreads();
        m = sh[0];
        __syncthreads();
    }
    float sum = 0.f;
    for (int j = threadIdx.x; j < len; j += blockDim.x) sum += __expf(row[j] - m);
    sum = block_reduce_sum(sum, sh);
    float inv = 1.0f / sum;
    for (int j = threadIdx.x; j < len; j += blockDim.x) {
        float p = __expf(row[j] - m) * inv;
        __nv_bfloat16 h = __float2bfloat16_rn(p);
        rh[j] = h;
        rl[j] = __float2bfloat16_rn(p - __bfloat162float(h));
    }
    __nv_bfloat16 z16 = __float2bfloat16_rn(0.f);
    for (int j = len + threadIdx.x; j < SS; j += blockDim.x) { rh[j] = z16; rl[j] = z16; }
}

// ---------------- weight transpose + bf16 hi/lo split: W[K][N] -> T[N][K] ----------------
__global__ void wtrans_kernel(const float* __restrict__ W,
                              __nv_bfloat16* __restrict__ Th,
                              __nv_bfloat16* __restrict__ Tl,
                              int Kd, int Nd) {
    __shared__ float t[32][33];
    int n0 = blockIdx.x * 32, k0 = blockIdx.y * 32;
    int tx = threadIdx.x, ty = threadIdx.y;   // 32 x 8
    #pragma unroll
    for (int r = 0; r < 32; r += 8)
        t[ty + r][tx] = W[(long)(k0 + ty + r) * Nd + (n0 + tx)];
    __syncthreads();
    #pragma unroll
    for (int r = 0; r < 32; r += 8) {
        int nn = n0 + ty + r, kk = k0 + tx;
        float x = t[tx][ty + r];
        __nv_bfloat16 h = __float2bfloat16_rn(x);
        Th[(long)nn * Kd + kk] = h;
        Tl[(long)nn * Kd + kk] = __float2bfloat16_rn(x - __bfloat162float(h));
    }
}

// ---------------- v transpose per head: fp32 [B,S,C] -> split bf16 [B,NH,DK,S] ----------------
__global__ void vtrans_kernel(const float* __restrict__ v,
                              __nv_bfloat16* __restrict__ th,
                              __nv_bfloat16* __restrict__ tl) {
    long idx = (long)blockIdx.x * blockDim.x + threadIdx.x;
    if (idx >= (long)BB*NH*DK*SS) return;
    int s = (int)(idx % SS);
    long r = idx / SS;
    int d = (int)(r % DK);
    long r2 = r / DK;
    int h = (int)(r2 % NH);
    int b = (int)(r2 / NH);
    float x = v[((long)b * SS + s) * CC + h * DK + d];
    __nv_bfloat16 hh = __float2bfloat16_rn(x);
    th[idx] = hh;
    tl[idx] = __float2bfloat16_rn(x - __bfloat162float(hh));
}

// =================== HMMA split-bf16 GEMM ===================
// C[z] = alpha * (Ah+Al)[z] @ (Bh+Bl)[z]^T (+ epilogue), A:[M][K], B:[N][K]
// EPI: 0 fp32, 1 split-bf16 out, 2 +bias+GeLU2 split out, 3 +bias+resid fp32 out
template<int EPI, bool CAUSAL, bool TRIMK>
__global__ void __launch_bounds__(256, 1)
hmma_gemm(const __nv_bfloat16* __restrict__ Ah, const __nv_bfloat16* __restrict__ Al,
          int lda, long aOffB, long aOffH,
          const __nv_bfloat16* __restrict__ Bh, const __nv_bfloat16* __restrict__ Bl,
          int ldb, long bOffB, long bOffH,
          float* __restrict__ C, __nv_bfloat16* __restrict__ Ch, __nv_bfloat16* __restrict__ Cl,
          int ldc, long cOffB, long cOffH,
          const float* __restrict__ bias, const float* __restrict__ resid,
          int M, int N, int K, float alpha) {
    int m0 = blockIdx.y * BM, n0 = blockIdx.x * BN;
    if (CAUSAL && n0 >= m0 + BM) return;

    extern __shared__ char smem[];
    uint32_t sb = smem_u32(smem);
    int tid = threadIdx.x;
    int z = blockIdx.z, zb = z / NH, zh = z % NH;
    Ah += (long)zb * aOffB + (long)zh * aOffH;
    Al += (long)zb * aOffB + (long)zh * aOffH;
    Bh += (long)zb * bOffB + (long)zh * bOffH;
    Bl += (long)zb * bOffB + (long)zh * bOffH;
    long cbase = (long)zb * cOffB + (long)zh * cOffH;

    int Keff = TRIMK ? min(K, m0 + BM) : K;
    int nch = (Keff + BK - 1) / BK;

    auto fill = [&](int chunk) {
        int k0 = chunk * BK;
        uint32_t sbase = sb + (uint32_t)(chunk % STAGES) * STAGE_BYTES;
        #pragma unroll
        for (int i = 0; i < 2; i++) {
            int idx = tid + i * 256;           // 0..511
            int row = idx >> 2, gr = idx & 3;
            int kk = k0 + gr * 8;
            int ksz = (kk + 8 <= Keff) ? 16 : 0;
            uint32_t doff = swz64((uint32_t)row * 64u + (uint32_t)gr * 16u);
            long aoff = (long)(m0 + row) * lda + kk;
            cpasync16(sbase + doff,               Ah + aoff, ksz);
            cpasync16(sbase + OPBYTES + doff,     Al + aoff, ksz);
            int nn = n0 + row;
            int bsz = (nn < N) ? ksz : 0;
            long boff = (long)min(nn, N - 1) * ldb + kk;
            cpasync16(sbase + 2*OPBYTES + doff,   Bh + boff, bsz);
            cpasync16(sbase + 3*OPBYTES + doff,   Bl + boff, bsz);
        }
    };

    fill(0); CP_COMMIT();
    if (nch > 1) fill(1);
    CP_COMMIT();

    int lane = tid & 31, wid = tid >> 5;
    int wm = wid & 1, wn = wid >> 1;           // warp grid 2 (M) x 4 (N)
    int lr = lane & 15, lc = lane >> 4;

    float acc[4][4][4] = {};

    for (int c = 0; c < nch; c++) {
        if (c + 2 < nch) fill(c + 2);
        CP_COMMIT();
        CP_WAIT(2);
        __syncthreads();
        uint32_t sbase = sb + (uint32_t)(c % STAGES) * STAGE_BYTES;
        #pragma unroll
        for (int ks = 0; ks < 2; ks++) {
            uint32_t ah[4][4], al[4][4], bh[4][2], bl[4][2];
            #pragma unroll
            for (int mt = 0; mt < 4; mt++) {
                uint32_t off = swz64((uint32_t)(wm*64 + mt*16 + lr) * 64u
                                     + (uint32_t)(ks*32 + lc*16));
                ldsm4(ah[mt], sbase + off);
                ldsm4(al[mt], sbase + OPBYTES + off);
            }
            #pragma unroll
            for (int np = 0; np < 2; np++) {
                uint32_t off = swz64((uint32_t)(wn*32 + np*16 + lr) * 64u
                                     + (uint32_t)(ks*32 + lc*16));
                uint32_t t[4];
                ldsm4(t, sbase + 2*OPBYTES + off);
                bh[2*np][0] = t[0]; bh[2*np+1][0] = t[1];
                bh[2*np][1] = t[2]; bh[2*np+1][1] = t[3];
                ldsm4(t, sbase + 3*OPBYTES + off);
                bl[2*np][0] = t[0]; bl[2*np+1][0] = t[1];
                bl[2*np][1] = t[2]; bl[2*np+1][1] = t[3];
            }
            #pragma unroll
            for (int mt = 0; mt < 4; mt++)
                #pragma unroll
                for (int nt = 0; nt < 4; nt++) {
                    mma16816(acc[mt][nt], ah[mt], bh[nt][0], bh[nt][1]);
                    mma16816(acc[mt][nt], ah[mt], bl[nt][0], bl[nt][1]);
                    mma16816(acc[mt][nt], al[mt], bh[nt][0], bh[nt][1]);
                }
        }
        __syncthreads();
    }

    // ---------------- epilogue (fragment-direct) ----------------
    int r0 = lane >> 2, c0 = (lane & 3) * 2;
    #pragma unroll
    for (int mt = 0; mt < 4; mt++) {
        #pragma unroll
        for (int nt = 0; nt < 4; nt++) {
            int gn = n0 + wn*32 + nt*8 + c0;
            if (gn >= N) continue;
            int gmb = m0 + wm*64 + mt*16 + r0;
            float* ac = acc[mt][nt];
            #pragma unroll
            for (int h2 = 0; h2 < 2; h2++) {
                int gm = gmb + h2 * 8;
                float v0 = ac[h2*2 + 0] * alpha;
                float v1 = ac[h2*2 + 1] * alpha;
                long off = cbase + (long)gm * ldc + gn;
                if (EPI == 0) {
                    *(float2*)&C[off] = make_float2(v0, v1);
                } else if (EPI == 1) {
                    __nv_bfloat162 hv, lv;
                    hv.x = __float2bfloat16_rn(v0);
                    hv.y = __float2bfloat16_rn(v1);
                    lv.x = __float2bfloat16_rn(v0 - __bfloat162float(hv.x));
                    lv.y = __float2bfloat16_rn(v1 - __bfloat162float(hv.y));
                    *(__nv_bfloat162*)&Ch[off] = hv;
                    *(__nv_bfloat162*)&Cl[off] = lv;
                } else if (EPI == 2) {
                    v0 += bias[gn]; v1 += bias[gn + 1];
                    v0 = v0 / (1.f + __expf(-1.702f * v0));
                    v1 = v1 / (1.f + __expf(-1.702f * v1));
                    __nv_bfloat162 hv, lv;
                    hv.x = __float2bfloat16_rn(v0);
                    hv.y = __float2bfloat16_rn(v1);
                    lv.x = __float2bfloat16_rn(v0 - __bfloat162float(hv.x));
                    lv.y = __float2bfloat16_rn(v1 - __bfloat162float(hv.y));
                    *(__nv_bfloat162*)&Ch[off] = hv;
                    *(__nv_bfloat162*)&Cl[off] = lv;
                } else { // EPI == 3
                    float2 r = *(const float2*)&resid[off];
                    v0 += bias[gn] + r.x;
                    v1 += bias[gn + 1] + r.y;
                    *(float2*)&C[off] = make_float2(v0, v1);
                }
            }
        }
    }
}

// ---------------- host orchestration ----------------
extern "C" void kernel_launch(void* const* d_in, const int* in_sizes, int n_in,
                              void* d_out, int out_size) {
    (void)in_sizes; (void)n_in; (void)out_size;
    const float* x     = (const float*)d_in[0];
    const float* pos0  = (const float*)d_in[1];
    const float* pos1  = (const float*)d_in[2];
    const float* pos2  = (const float*)d_in[3];
    const float* ln1_g = (const float*)d_in[4];
    const float* ln1_b = (const float*)d_in[5];
    const float* wq    = (const float*)d_in[6];
    const float* wk    = (const float*)d_in[7];
    const float* wv    = (const float*)d_in[8];
    const float* wo    = (const float*)d_in[9];
    const float* wo_b  = (const float*)d_in[10];
    const float* ln2_g = (const float*)d_in[11];
    const float* ln2_b = (const float*)d_in[12];
    const float* w1    = (const float*)d_in[13];
    const float* b1    = (const float*)d_in[14];
    const float* w2    = (const float*)d_in[15];
    const float* b2    = (const float*)d_in[16];

    float *xf, *v, *att;
    __nv_bfloat16 *hh,*hl,*qh,*ql,*kh,*kl,*ah,*al,*vth,*vtl,*atth,*attl,*ffnh,*ffnl,*wth,*wtl;
    cudaGetSymbolAddress((void**)&xf,   g_xf);
    cudaGetSymbolAddress((void**)&v,    g_v);
    cudaGetSymbolAddress((void**)&att,  g_att);
    cudaGetSymbolAddress((void**)&hh,   g_hh);   cudaGetSymbolAddress((void**)&hl,   g_hl);
    cudaGetSymbolAddress((void**)&qh,   g_qh);   cudaGetSymbolAddress((void**)&ql,   g_ql);
    cudaGetSymbolAddress((void**)&kh,   g_kh);   cudaGetSymbolAddress((void**)&kl,   g_kl);
    cudaGetSymbolAddress((void**)&ah,   g_ah);   cudaGetSymbolAddress((void**)&al,   g_al);
    cudaGetSymbolAddress((void**)&vth,  g_vth);  cudaGetSymbolAddress((void**)&vtl,  g_vtl);
    cudaGetSymbolAddress((void**)&atth, g_atth); cudaGetSymbolAddress((void**)&attl, g_attl);
    cudaGetSymbolAddress((void**)&ffnh, g_ffnh); cudaGetSymbolAddress((void**)&ffnl, g_ffnl);
    cudaGetSymbolAddress((void**)&wth,  g_wth);  cudaGetSymbolAddress((void**)&wtl,  g_wtl);

    cudaFuncSetAttribute(hmma_gemm<0,false,false>, cudaFuncAttributeMaxDynamicSharedMemorySize, SMEM_DYN);
    cudaFuncSetAttribute(hmma_gemm<0,true ,false>, cudaFuncAttributeMaxDynamicSharedMemorySize, SMEM_DYN);
    cudaFuncSetAttribute(hmma_gemm<1,false,false>, cudaFuncAttributeMaxDynamicSharedMemorySize, SMEM_DYN);
    cudaFuncSetAttribute(hmma_gemm<1,false,true >, cudaFuncAttributeMaxDynamicSharedMemorySize, SMEM_DYN);
    cudaFuncSetAttribute(hmma_gemm<2,false,false>, cudaFuncAttributeMaxDynamicSharedMemorySize, SMEM_DYN);
    cudaFuncSetAttribute(hmma_gemm<3,false,false>, cudaFuncAttributeMaxDynamicSharedMemorySize, SMEM_DYN);

    const float scale = 1.0f / sqrtf((float)DK);
    long n_elem = (long)MM * CC;
    int nb = (int)((n_elem + 255) / 256);

    shiftpos_kernel<<<nb, 256>>>(x, pos0, pos1, pos2, xf);

    dim3 thr(32, 8);
    for (int l = 0; l < LL; l++) {
        long wb = (long)l * WLAYER;
        wtrans_kernel<<<dim3(CC/32, CC/32), thr>>>(wq + (long)l*CC*CC, wth + wb + WQT_OFF, wtl + wb + WQT_OFF, CC, CC);
        wtrans_kernel<<<dim3(CC/32, CC/32), thr>>>(wk + (long)l*CC*CC, wth + wb + WKT_OFF, wtl + wb + WKT_OFF, CC, CC);
        wtrans_kernel<<<dim3(CC/32, CC/32), thr>>>(wv + (long)l*CC*CC, wth + wb + WVT_OFF, wtl + wb + WVT_OFF, CC, CC);
        wtrans_kernel<<<dim3(CC/32, CC/32), thr>>>(wo + (long)l*CC*CC, wth + wb + WOT_OFF, wtl + wb + WOT_OFF, CC, CC);
        wtrans_kernel<<<dim3(FF/32, CC/32), thr>>>(w1 + (long)l*CC*FF, wth + wb + W1T_OFF, wtl + wb + W1T_OFF, CC, FF);
        wtrans_kernel<<<dim3(CC/32, FF/32), thr>>>(w2 + (long)l*CC*FF, wth + wb + W2T_OFF, wtl + wb + W2T_OFF, FF, CC);
    }

    dim3 gProj(5, MM/BM, 1);                 // N=576
    dim3 gScores(SS/BN, SS/BM, BB*NH);       // 8x8x32, causal-skipped
    dim3 gAV(1, SS/BM, BB*NH);               // N=72
    dim3 gF1(FF/BN, MM/BM, 1);               // 18x32

    for (int l = 0; l < LL; l++) {
        long wb = (long)l * WLAYER;
        // --- attention ---
        layernorm_split_kernel<<<MM, 256>>>(xf, ln1_g + l*CC, ln1_b + l*CC, hh, hl);
        hmma_gemm<1,false,false><<<gProj, 256, SMEM_DYN>>>(
            hh, hl, CC, 0, 0, wth + wb + WQT_OFF, wtl + wb + WQT_OFF, CC, 0, 0,
            nullptr, qh, ql, CC, 0, 0, nullptr, nullptr, MM, CC, CC, 1.f);
        hmma_gemm<1,false,false><<<gProj, 256, SMEM_DYN>>>(
            hh, hl, CC, 0, 0, wth + wb + WKT_OFF, wtl + wb + WKT_OFF, CC, 0, 0,
            nullptr, kh, kl, CC, 0, 0, nullptr, nullptr, MM, CC, CC, 1.f);
        hmma_gemm<0,false,false><<<gProj, 256, SMEM_DYN>>>(
            hh, hl, CC, 0, 0, wth + wb + WVT_OFF, wtl + wb + WVT_OFF, CC, 0, 0,
            v, nullptr, nullptr, CC, 0, 0, nullptr, nullptr, MM, CC, CC, 1.f);
        vtrans_kernel<<<(int)(((long)BB*NH*DK*SS + 255)/256), 256>>>(v, vth, vtl);
        // scores = scale * q @ k^T (batched b,h; lower-tri tiles only)
        hmma_gemm<0,true,false><<<gScores, 256, SMEM_DYN>>>(
            qh, ql, CC, (long)SS*CC, DK,
            kh, kl, CC, (long)SS*CC, DK,
            att, nullptr, nullptr, SS, (long)NH*SS*SS, (long)SS*SS,
            nullptr, nullptr, SS, SS, DK, scale);
        softmax_split_kernel<<<dim3(SS, BB*NH), 256>>>(att, atth, attl);
        // a = att @ v   (K trimmed to causal extent)
        hmma_gemm<1,false,true><<<gAV, 256, SMEM_DYN>>>(
            atth, attl, SS, (long)NH*SS*SS, (long)SS*SS,
            vth, vtl, SS, (long)NH*DK*SS, (long)DK*SS,
            nullptr, ah, al, CC, (long)SS*CC, DK,
            nullptr, nullptr, SS, DK, SS, 1.f);
        // xf = xf + a @ wo + wo_b
        hmma_gemm<3,false,false><<<gProj, 256, SMEM_DYN>>>(
            ah, al, CC, 0, 0, wth + wb + WOT_OFF, wtl + wb + WOT_OFF, CC, 0, 0,
            xf, nullptr, nullptr, CC, 0, 0, wo_b + l*CC, xf, MM, CC, CC, 1.f);

        // --- FFN ---
        layernorm_split_kernel<<<MM, 256>>>(xf, ln2_g + l*CC, ln2_b + l*CC, hh, hl);
        hmma_gemm<2,false,false><<<gF1, 256, SMEM_DYN>>>(
            hh, hl, CC, 0, 0, wth + wb + W1T_OFF, wtl + wb + W1T_OFF, CC, 0, 0,
            nullptr, ffnh, ffnl, FF, 0, 0, b1 + (long)l*FF, nullptr, MM, FF, CC, 1.f);
        float* outp = (l == LL - 1) ? (float*)d_out : xf;
        hmma_gemm<3,false,false><<<gProj, 256, SMEM_DYN>>>(
            ffnh, ffnl, FF, 0, 0, wth + wb + W2T_OFF, wtl + wb + W2T_OFF, FF, 0, 0,
            outp, nullptr, nullptr, CC, 0, 0, b2 + (long)l*CC, xf, MM, CC, FF, 1.f);
    }
}

// round 6
// speedup vs baseline: 5.8736x; 1.5600x over previous
#include <cuda_runtime.h>
#include <cuda_bf16.h>
#include <cuda_fp16.h>
#include <math.h>
#include <stdint.h>

#define BB 4
#define SS 1024
#define CC 576
#define NH 8
#define DK 72
#define LL 4
#define PD 192
#define FF 2304
#define MM (BB*SS)
#define QKVN (3*CC)          // 1728

#define BM 128
#define BK 32
#define STAGES 3

// ---------------- scratch (device globals; no runtime allocation) ----------------
__device__ __align__(16) float g_xf[MM*CC];
__device__ __align__(16) float g_att[(long)BB*NH*SS*SS];

__device__ __align__(16) __nv_bfloat16 g_hh[MM*CC],  g_hl[MM*CC];
__device__ __align__(16) __nv_bfloat16 g_qkvh[(long)MM*QKVN], g_qkvl[(long)MM*QKVN];
__device__ __align__(16) __nv_bfloat16 g_ah[MM*CC],  g_al[MM*CC];
__device__ __align__(16) __half        g_attp[(long)BB*NH*SS*SS];
__device__ __align__(16) __half        g_vth[BB*NH*DK*SS], g_vtl[BB*NH*DK*SS];
__device__ __align__(16) __nv_bfloat16 g_ffnh[(long)MM*FF], g_ffnl[(long)MM*FF];

// transposed weights [N][K] bf16 hi/lo
#define WQT_OFF 0
#define WKT_OFF (CC*CC)
#define WVT_OFF (2*CC*CC)
#define WOT_OFF (3*CC*CC)
#define W1T_OFF (4*CC*CC)
#define W2T_OFF (4*CC*CC + CC*FF)
#define WLAYER  (4*CC*CC + 2*CC*FF)
__device__ __align__(16) __nv_bfloat16 g_wth[(long)LL*WLAYER];
__device__ __align__(16) __nv_bfloat16 g_wtl[(long)LL*WLAYER];

// ================= PTX helpers =================
__device__ __forceinline__ uint32_t smem_u32(const void* p) {
    uint32_t a;
    asm("{ .reg .u64 t; cvta.to.shared.u64 t, %1; cvt.u32.u64 %0, t; }" : "=r"(a) : "l"(p));
    return a;
}
__device__ __forceinline__ void cpasync16(uint32_t dst, const void* src, int sz) {
    asm volatile("cp.async.cg.shared.global [%0], [%1], 16, %2;"
                 :: "r"(dst), "l"(src), "r"(sz) : "memory");
}
#define CP_COMMIT() asm volatile("cp.async.commit_group;" ::: "memory")
#define CP_WAIT(n)  asm volatile("cp.async.wait_group %0;" :: "n"(n) : "memory")

__device__ __forceinline__ void ldsm4(uint32_t (&r)[4], uint32_t addr) {
    asm volatile("ldmatrix.sync.aligned.m8n8.x4.shared.b16 {%0,%1,%2,%3}, [%4];"
        : "=r"(r[0]), "=r"(r[1]), "=r"(r[2]), "=r"(r[3]) : "r"(addr));
}
template<bool FP16>
__device__ __forceinline__ void mma16816(float (&d)[4], const uint32_t (&a)[4],
                                         uint32_t b0, uint32_t b1) {
    if (FP16)
        asm volatile("mma.sync.aligned.m16n8k16.row.col.f32.f16.f16.f32 "
            "{%0,%1,%2,%3}, {%4,%5,%6,%7}, {%8,%9}, {%0,%1,%2,%3};"
            : "+f"(d[0]), "+f"(d[1]), "+f"(d[2]), "+f"(d[3])
            : "r"(a[0]), "r"(a[1]), "r"(a[2]), "r"(a[3]), "r"(b0), "r"(b1));
    else
        asm volatile("mma.sync.aligned.m16n8k16.row.col.f32.bf16.bf16.f32 "
            "{%0,%1,%2,%3}, {%4,%5,%6,%7}, {%8,%9}, {%0,%1,%2,%3};"
            : "+f"(d[0]), "+f"(d[1]), "+f"(d[2]), "+f"(d[3])
            : "r"(a[0]), "r"(a[1]), "r"(a[2]), "r"(a[3]), "r"(b0), "r"(b1));
}
__device__ __forceinline__ uint32_t swz64(uint32_t o) { return o ^ ((o >> 3) & 0x30); }

// ---------------- shift + positional embedding ----------------
__global__ void shiftpos_kernel(const float* __restrict__ x,
                                const float* __restrict__ p0,
                                const float* __restrict__ p1,
                                const float* __restrict__ p2,
                                float* __restrict__ xf) {
    long idx = (long)blockIdx.x * blockDim.x + threadIdx.x;
    if (idx >= (long)MM*CC) return;
    int c = (int)(idx % CC);
    long bs = idx / CC;
    int s = (int)(bs % SS);
    float v = (s == 0) ? 0.f : x[idx - CC];
    int t = s >> 8, hh = (s >> 4) & 15, w = s & 15;
    float p;
    if (c < PD)          p = p0[t * PD + c];
    else if (c < 2 * PD) p = p1[hh * PD + (c - PD)];
    else                 p = p2[w * PD + (c - 2 * PD)];
    xf[idx] = v + p;
}

// ---------------- reductions ----------------
__device__ __forceinline__ float block_reduce_sum(float v, float* sh) {
    int lane = threadIdx.x & 31, warp = threadIdx.x >> 5;
    #pragma unroll
    for (int o = 16; o; o >>= 1) v += __shfl_down_sync(0xffffffffu, v, o);
    if (lane == 0) sh[warp] = v;
    __syncthreads();
    if (warp == 0) {
        v = (lane < (int)(blockDim.x >> 5)) ? sh[lane] : 0.f;
        #pragma unroll
        for (int o = 16; o; o >>= 1) v += __shfl_down_sync(0xffffffffu, v, o);
        if (lane == 0) sh[0] = v;
    }
    __syncthreads();
    float r = sh[0];
    __syncthreads();
    return r;
}

// ---------------- layernorm -> split bf16 ----------------
__global__ void layernorm_split_kernel(const float* __restrict__ x,
                                       const float* __restrict__ g,
                                       const float* __restrict__ b,
                                       __nv_bfloat16* __restrict__ yh,
                                       __nv_bfloat16* __restrict__ yl) {
    __shared__ float sh[32];
    long row = blockIdx.x;
    const float* xr = x + row * CC;
    float s = 0.f;
    for (int c = threadIdx.x; c < CC; c += blockDim.x) s += xr[c];
    float mu = block_reduce_sum(s, sh) * (1.0f / CC);
    float s2 = 0.f;
    for (int c = threadIdx.x; c < CC; c += blockDim.x) { float d = xr[c] - mu; s2 += d * d; }
    float var = block_reduce_sum(s2, sh) * (1.0f / CC);
    float mult = 1e-5f + rsqrtf(var);
    for (int c = threadIdx.x; c < CC; c += blockDim.x) {
        float y = (xr[c] - mu) * mult * g[c] + b[c];
        __nv_bfloat16 h = __float2bfloat16_rn(y);
        yh[row * CC + c] = h;
        yl[row * CC + c] = __float2bfloat16_rn(y - __bfloat162float(h));
    }
}

// ---------------- causal softmax fp32 -> fp16 ----------------
__global__ void softmax_kernel(const float* __restrict__ att,
                               __half* __restrict__ ph) {
    __shared__ float sh[32];
    int i = blockIdx.x;
    long z = blockIdx.y;
    const float* row = att + (z * SS + i) * (long)SS;
    __half* rh = ph + (z * SS + i) * (long)SS;
    int len = i + 1;
    float m = -INFINITY;
    for (int j = threadIdx.x; j < len; j += blockDim.x) m = fmaxf(m, row[j]);
    {
        int lane = threadIdx.x & 31, warp = threadIdx.x >> 5;
        #pragma unroll
        for (int o = 16; o; o >>= 1) m = fmaxf(m, __shfl_down_sync(0xffffffffu, m, o));
        if (lane == 0) sh[warp] = m;
        __syncthreads();
        if (warp == 0) {
            m = (lane < (int)(blockDim.x >> 5)) ? sh[lane] : -INFINITY;
            #pragma unroll
            for (int o = 16; o; o >>= 1) m = fmaxf(m, __shfl_down_sync(0xffffffffu, m, o));
            if (lane == 0) sh[0] = m;
        }
        __syncthreads();
        m = sh[0];
        __syncthreads();
    }
    float sum = 0.f;
    for (int j = threadIdx.x; j < len; j += blockDim.x) sum += __expf(row[j] - m);
    sum = block_reduce_sum(sum, sh);
    float inv = 1.0f / sum;
    for (int j = threadIdx.x; j < len; j += blockDim.x)
        rh[j] = __float2half_rn(__expf(row[j] - m) * inv);
    __half z16 = __float2half_rn(0.f);
    for (int j = len + threadIdx.x; j < SS; j += blockDim.x) rh[j] = z16;
}

// ---------------- weight transpose + bf16 hi/lo split (batched over layers) ----------------
__global__ void wtrans_kernel(const float* __restrict__ W,
                              __nv_bfloat16* __restrict__ Th,
                              __nv_bfloat16* __restrict__ Tl,
                              int Kd, int Nd, long wstride, long tstride) {
    __shared__ float t[32][33];
    W  += (long)blockIdx.z * wstride;
    Th += (long)blockIdx.z * tstride;
    Tl += (long)blockIdx.z * tstride;
    int n0 = blockIdx.x * 32, k0 = blockIdx.y * 32;
    int tx = threadIdx.x, ty = threadIdx.y;   // 32 x 8
    #pragma unroll
    for (int r = 0; r < 32; r += 8)
        t[ty + r][tx] = W[(long)(k0 + ty + r) * Nd + (n0 + tx)];
    __syncthreads();
    #pragma unroll
    for (int r = 0; r < 32; r += 8) {
        int nn = n0 + ty + r, kk = k0 + tx;
        float x = t[tx][ty + r];
        __nv_bfloat16 h = __float2bfloat16_rn(x);
        Th[(long)nn * Kd + kk] = h;
        Tl[(long)nn * Kd + kk] = __float2bfloat16_rn(x - __bfloat162float(h));
    }
}

// ---------------- v transpose per head: qkv split cols [1152,1728) -> fp16 [B,NH,DK,S] ----------------
__global__ void vtrans_kernel(const __nv_bfloat16* __restrict__ qh,
                              const __nv_bfloat16* __restrict__ ql,
                              __half* __restrict__ th,
                              __half* __restrict__ tl) {
    long idx = (long)blockIdx.x * blockDim.x + threadIdx.x;
    if (idx >= (long)BB*NH*DK*SS) return;
    int s = (int)(idx % SS);
    long r = idx / SS;
    int d = (int)(r % DK);
    long r2 = r / DK;
    int h = (int)(r2 % NH);
    int b = (int)(r2 / NH);
    long src = (long)(b * SS + s) * QKVN + 2*CC + h * DK + d;
    float x = __bfloat162float(qh[src]) + __bfloat162float(ql[src]);
    __half hh = __float2half_rn(x);
    th[idx] = hh;
    tl[idx] = __float2half_rn(x - __half2float(hh));
}

// =================== HMMA split GEMM ===================
// C[z] = alpha * (Ah[+Al]) @ (Bh[+Bl])^T (+ epilogue), A:[M][K], B:[N][K]
// terms: ah*bh (+ ah*bl if B2) (+ al*bh if A2)
// EPI: 0 fp32, 1 split-bf16 out, 2 +bias+GeLU2 split out, 3 +bias+resid fp32 out
template<int EPI, bool CAUSAL, bool TRIMK, bool A2, bool B2, bool FP16, int NT>
__global__ void __launch_bounds__(256, 1)
hmma_gemm(const uint16_t* __restrict__ Ah, const uint16_t* __restrict__ Al,
          int lda, long aOffB, long aOffH,
          const uint16_t* __restrict__ Bh, const uint16_t* __restrict__ Bl,
          int ldb, long bOffB, long bOffH,
          float* __restrict__ C, __nv_bfloat16* __restrict__ Ch, __nv_bfloat16* __restrict__ Cl,
          int ldc, long cOffB, long cOffH,
          const float* __restrict__ bias, const float* __restrict__ resid,
          int M, int N, int K, float alpha) {
    constexpr int BN = 32 * NT;
    constexpr uint32_t OPA = 8192;             // 128 rows x 64B
    constexpr uint32_t OPB = (uint32_t)BN * 64;
    constexpr uint32_t OFF_AL = OPA;           // valid when A2
    constexpr uint32_t OFF_BH = OPA * (A2 ? 2 : 1);
    constexpr uint32_t OFF_BL = OFF_BH + OPB;
    constexpr uint32_t STAGE = OFF_BH + OPB * (B2 ? 2 : 1);

    int m0 = blockIdx.y * BM, n0 = blockIdx.x * BN;
    if (CAUSAL && n0 >= m0 + BM) return;

    extern __shared__ char smem[];
    uint32_t sb = smem_u32(smem);
    int tid = threadIdx.x;
    int z = blockIdx.z, zb = z / NH, zh = z % NH;
    Ah += (long)zb * aOffB + (long)zh * aOffH;
    if (A2) Al += (long)zb * aOffB + (long)zh * aOffH;
    Bh += (long)zb * bOffB + (long)zh * bOffH;
    if (B2) Bl += (long)zb * bOffB + (long)zh * bOffH;
    long cbase = (long)zb * cOffB + (long)zh * cOffH;

    int Keff = TRIMK ? min(K, m0 + BM) : K;
    int nch = (Keff + BK - 1) / BK;

    auto fill = [&](int chunk) {
        int k0 = chunk * BK;
        uint32_t sbase = sb + (uint32_t)(chunk % STAGES) * STAGE;
        const int ATOT = BM * 4, BTOT = BN * 4;
        for (int idx = tid; idx < ATOT + BTOT; idx += 256) {
            if (idx < ATOT) {
                int row = idx >> 2, gr = idx & 3;
                int kk = k0 + gr * 8;
                int ksz = (kk + 8 <= Keff) ? 16 : 0;
                uint32_t doff = swz64((uint32_t)row * 64u + (uint32_t)gr * 16u);
                long aoff = (long)(m0 + row) * lda + kk;
                cpasync16(sbase + doff, Ah + aoff, ksz);
                if (A2) cpasync16(sbase + OFF_AL + doff, Al + aoff, ksz);
            } else {
                int j = idx - ATOT;
                int row = j >> 2, gr = j & 3;
                int kk = k0 + gr * 8;
                int nn = n0 + row;
                int bsz = (nn < N && kk + 8 <= Keff) ? 16 : 0;
                long boff = (long)min(nn, N - 1) * ldb + kk;
                uint32_t doff = swz64((uint32_t)row * 64u + (uint32_t)gr * 16u);
                cpasync16(sbase + OFF_BH + doff, Bh + boff, bsz);
                if (B2) cpasync16(sbase + OFF_BL + doff, Bl + boff, bsz);
            }
        }
    };

    fill(0); CP_COMMIT();
    if (nch > 1) fill(1);
    CP_COMMIT();

    int lane = tid & 31, wid = tid >> 5;
    int wm = wid & 1, wn = wid >> 1;           // warp grid 2 (M) x 4 (N)
    int lr = lane & 15, lc = lane >> 4;

    float acc[4][NT][4] = {};

    for (int c = 0; c < nch; c++) {
        if (c + 2 < nch) fill(c + 2);
        CP_COMMIT();
        CP_WAIT(2);
        __syncthreads();
        uint32_t sbase = sb + (uint32_t)(c % STAGES) * STAGE;
        #pragma unroll
        for (int ks = 0; ks < 2; ks++) {
            uint32_t ah[4][4], al[4][4], bh[NT][2], bl[NT][2];
            #pragma unroll
            for (int mt = 0; mt < 4; mt++) {
                uint32_t off = swz64((uint32_t)(wm*64 + mt*16 + lr) * 64u
                                     + (uint32_t)(ks*32 + lc*16));
                ldsm4(ah[mt], sbase + off);
                if (A2) ldsm4(al[mt], sbase + OFF_AL + off);
            }
            #pragma unroll
            for (int np = 0; np < NT/2; np++) {
                uint32_t off = swz64((uint32_t)(wn*(8*NT) + np*16 + lr) * 64u
                                     + (uint32_t)(ks*32 + lc*16));
                uint32_t t[4];
                ldsm4(t, sbase + OFF_BH + off);
                bh[2*np][0] = t[0]; bh[2*np+1][0] = t[1];
                bh[2*np][1] = t[2]; bh[2*np+1][1] = t[3];
                if (B2) {
                    ldsm4(t, sbase + OFF_BL + off);
                    bl[2*np][0] = t[0]; bl[2*np+1][0] = t[1];
                    bl[2*np][1] = t[2]; bl[2*np+1][1] = t[3];
                }
            }
            #pragma unroll
            for (int mt = 0; mt < 4; mt++)
                #pragma unroll
                for (int nt = 0; nt < NT; nt++) {
                    mma16816<FP16>(acc[mt][nt], ah[mt], bh[nt][0], bh[nt][1]);
                    if (B2) mma16816<FP16>(acc[mt][nt], ah[mt], bl[nt][0], bl[nt][1]);
                    if (A2) mma16816<FP16>(acc[mt][nt], al[mt], bh[nt][0], bh[nt][1]);
                }
        }
        __syncthreads();
    }

    // ---------------- epilogue (fragment-direct) ----------------
    int r0 = lane >> 2, c0 = (lane & 3) * 2;
    #pragma unroll
    for (int mt = 0; mt < 4; mt++) {
        #pragma unroll
        for (int nt = 0; nt < NT; nt++) {
            int gn = n0 + wn*(8*NT) + nt*8 + c0;
            if (gn >= N) continue;
            int gmb = m0 + wm*64 + mt*16 + r0;
            float* ac = acc[mt][nt];
            #pragma unroll
            for (int h2 = 0; h2 < 2; h2++) {
                int gm = gmb + h2 * 8;
                float v0 = ac[h2*2 + 0] * alpha;
                float v1 = ac[h2*2 + 1] * alpha;
                long off = cbase + (long)gm * ldc + gn;
                if (EPI == 0) {
                    *(float2*)&C[off] = make_float2(v0, v1);
                } else if (EPI == 1) {
                    __nv_bfloat162 hv, lv;
                    hv.x = __float2bfloat16_rn(v0);
                    hv.y = __float2bfloat16_rn(v1);
                    lv.x = __float2bfloat16_rn(v0 - __bfloat162float(hv.x));
                    lv.y = __float2bfloat16_rn(v1 - __bfloat162float(hv.y));
                    *(__nv_bfloat162*)&Ch[off] = hv;
                    *(__nv_bfloat162*)&Cl[off] = lv;
                } else if (EPI == 2) {
                    v0 += bias[gn]; v1 += bias[gn + 1];
                    v0 = v0 / (1.f + __expf(-1.702f * v0));
                    v1 = v1 / (1.f + __expf(-1.702f * v1));
                    __nv_bfloat162 hv, lv;
                    hv.x = __float2bfloat16_rn(v0);
                    hv.y = __float2bfloat16_rn(v1);
                    lv.x = __float2bfloat16_rn(v0 - __bfloat162float(hv.x));
                    lv.y = __float2bfloat16_rn(v1 - __bfloat162float(hv.y));
                    *(__nv_bfloat162*)&Ch[off] = hv;
                    *(__nv_bfloat162*)&Cl[off] = lv;
                } else { // EPI == 3
                    float2 r = *(const float2*)&resid[off];
                    v0 += bias[gn] + r.x;
                    v1 += bias[gn + 1] + r.y;
                    *(float2*)&C[off] = make_float2(v0, v1);
                }
            }
        }
    }
}

#define SM_NT4_AB 98304   // 3*(8192*2 + 8192*2)
#define SM_NT2_AB 73728   // 3*(8192*2 + 4096*2)
#define SM_AV     73728   // 3*(8192 + 8192*2)

// ---------------- host orchestration ----------------
extern "C" void kernel_launch(void* const* d_in, const int* in_sizes, int n_in,
                              void* d_out, int out_size) {
    (void)in_sizes; (void)n_in; (void)out_size;
    const float* x     = (const float*)d_in[0];
    const float* pos0  = (const float*)d_in[1];
    const float* pos1  = (const float*)d_in[2];
    const float* pos2  = (const float*)d_in[3];
    const float* ln1_g = (const float*)d_in[4];
    const float* ln1_b = (const float*)d_in[5];
    const float* wq    = (const float*)d_in[6];
    const float* wk    = (const float*)d_in[7];
    const float* wv    = (const float*)d_in[8];
    const float* wo    = (const float*)d_in[9];
    const float* wo_b  = (const float*)d_in[10];
    const float* ln2_g = (const float*)d_in[11];
    const float* ln2_b = (const float*)d_in[12];
    const float* w1    = (const float*)d_in[13];
    const float* b1    = (const float*)d_in[14];
    const float* w2    = (const float*)d_in[15];
    const float* b2    = (const float*)d_in[16];

    float *xf, *att;
    __nv_bfloat16 *hh,*hl,*qkvh,*qkvl,*ah,*al,*ffnh,*ffnl,*wth,*wtl;
    __half *attp,*vth,*vtl;
    cudaGetSymbolAddress((void**)&xf,   g_xf);
    cudaGetSymbolAddress((void**)&att,  g_att);
    cudaGetSymbolAddress((void**)&hh,   g_hh);   cudaGetSymbolAddress((void**)&hl,   g_hl);
    cudaGetSymbolAddress((void**)&qkvh, g_qkvh); cudaGetSymbolAddress((void**)&qkvl, g_qkvl);
    cudaGetSymbolAddress((void**)&ah,   g_ah);   cudaGetSymbolAddress((void**)&al,   g_al);
    cudaGetSymbolAddress((void**)&attp, g_attp);
    cudaGetSymbolAddress((void**)&vth,  g_vth);  cudaGetSymbolAddress((void**)&vtl,  g_vtl);
    cudaGetSymbolAddress((void**)&ffnh, g_ffnh); cudaGetSymbolAddress((void**)&ffnl, g_ffnl);
    cudaGetSymbolAddress((void**)&wth,  g_wth);  cudaGetSymbolAddress((void**)&wtl,  g_wtl);

    // instantiations
    auto kQKV   = hmma_gemm<1,false,false,true ,true ,false,4>;
    auto kSCORE = hmma_gemm<0,true ,false,true ,true ,false,4>;
    auto kAV    = hmma_gemm<1,false,true ,false,true ,true ,4>;
    auto kWO    = hmma_gemm<3,false,false,true ,true ,false,2>;
    auto kFFN1  = hmma_gemm<2,false,false,true ,true ,false,4>;
    auto kFFN2  = hmma_gemm<3,false,false,true ,true ,false,2>;

    cudaFuncSetAttribute(kQKV,   cudaFuncAttributeMaxDynamicSharedMemorySize, SM_NT4_AB);
    cudaFuncSetAttribute(kSCORE, cudaFuncAttributeMaxDynamicSharedMemorySize, SM_NT4_AB);
    cudaFuncSetAttribute(kAV,    cudaFuncAttributeMaxDynamicSharedMemorySize, SM_AV);
    cudaFuncSetAttribute(kWO,    cudaFuncAttributeMaxDynamicSharedMemorySize, SM_NT2_AB);
    cudaFuncSetAttribute(kFFN1,  cudaFuncAttributeMaxDynamicSharedMemorySize, SM_NT4_AB);
    cudaFuncSetAttribute(kFFN2,  cudaFuncAttributeMaxDynamicSharedMemorySize, SM_NT2_AB);

    const float scale = 1.0f / sqrtf((float)DK);
    long n_elem = (long)MM * CC;
    int nb = (int)((n_elem + 255) / 256);

    shiftpos_kernel<<<nb, 256>>>(x, pos0, pos1, pos2, xf);

    // transpose + split all weights (batched over layers)
    dim3 thr(32, 8);
    wtrans_kernel<<<dim3(CC/32, CC/32, LL), thr>>>(wq, wth + WQT_OFF, wtl + WQT_OFF, CC, CC, (long)CC*CC, WLAYER);
    wtrans_kernel<<<dim3(CC/32, CC/32, LL), thr>>>(wk, wth + WKT_OFF, wtl + WKT_OFF, CC, CC, (long)CC*CC, WLAYER);
    wtrans_kernel<<<dim3(CC/32, CC/32, LL), thr>>>(wv, wth + WVT_OFF, wtl + WVT_OFF, CC, CC, (long)CC*CC, WLAYER);
    wtrans_kernel<<<dim3(CC/32, CC/32, LL), thr>>>(wo, wth + WOT_OFF, wtl + WOT_OFF, CC, CC, (long)CC*CC, WLAYER);
    wtrans_kernel<<<dim3(FF/32, CC/32, LL), thr>>>(w1, wth + W1T_OFF, wtl + W1T_OFF, CC, FF, (long)CC*FF, WLAYER);
    wtrans_kernel<<<dim3(CC/32, FF/32, LL), thr>>>(w2, wth + W2T_OFF, wtl + W2T_OFF, FF, CC, (long)CC*FF, WLAYER);

    dim3 gQKV((QKVN + 127)/128, MM/BM, 1);     // (14, 32)
    dim3 gScores(SS/128, SS/BM, BB*NH);        // (8, 8, 32)
    dim3 gAV(1, SS/BM, BB*NH);                 // (1, 8, 32)
    dim3 gN2(CC/64, MM/BM, 1);                 // (9, 32)
    dim3 gF1(FF/128, MM/BM, 1);                // (18, 32)

    for (int l = 0; l < LL; l++) {
        long wb = (long)l * WLAYER;
        // --- attention ---
        layernorm_split_kernel<<<MM, 256>>>(xf, ln1_g + l*CC, ln1_b + l*CC, hh, hl);
        // fused q,k,v: N = 1728 (wq/wk/wv transposed rows are contiguous)
        kQKV<<<gQKV, 256, SM_NT4_AB>>>(
            (const uint16_t*)hh, (const uint16_t*)hl, CC, 0, 0,
            (const uint16_t*)(wth + wb), (const uint16_t*)(wtl + wb), CC, 0, 0,
            nullptr, qkvh, qkvl, QKVN, 0, 0, nullptr, nullptr, MM, QKVN, CC, 1.f);
        vtrans_kernel<<<(int)(((long)BB*NH*DK*SS + 255)/256), 256>>>(qkvh, qkvl, vth, vtl);
        // scores = scale * q @ k^T (batched b,h; lower-tri tiles only)
        kSCORE<<<gScores, 256, SM_NT4_AB>>>(
            (const uint16_t*)qkvh, (const uint16_t*)qkvl, QKVN, (long)SS*QKVN, DK,
            (const uint16_t*)(qkvh + CC), (const uint16_t*)(qkvl + CC), QKVN, (long)SS*QKVN, DK,
            att, nullptr, nullptr, SS, (long)NH*SS*SS, (long)SS*SS,
            nullptr, nullptr, SS, SS, DK, scale);
        softmax_kernel<<<dim3(SS, BB*NH), 256>>>(att, attp);
        // a = p @ v   (fp16, 2-term on B; K trimmed to causal extent)
        kAV<<<gAV, 256, SM_AV>>>(
            (const uint16_t*)attp, nullptr, SS, (long)NH*SS*SS, (long)SS*SS,
            (const uint16_t*)vth, (const uint16_t*)vtl, SS, (long)NH*DK*SS, (long)DK*SS,
            nullptr, ah, al, CC, (long)SS*CC, DK,
            nullptr, nullptr, SS, DK, SS, 1.f);
        // xf = xf + a @ wo + wo_b
        kWO<<<gN2, 256, SM_NT2_AB>>>(
            (const uint16_t*)ah, (const uint16_t*)al, CC, 0, 0,
            (const uint16_t*)(wth + wb + WOT_OFF), (const uint16_t*)(wtl + wb + WOT_OFF), CC, 0, 0,
            xf, nullptr, nullptr, CC, 0, 0, wo_b + l*CC, xf, MM, CC, CC, 1.f);

        // --- FFN ---
        layernorm_split_kernel<<<MM, 256>>>(xf, ln2_g + l*CC, ln2_b + l*CC, hh, hl);
        kFFN1<<<gF1, 256, SM_NT4_AB>>>(
            (const uint16_t*)hh, (const uint16_t*)hl, CC, 0, 0,
            (const uint16_t*)(wth + wb + W1T_OFF), (const uint16_t*)(wtl + wb + W1T_OFF), CC, 0, 0,
            nullptr, ffnh, ffnl, FF, 0, 0, b1 + (long)l*FF, nullptr, MM, FF, CC, 1.f);
        float* outp = (l == LL - 1) ? (float*)d_out : xf;
        kFFN2<<<gN2, 256, SM_NT2_AB>>>(
            (const uint16_t*)ffnh, (const uint16_t*)ffnl, FF, 0, 0,
            (const uint16_t*)(wth + wb + W2T_OFF), (const uint16_t*)(wtl + wb + W2T_OFF), FF, 0, 0,
            outp, nullptr, nullptr, CC, 0, 0, b2 + (long)l*CC, xf, MM, CC, FF, 1.f);
    }
}

// round 7
// speedup vs baseline: 7.3950x; 1.2590x over previous
#include <cuda_runtime.h>
#include <cuda_bf16.h>
#include <cuda_fp16.h>
#include <math.h>
#include <stdint.h>

#define BB 4
#define SS 1024
#define CC 576
#define NH 8
#define DK 72
#define LL 4
#define PD 192
#define FF 2304
#define MM (BB*SS)
#define QKVN (3*CC)          // 1728

#define BM 128
#define BK 32
#define STAGES 3

// ---------------- scratch (device globals; no runtime allocation) ----------------
__device__ __align__(16) float g_xf[MM*CC];
__device__ __align__(16) __half g_att[(long)BB*NH*SS*SS];   // scores -> probs (in place)

__device__ __align__(16) __nv_bfloat16 g_hh[MM*CC],  g_hl[MM*CC];   // ln1 out (split bf16)
__device__ __align__(16) __half        g_h2[MM*CC];                 // ln2 out (fp16)
__device__ __align__(16) __nv_bfloat16 g_qkvh[(long)MM*QKVN], g_qkvl[(long)MM*QKVN];
__device__ __align__(16) __half        g_af[MM*CC];                 // attention out (fp16)
__device__ __align__(16) __half        g_vth[BB*NH*DK*SS], g_vtl[BB*NH*DK*SS];
__device__ __align__(16) __half        g_ffn[(long)MM*FF];          // gelu out (fp16)

// qkv weights transposed [N][K] bf16 hi/lo (3-term path)
#define WLAYER  (3*CC*CC)
__device__ __align__(16) __nv_bfloat16 g_wth[(long)LL*WLAYER];
__device__ __align__(16) __nv_bfloat16 g_wtl[(long)LL*WLAYER];
// wo/w1/w2 transposed fp16 hi/lo (2-term path)
#define WO2_OFF 0
#define W12_OFF (CC*CC)
#define W22_OFF (CC*CC + CC*FF)
#define W2LAYER (CC*CC + 2*CC*FF)
__device__ __align__(16) __half g_fwh[(long)LL*W2LAYER];
__device__ __align__(16) __half g_fwl[(long)LL*W2LAYER];

// ================= PTX helpers =================
__device__ __forceinline__ uint32_t smem_u32(const void* p) {
    uint32_t a;
    asm("{ .reg .u64 t; cvta.to.shared.u64 t, %1; cvt.u32.u64 %0, t; }" : "=r"(a) : "l"(p));
    return a;
}
__device__ __forceinline__ void cpasync16(uint32_t dst, const void* src, int sz) {
    asm volatile("cp.async.cg.shared.global [%0], [%1], 16, %2;"
                 :: "r"(dst), "l"(src), "r"(sz) : "memory");
}
#define CP_COMMIT() asm volatile("cp.async.commit_group;" ::: "memory")
#define CP_WAIT(n)  asm volatile("cp.async.wait_group %0;" :: "n"(n) : "memory")

__device__ __forceinline__ void ldsm4(uint32_t (&r)[4], uint32_t addr) {
    asm volatile("ldmatrix.sync.aligned.m8n8.x4.shared.b16 {%0,%1,%2,%3}, [%4];"
        : "=r"(r[0]), "=r"(r[1]), "=r"(r[2]), "=r"(r[3]) : "r"(addr));
}
template<bool FP16>
__device__ __forceinline__ void mma16816(float (&d)[4], const uint32_t (&a)[4],
                                         uint32_t b0, uint32_t b1) {
    if (FP16)
        asm volatile("mma.sync.aligned.m16n8k16.row.col.f32.f16.f16.f32 "
            "{%0,%1,%2,%3}, {%4,%5,%6,%7}, {%8,%9}, {%0,%1,%2,%3};"
            : "+f"(d[0]), "+f"(d[1]), "+f"(d[2]), "+f"(d[3])
            : "r"(a[0]), "r"(a[1]), "r"(a[2]), "r"(a[3]), "r"(b0), "r"(b1));
    else
        asm volatile("mma.sync.aligned.m16n8k16.row.col.f32.bf16.bf16.f32 "
            "{%0,%1,%2,%3}, {%4,%5,%6,%7}, {%8,%9}, {%0,%1,%2,%3};"
            : "+f"(d[0]), "+f"(d[1]), "+f"(d[2]), "+f"(d[3])
            : "r"(a[0]), "r"(a[1]), "r"(a[2]), "r"(a[3]), "r"(b0), "r"(b1));
}
__device__ __forceinline__ uint32_t swz64(uint32_t o) { return o ^ ((o >> 3) & 0x30); }

// ---------------- shift + positional embedding ----------------
__global__ void shiftpos_kernel(const float* __restrict__ x,
                                const float* __restrict__ p0,
                                const float* __restrict__ p1,
                                const float* __restrict__ p2,
                                float* __restrict__ xf) {
    long idx = (long)blockIdx.x * blockDim.x + threadIdx.x;
    if (idx >= (long)MM*CC) return;
    int c = (int)(idx % CC);
    long bs = idx / CC;
    int s = (int)(bs % SS);
    float v = (s == 0) ? 0.f : x[idx - CC];
    int t = s >> 8, hh = (s >> 4) & 15, w = s & 15;
    float p;
    if (c < PD)          p = p0[t * PD + c];
    else if (c < 2 * PD) p = p1[hh * PD + (c - PD)];
    else                 p = p2[w * PD + (c - 2 * PD)];
    xf[idx] = v + p;
}

// ---------------- reductions ----------------
__device__ __forceinline__ float block_reduce_sum(float v, float* sh) {
    int lane = threadIdx.x & 31, warp = threadIdx.x >> 5;
    #pragma unroll
    for (int o = 16; o; o >>= 1) v += __shfl_down_sync(0xffffffffu, v, o);
    if (lane == 0) sh[warp] = v;
    __syncthreads();
    if (warp == 0) {
        v = (lane < (int)(blockDim.x >> 5)) ? sh[lane] : 0.f;
        #pragma unroll
        for (int o = 16; o; o >>= 1) v += __shfl_down_sync(0xffffffffu, v, o);
        if (lane == 0) sh[0] = v;
    }
    __syncthreads();
    float r = sh[0];
    __syncthreads();
    return r;
}

// ---------------- layernorm -> split bf16 (for QKV path) ----------------
__global__ void layernorm_split_kernel(const float* __restrict__ x,
                                       const float* __restrict__ g,
                                       const float* __restrict__ b,
                                       __nv_bfloat16* __restrict__ yh,
                                       __nv_bfloat16* __restrict__ yl) {
    __shared__ float sh[32];
    long row = blockIdx.x;
    const float* xr = x + row * CC;
    float s = 0.f;
    for (int c = threadIdx.x; c < CC; c += blockDim.x) s += xr[c];
    float mu = block_reduce_sum(s, sh) * (1.0f / CC);
    float s2 = 0.f;
    for (int c = threadIdx.x; c < CC; c += blockDim.x) { float d = xr[c] - mu; s2 += d * d; }
    float var = block_reduce_sum(s2, sh) * (1.0f / CC);
    float mult = 1e-5f + rsqrtf(var);
    for (int c = threadIdx.x; c < CC; c += blockDim.x) {
        float y = (xr[c] - mu) * mult * g[c] + b[c];
        __nv_bfloat16 h = __float2bfloat16_rn(y);
        yh[row * CC + c] = h;
        yl[row * CC + c] = __float2bfloat16_rn(y - __bfloat162float(h));
    }
}

// ---------------- layernorm -> single fp16 (for FFN path) ----------------
__global__ void layernorm_f16_kernel(const float* __restrict__ x,
                                     const float* __restrict__ g,
                                     const float* __restrict__ b,
                                     __half* __restrict__ y) {
    __shared__ float sh[32];
    long row = blockIdx.x;
    const float* xr = x + row * CC;
    float s = 0.f;
    for (int c = threadIdx.x; c < CC; c += blockDim.x) s += xr[c];
    float mu = block_reduce_sum(s, sh) * (1.0f / CC);
    float s2 = 0.f;
    for (int c = threadIdx.x; c < CC; c += blockDim.x) { float d = xr[c] - mu; s2 += d * d; }
    float var = block_reduce_sum(s2, sh) * (1.0f / CC);
    float mult = 1e-5f + rsqrtf(var);
    for (int c = threadIdx.x; c < CC; c += blockDim.x)
        y[row * CC + c] = __float2half_rn((xr[c] - mu) * mult * g[c] + b[c]);
}

// ---------------- causal softmax, warp-per-row, fp16 in-place ----------------
__global__ void softmax_kernel(__half* __restrict__ att) {
    int wrow = blockIdx.x * (blockDim.x >> 5) + (threadIdx.x >> 5);
    int lane = threadIdx.x & 31;
    int z = wrow >> 10;             // / SS
    int i = wrow & (SS - 1);        // % SS
    __half* row = att + ((long)z * SS + i) * (long)SS;
    int len = i + 1;
    int kend = ((i >> 7) + 1) << 7;   // round len up to tile boundary AV will read

    float m = -INFINITY;
    #pragma unroll
    for (int it = 0; it < 16; it++) {
        int j = lane * 2 + it * 64;
        if (j < len) {
            __half2 v = *(const __half2*)&row[j];
            m = fmaxf(m, __half2float(v.x));
            if (j + 1 < len) m = fmaxf(m, __half2float(v.y));
        }
    }
    #pragma unroll
    for (int o = 16; o; o >>= 1) m = fmaxf(m, __shfl_xor_sync(0xffffffffu, m, o));

    float2 ev[16];
    float sum = 0.f;
    #pragma unroll
    for (int it = 0; it < 16; it++) {
        int j = lane * 2 + it * 64;
        if (j < kend) {
            float e0 = 0.f, e1 = 0.f;
            __half2 v = *(const __half2*)&row[j];
            if (j < len)     e0 = __expf(__half2float(v.x) - m);
            if (j + 1 < len) e1 = __expf(__half2float(v.y) - m);
            ev[it] = make_float2(e0, e1);
            sum += e0 + e1;
        }
    }
    #pragma unroll
    for (int o = 16; o; o >>= 1) sum += __shfl_xor_sync(0xffffffffu, sum, o);
    float inv = 1.0f / sum;
    #pragma unroll
    for (int it = 0; it < 16; it++) {
        int j = lane * 2 + it * 64;
        if (j < kend) {
            __half2 o2;
            o2.x = __float2half_rn(ev[it].x * inv);
            o2.y = __float2half_rn(ev[it].y * inv);
            *(__half2*)&row[j] = o2;
        }
    }
}

// ---------------- weight transpose + hi/lo split: W[K][N] -> T[N][K] ----------------
template<bool F16>
__global__ void wtrans_kernel(const float* __restrict__ W,
                              uint16_t* __restrict__ Th,
                              uint16_t* __restrict__ Tl,
                              int Kd, int Nd, long wstride, long tstride) {
    __shared__ float t[32][33];
    W  += (long)blockIdx.z * wstride;
    Th += (long)blockIdx.z * tstride;
    Tl += (long)blockIdx.z * tstride;
    int n0 = blockIdx.x * 32, k0 = blockIdx.y * 32;
    int tx = threadIdx.x, ty = threadIdx.y;   // 32 x 8
    #pragma unroll
    for (int r = 0; r < 32; r += 8)
        t[ty + r][tx] = W[(long)(k0 + ty + r) * Nd + (n0 + tx)];
    __syncthreads();
    #pragma unroll
    for (int r = 0; r < 32; r += 8) {
        int nn = n0 + ty + r, kk = k0 + tx;
        float x = t[tx][ty + r];
        if (F16) {
            __half h = __float2half_rn(x);
            Th[(long)nn * Kd + kk] = __half_as_ushort(h);
            Tl[(long)nn * Kd + kk] = __half_as_ushort(__float2half_rn(x - __half2float(h)));
        } else {
            __nv_bfloat16 h = __float2bfloat16_rn(x);
            Th[(long)nn * Kd + kk] = __bfloat16_as_ushort(h);
            Tl[(long)nn * Kd + kk] = __bfloat16_as_ushort(__float2bfloat16_rn(x - __bfloat162float(h)));
        }
    }
}

// ---------------- v transpose per head: qkv split cols [1152,1728) -> fp16 hi/lo [B,NH,DK,S] ----------------
__global__ void vtrans_kernel(const __nv_bfloat16* __restrict__ qh,
                              const __nv_bfloat16* __restrict__ ql,
                              __half* __restrict__ th,
                              __half* __restrict__ tl) {
    long idx = (long)blockIdx.x * blockDim.x + threadIdx.x;
    if (idx >= (long)BB*NH*DK*SS) return;
    int s = (int)(idx % SS);
    long r = idx / SS;
    int d = (int)(r % DK);
    long r2 = r / DK;
    int h = (int)(r2 % NH);
    int b = (int)(r2 / NH);
    long src = (long)(b * SS + s) * QKVN + 2*CC + h * DK + d;
    float x = __bfloat162float(qh[src]) + __bfloat162float(ql[src]);
    __half hh = __float2half_rn(x);
    th[idx] = hh;
    tl[idx] = __float2half_rn(x - __half2float(hh));
}

// =================== HMMA split GEMM ===================
// C[z] = alpha * (Ah[+Al]) @ (Bh[+Bl])^T (+ epilogue), A:[M][K], B:[N][K]
// terms: ah*bh (+ ah*bl if B2) (+ al*bh if A2)
// EPI: 1 split-bf16 out, 3 +bias+resid fp32 out, 4 fp16 out (x alpha), 6 +bias+GeLU2 fp16 out
template<int EPI, bool CAUSAL, bool TRIMK, bool A2, bool B2, bool FP16, int NT>
__global__ void __launch_bounds__(256, 1)
hmma_gemm(const uint16_t* __restrict__ Ah, const uint16_t* __restrict__ Al,
          int lda, long aOffB, long aOffH,
          const uint16_t* __restrict__ Bh, const uint16_t* __restrict__ Bl,
          int ldb, long bOffB, long bOffH,
          float* __restrict__ C, __nv_bfloat16* __restrict__ Ch, __nv_bfloat16* __restrict__ Cl,
          int ldc, long cOffB, long cOffH,
          const float* __restrict__ bias, const float* __restrict__ resid,
          int M, int N, int K, float alpha) {
    constexpr int BN = 32 * NT;
    constexpr uint32_t OPA = 8192;             // 128 rows x 64B
    constexpr uint32_t OPB = (uint32_t)BN * 64;
    constexpr uint32_t OFF_AL = OPA;           // valid when A2
    constexpr uint32_t OFF_BH = OPA * (A2 ? 2 : 1);
    constexpr uint32_t OFF_BL = OFF_BH + OPB;
    constexpr uint32_t STAGE = OFF_BH + OPB * (B2 ? 2 : 1);

    int m0 = blockIdx.y * BM, n0 = blockIdx.x * BN;
    if (CAUSAL && n0 >= m0 + BM) return;

    extern __shared__ char smem[];
    uint32_t sb = smem_u32(smem);
    int tid = threadIdx.x;
    int z = blockIdx.z, zb = z / NH, zh = z % NH;
    Ah += (long)zb * aOffB + (long)zh * aOffH;
    if (A2) Al += (long)zb * aOffB + (long)zh * aOffH;
    Bh += (long)zb * bOffB + (long)zh * bOffH;
    if (B2) Bl += (long)zb * bOffB + (long)zh * bOffH;
    long cbase = (long)zb * cOffB + (long)zh * cOffH;

    int Keff = TRIMK ? min(K, m0 + BM) : K;
    int nch = (Keff + BK - 1) / BK;

    auto fill = [&](int chunk) {
        int k0 = chunk * BK;
        uint32_t sbase = sb + (uint32_t)(chunk % STAGES) * STAGE;
        const int ATOT = BM * 4, BTOT = BN * 4;
        for (int idx = tid; idx < ATOT + BTOT; idx += 256) {
            if (idx < ATOT) {
                int row = idx >> 2, gr = idx & 3;
                int kk = k0 + gr * 8;
                int ksz = (kk + 8 <= Keff) ? 16 : 0;
                uint32_t doff = swz64((uint32_t)row * 64u + (uint32_t)gr * 16u);
                long aoff = (long)(m0 + row) * lda + kk;
                cpasync16(sbase + doff, Ah + aoff, ksz);
                if (A2) cpasync16(sbase + OFF_AL + doff, Al + aoff, ksz);
            } else {
                int j = idx - ATOT;
                int row = j >> 2, gr = j & 3;
                int kk = k0 + gr * 8;
                int nn = n0 + row;
                int bsz = (nn < N && kk + 8 <= Keff) ? 16 : 0;
                long boff = (long)min(nn, N - 1) * ldb + kk;
                uint32_t doff = swz64((uint32_t)row * 64u + (uint32_t)gr * 16u);
                cpasync16(sbase + OFF_BH + doff, Bh + boff, bsz);
                if (B2) cpasync16(sbase + OFF_BL + doff, Bl + boff, bsz);
            }
        }
    };

    fill(0); CP_COMMIT();
    if (nch > 1) fill(1);
    CP_COMMIT();

    int lane = tid & 31, wid = tid >> 5;
    int wm = wid & 1, wn = wid >> 1;           // warp grid 2 (M) x 4 (N)
    int lr = lane & 15, lc = lane >> 4;

    float acc[4][NT][4] = {};

    for (int c = 0; c < nch; c++) {
        if (c + 2 < nch) fill(c + 2);
        CP_COMMIT();
        CP_WAIT(2);
        __syncthreads();
        uint32_t sbase = sb + (uint32_t)(c % STAGES) * STAGE;
        #pragma unroll
        for (int ks = 0; ks < 2; ks++) {
            uint32_t ah[4][4], al[4][4], bh[NT][2], bl[NT][2];
            #pragma unroll
            for (int mt = 0; mt < 4; mt++) {
                uint32_t off = swz64((uint32_t)(wm*64 + mt*16 + lr) * 64u
                                     + (uint32_t)(ks*32 + lc*16));
                ldsm4(ah[mt], sbase + off);
                if (A2) ldsm4(al[mt], sbase + OFF_AL + off);
            }
            #pragma unroll
            for (int np = 0; np < NT/2; np++) {
                uint32_t off = swz64((uint32_t)(wn*(8*NT) + np*16 + lr) * 64u
                                     + (uint32_t)(ks*32 + lc*16));
                uint32_t t[4];
                ldsm4(t, sbase + OFF_BH + off);
                bh[2*np][0] = t[0]; bh[2*np+1][0] = t[1];
                bh[2*np][1] = t[2]; bh[2*np+1][1] = t[3];
                if (B2) {
                    ldsm4(t, sbase + OFF_BL + off);
                    bl[2*np][0] = t[0]; bl[2*np+1][0] = t[1];
                    bl[2*np][1] = t[2]; bl[2*np+1][1] = t[3];
                }
            }
            #pragma unroll
            for (int mt = 0; mt < 4; mt++)
                #pragma unroll
                for (int nt = 0; nt < NT; nt++) {
                    mma16816<FP16>(acc[mt][nt], ah[mt], bh[nt][0], bh[nt][1]);
                    if (B2) mma16816<FP16>(acc[mt][nt], ah[mt], bl[nt][0], bl[nt][1]);
                    if (A2) mma16816<FP16>(acc[mt][nt], al[mt], bh[nt][0], bh[nt][1]);
                }
        }
        __syncthreads();
    }

    // ---------------- epilogue (fragment-direct) ----------------
    __half* Cf16 = (__half*)C;
    int r0 = lane >> 2, c0 = (lane & 3) * 2;
    #pragma unroll
    for (int mt = 0; mt < 4; mt++) {
        #pragma unroll
        for (int nt = 0; nt < NT; nt++) {
            int gn = n0 + wn*(8*NT) + nt*8 + c0;
            if (gn >= N) continue;
            int gmb = m0 + wm*64 + mt*16 + r0;
            float* ac = acc[mt][nt];
            #pragma unroll
            for (int h2 = 0; h2 < 2; h2++) {
                int gm = gmb + h2 * 8;
                float v0 = ac[h2*2 + 0] * alpha;
                float v1 = ac[h2*2 + 1] * alpha;
                long off = cbase + (long)gm * ldc + gn;
                if (EPI == 1) {
                    __nv_bfloat162 hv, lv;
                    hv.x = __float2bfloat16_rn(v0);
                    hv.y = __float2bfloat16_rn(v1);
                    lv.x = __float2bfloat16_rn(v0 - __bfloat162float(hv.x));
                    lv.y = __float2bfloat16_rn(v1 - __bfloat162float(hv.y));
                    *(__nv_bfloat162*)&Ch[off] = hv;
                    *(__nv_bfloat162*)&Cl[off] = lv;
                } else if (EPI == 3) {
                    float2 r = *(const float2*)&resid[off];
                    v0 += bias[gn] + r.x;
                    v1 += bias[gn + 1] + r.y;
                    *(float2*)&C[off] = make_float2(v0, v1);
                } else if (EPI == 4) {
                    __half2 o2;
                    o2.x = __float2half_rn(v0);
                    o2.y = __float2half_rn(v1);
                    *(__half2*)&Cf16[off] = o2;
                } else if (EPI == 6) {
                    v0 += bias[gn]; v1 += bias[gn + 1];
                    v0 = v0 / (1.f + __expf(-1.702f * v0));
                    v1 = v1 / (1.f + __expf(-1.702f * v1));
                    __half2 o2;
                    o2.x = __float2half_rn(v0);
                    o2.y = __float2half_rn(v1);
                    *(__half2*)&Cf16[off] = o2;
                }
            }
        }
    }
}

#define SM_QKV  98304   // 3*(2*8192 + 2*8192)    A2 B2 NT4
#define SM_AV   73728   // 3*(8192 + 2*8192)      A1 B2 NT4
#define SM_N2   49152   // 3*(8192 + 2*4096)      A1 B2 NT2
#define SM_F1   73728   // 3*(8192 + 2*8192)      A1 B2 NT4

// ---------------- host orchestration ----------------
extern "C" void kernel_launch(void* const* d_in, const int* in_sizes, int n_in,
                              void* d_out, int out_size) {
    (void)in_sizes; (void)n_in; (void)out_size;
    const float* x     = (const float*)d_in[0];
    const float* pos0  = (const float*)d_in[1];
    const float* pos1  = (const float*)d_in[2];
    const float* pos2  = (const float*)d_in[3];
    const float* ln1_g = (const float*)d_in[4];
    const float* ln1_b = (const float*)d_in[5];
    const float* wq    = (const float*)d_in[6];
    const float* wk    = (const float*)d_in[7];
    const float* wv    = (const float*)d_in[8];
    const float* wo    = (const float*)d_in[9];
    const float* wo_b  = (const float*)d_in[10];
    const float* ln2_g = (const float*)d_in[11];
    const float* ln2_b = (const float*)d_in[12];
    const float* w1    = (const float*)d_in[13];
    const float* b1    = (const float*)d_in[14];
    const float* w2    = (const float*)d_in[15];
    const float* b2    = (const float*)d_in[16];

    float *xf;
    __nv_bfloat16 *hh,*hl,*qkvh,*qkvl,*wth,*wtl;
    __half *att,*h2,*af,*vth,*vtl,*ffn,*fwh,*fwl;
    cudaGetSymbolAddress((void**)&xf,   g_xf);
    cudaGetSymbolAddress((void**)&att,  g_att);
    cudaGetSymbolAddress((void**)&hh,   g_hh);   cudaGetSymbolAddress((void**)&hl,   g_hl);
    cudaGetSymbolAddress((void**)&h2,   g_h2);
    cudaGetSymbolAddress((void**)&qkvh, g_qkvh); cudaGetSymbolAddress((void**)&qkvl, g_qkvl);
    cudaGetSymbolAddress((void**)&af,   g_af);
    cudaGetSymbolAddress((void**)&vth,  g_vth);  cudaGetSymbolAddress((void**)&vtl,  g_vtl);
    cudaGetSymbolAddress((void**)&ffn,  g_ffn);
    cudaGetSymbolAddress((void**)&wth,  g_wth);  cudaGetSymbolAddress((void**)&wtl,  g_wtl);
    cudaGetSymbolAddress((void**)&fwh,  g_fwh);  cudaGetSymbolAddress((void**)&fwl,  g_fwl);

    // instantiations
    auto kQKV   = hmma_gemm<1,false,false,true ,true ,false,4>;  // split bf16 out
    auto kSCORE = hmma_gemm<4,true ,false,true ,true ,false,4>;  // fp16 out x alpha
    auto kAV    = hmma_gemm<4,false,true ,false,true ,true ,4>;  // fp16 out
    auto kWO    = hmma_gemm<3,false,false,false,true ,true ,2>;  // fp32 +bias+resid
    auto kFFN1  = hmma_gemm<6,false,false,false,true ,true ,4>;  // fp16 +bias+gelu
    auto kFFN2  = hmma_gemm<3,false,false,false,true ,true ,2>;  // fp32 +bias+resid

    cudaFuncSetAttribute(kQKV,   cudaFuncAttributeMaxDynamicSharedMemorySize, SM_QKV);
    cudaFuncSetAttribute(kSCORE, cudaFuncAttributeMaxDynamicSharedMemorySize, SM_QKV);
    cudaFuncSetAttribute(kAV,    cudaFuncAttributeMaxDynamicSharedMemorySize, SM_AV);
    cudaFuncSetAttribute(kWO,    cudaFuncAttributeMaxDynamicSharedMemorySize, SM_N2);
    cudaFuncSetAttribute(kFFN1,  cudaFuncAttributeMaxDynamicSharedMemorySize, SM_F1);
    cudaFuncSetAttribute(kFFN2,  cudaFuncAttributeMaxDynamicSharedMemorySize, SM_N2);

    const float scale = 1.0f / sqrtf((float)DK);
    long n_elem = (long)MM * CC;
    int nb = (int)((n_elem + 255) / 256);

    shiftpos_kernel<<<nb, 256>>>(x, pos0, pos1, pos2, xf);

    // transpose + split all weights (batched over layers)
    dim3 thr(32, 8);
    wtrans_kernel<false><<<dim3(CC/32, CC/32, LL), thr>>>(wq, (uint16_t*)wth + 0,        (uint16_t*)wtl + 0,        CC, CC, (long)CC*CC, WLAYER);
    wtrans_kernel<false><<<dim3(CC/32, CC/32, LL), thr>>>(wk, (uint16_t*)wth + CC*CC,    (uint16_t*)wtl + CC*CC,    CC, CC, (long)CC*CC, WLAYER);
    wtrans_kernel<false><<<dim3(CC/32, CC/32, LL), thr>>>(wv, (uint16_t*)wth + 2*CC*CC,  (uint16_t*)wtl + 2*CC*CC,  CC, CC, (long)CC*CC, WLAYER);
    wtrans_kernel<true ><<<dim3(CC/32, CC/32, LL), thr>>>(wo, (uint16_t*)fwh + WO2_OFF,  (uint16_t*)fwl + WO2_OFF,  CC, CC, (long)CC*CC, W2LAYER);
    wtrans_kernel<true ><<<dim3(FF/32, CC/32, LL), thr>>>(w1, (uint16_t*)fwh + W12_OFF,  (uint16_t*)fwl + W12_OFF,  CC, FF, (long)CC*FF, W2LAYER);
    wtrans_kernel<true ><<<dim3(CC/32, FF/32, LL), thr>>>(w2, (uint16_t*)fwh + W22_OFF,  (uint16_t*)fwl + W22_OFF,  FF, CC, (long)CC*FF, W2LAYER);

    dim3 gQKV((QKVN + 127)/128, MM/BM, 1);     // (14, 32)
    dim3 gScores(SS/128, SS/BM, BB*NH);        // (8, 8, 32)
    dim3 gAV(1, SS/BM, BB*NH);                 // (1, 8, 32)
    dim3 gN2(CC/64, MM/BM, 1);                 // (9, 32)
    dim3 gF1(FF/128, MM/BM, 1);                // (18, 32)

    for (int l = 0; l < LL; l++) {
        long wb = (long)l * WLAYER;
        long fb = (long)l * W2LAYER;
        // --- attention ---
        layernorm_split_kernel<<<MM, 256>>>(xf, ln1_g + l*CC, ln1_b + l*CC, hh, hl);
        kQKV<<<gQKV, 256, SM_QKV>>>(
            (const uint16_t*)hh, (const uint16_t*)hl, CC, 0, 0,
            (const uint16_t*)(wth + wb), (const uint16_t*)(wtl + wb), CC, 0, 0,
            nullptr, qkvh, qkvl, QKVN, 0, 0, nullptr, nullptr, MM, QKVN, CC, 1.f);
        vtrans_kernel<<<(int)(((long)BB*NH*DK*SS + 255)/256), 256>>>(qkvh, qkvl, vth, vtl);
        // scores = scale * q @ k^T -> fp16 (batched b,h; lower-tri tiles only)
        kSCORE<<<gScores, 256, SM_QKV>>>(
            (const uint16_t*)qkvh, (const uint16_t*)qkvl, QKVN, (long)SS*QKVN, DK,
            (const uint16_t*)(qkvh + CC), (const uint16_t*)(qkvl + CC), QKVN, (long)SS*QKVN, DK,
            (float*)att, nullptr, nullptr, SS, (long)NH*SS*SS, (long)SS*SS,
            nullptr, nullptr, SS, SS, DK, scale);
        softmax_kernel<<<BB*NH*SS/8, 256>>>(att);
        // a = p @ v  -> fp16 (2-term on V; K trimmed to causal extent)
        kAV<<<gAV, 256, SM_AV>>>(
            (const uint16_t*)att, nullptr, SS, (long)NH*SS*SS, (long)SS*SS,
            (const uint16_t*)vth, (const uint16_t*)vtl, SS, (long)NH*DK*SS, (long)DK*SS,
            (float*)af, nullptr, nullptr, CC, (long)SS*CC, DK,
            nullptr, nullptr, SS, DK, SS, 1.f);
        // xf = xf + a @ wo + wo_b
        kWO<<<gN2, 256, SM_N2>>>(
            (const uint16_t*)af, nullptr, CC, 0, 0,
            (const uint16_t*)(fwh + fb + WO2_OFF), (const uint16_t*)(fwl + fb + WO2_OFF), CC, 0, 0,
            xf, nullptr, nullptr, CC, 0, 0, wo_b + l*CC, xf, MM, CC, CC, 1.f);

        // --- FFN ---
        layernorm_f16_kernel<<<MM, 256>>>(xf, ln2_g + l*CC, ln2_b + l*CC, h2);
        kFFN1<<<gF1, 256, SM_F1>>>(
            (const uint16_t*)h2, nullptr, CC, 0, 0,
            (const uint16_t*)(fwh + fb + W12_OFF), (const uint16_t*)(fwl + fb + W12_OFF), CC, 0, 0,
            (float*)ffn, nullptr, nullptr, FF, 0, 0, b1 + (long)l*FF, nullptr, MM, FF, CC, 1.f);
        float* outp = (l == LL - 1) ? (float*)d_out : xf;
        kFFN2<<<gN2, 256, SM_N2>>>(
            (const uint16_t*)ffn, nullptr, FF, 0, 0,
            (const uint16_t*)(fwh + fb + W22_OFF), (const uint16_t*)(fwl + fb + W22_OFF), FF, 0, 0,
            outp, nullptr, nullptr, CC, 0, 0, b2 + (long)l*CC, xf, MM, CC, FF, 1.f);
    }
}

// round 8
// speedup vs baseline: 8.4609x; 1.1441x over previous
#include <cuda_runtime.h>
#include <cuda_bf16.h>
#include <cuda_fp16.h>
#include <math.h>
#include <stdint.h>

#define BB 4
#define SS 1024
#define CC 576
#define NH 8
#define DK 72
#define LL 4
#define PD 192
#define FF 2304
#define MM (BB*SS)
#define QKVN (3*CC)          // 1728

#define BM 128
#define BK 32
#define STAGES 3

// ---------------- scratch (device globals; no runtime allocation) ----------------
__device__ __align__(16) float g_xf[MM*CC];

__device__ __align__(16) __nv_bfloat16 g_hh[MM*CC],  g_hl[MM*CC];   // ln1 out (split bf16)
__device__ __align__(16) __half        g_h2[MM*CC];                 // ln2 out (fp16)
__device__ __align__(16) __nv_bfloat16 g_qkvh[(long)MM*QKVN], g_qkvl[(long)MM*QKVN];
__device__ __align__(16) __half        g_af[MM*CC];                 // attention out (fp16)
__device__ __align__(16) __half        g_vth[BB*NH*DK*SS], g_vtl[BB*NH*DK*SS];
__device__ __align__(16) __half        g_ffn[(long)MM*FF];          // gelu out (fp16)

// qkv weights transposed [N][K] bf16 hi/lo (3-term path)
#define WLAYER  (3*CC*CC)
__device__ __align__(16) __nv_bfloat16 g_wth[(long)LL*WLAYER];
__device__ __align__(16) __nv_bfloat16 g_wtl[(long)LL*WLAYER];
// wo/w1/w2 transposed fp16 hi/lo (2-term path)
#define WO2_OFF 0
#define W12_OFF (CC*CC)
#define W22_OFF (CC*CC + CC*FF)
#define W2LAYER (CC*CC + 2*CC*FF)
__device__ __align__(16) __half g_fwh[(long)LL*W2LAYER];
__device__ __align__(16) __half g_fwl[(long)LL*W2LAYER];

// ================= PTX helpers =================
__device__ __forceinline__ uint32_t smem_u32(const void* p) {
    uint32_t a;
    asm("{ .reg .u64 t; cvta.to.shared.u64 t, %1; cvt.u32.u64 %0, t; }" : "=r"(a) : "l"(p));
    return a;
}
__device__ __forceinline__ void cpasync16(uint32_t dst, const void* src, int sz) {
    asm volatile("cp.async.cg.shared.global [%0], [%1], 16, %2;"
                 :: "r"(dst), "l"(src), "r"(sz) : "memory");
}
#define CP_COMMIT() asm volatile("cp.async.commit_group;" ::: "memory")
#define CP_WAIT(n)  asm volatile("cp.async.wait_group %0;" :: "n"(n) : "memory")

__device__ __forceinline__ void ldsm4(uint32_t (&r)[4], uint32_t addr) {
    asm volatile("ldmatrix.sync.aligned.m8n8.x4.shared.b16 {%0,%1,%2,%3}, [%4];"
        : "=r"(r[0]), "=r"(r[1]), "=r"(r[2]), "=r"(r[3]) : "r"(addr));
}
template<bool FP16>
__device__ __forceinline__ void mma16816(float (&d)[4], const uint32_t (&a)[4],
                                         uint32_t b0, uint32_t b1) {
    if (FP16)
        asm volatile("mma.sync.aligned.m16n8k16.row.col.f32.f16.f16.f32 "
            "{%0,%1,%2,%3}, {%4,%5,%6,%7}, {%8,%9}, {%0,%1,%2,%3};"
            : "+f"(d[0]), "+f"(d[1]), "+f"(d[2]), "+f"(d[3])
            : "r"(a[0]), "r"(a[1]), "r"(a[2]), "r"(a[3]), "r"(b0), "r"(b1));
    else
        asm volatile("mma.sync.aligned.m16n8k16.row.col.f32.bf16.bf16.f32 "
            "{%0,%1,%2,%3}, {%4,%5,%6,%7}, {%8,%9}, {%0,%1,%2,%3};"
            : "+f"(d[0]), "+f"(d[1]), "+f"(d[2]), "+f"(d[3])
            : "r"(a[0]), "r"(a[1]), "r"(a[2]), "r"(a[3]), "r"(b0), "r"(b1));
}
__device__ __forceinline__ uint32_t swz64(uint32_t o) { return o ^ ((o >> 3) & 0x30); }
__device__ __forceinline__ uint32_t packh2(float a, float b) {
    __half2 h; h.x = __float2half_rn(a); h.y = __float2half_rn(b);
    return *(uint32_t*)&h;
}

// ---------------- shift + positional embedding ----------------
__global__ void shiftpos_kernel(const float* __restrict__ x,
                                const float* __restrict__ p0,
                                const float* __restrict__ p1,
                                const float* __restrict__ p2,
                                float* __restrict__ xf) {
    long idx = (long)blockIdx.x * blockDim.x + threadIdx.x;
    if (idx >= (long)MM*CC) return;
    int c = (int)(idx % CC);
    long bs = idx / CC;
    int s = (int)(bs % SS);
    float v = (s == 0) ? 0.f : x[idx - CC];
    int t = s >> 8, hh = (s >> 4) & 15, w = s & 15;
    float p;
    if (c < PD)          p = p0[t * PD + c];
    else if (c < 2 * PD) p = p1[hh * PD + (c - PD)];
    else                 p = p2[w * PD + (c - 2 * PD)];
    xf[idx] = v + p;
}

// ---------------- reductions ----------------
__device__ __forceinline__ float block_reduce_sum(float v, float* sh) {
    int lane = threadIdx.x & 31, warp = threadIdx.x >> 5;
    #pragma unroll
    for (int o = 16; o; o >>= 1) v += __shfl_down_sync(0xffffffffu, v, o);
    if (lane == 0) sh[warp] = v;
    __syncthreads();
    if (warp == 0) {
        v = (lane < (int)(blockDim.x >> 5)) ? sh[lane] : 0.f;
        #pragma unroll
        for (int o = 16; o; o >>= 1) v += __shfl_down_sync(0xffffffffu, v, o);
        if (lane == 0) sh[0] = v;
    }
    __syncthreads();
    float r = sh[0];
    __syncthreads();
    return r;
}

// ---------------- layernorm -> split bf16 (for QKV path) ----------------
__global__ void layernorm_split_kernel(const float* __restrict__ x,
                                       const float* __restrict__ g,
                                       const float* __restrict__ b,
                                       __nv_bfloat16* __restrict__ yh,
                                       __nv_bfloat16* __restrict__ yl) {
    __shared__ float sh[32];
    long row = blockIdx.x;
    const float* xr = x + row * CC;
    float s = 0.f;
    for (int c = threadIdx.x; c < CC; c += blockDim.x) s += xr[c];
    float mu = block_reduce_sum(s, sh) * (1.0f / CC);
    float s2 = 0.f;
    for (int c = threadIdx.x; c < CC; c += blockDim.x) { float d = xr[c] - mu; s2 += d * d; }
    float var = block_reduce_sum(s2, sh) * (1.0f / CC);
    float mult = 1e-5f + rsqrtf(var);
    for (int c = threadIdx.x; c < CC; c += blockDim.x) {
        float y = (xr[c] - mu) * mult * g[c] + b[c];
        __nv_bfloat16 h = __float2bfloat16_rn(y);
        yh[row * CC + c] = h;
        yl[row * CC + c] = __float2bfloat16_rn(y - __bfloat162float(h));
    }
}

// ---------------- layernorm -> single fp16 (for FFN path) ----------------
__global__ void layernorm_f16_kernel(const float* __restrict__ x,
                                     const float* __restrict__ g,
                                     const float* __restrict__ b,
                                     __half* __restrict__ y) {
    __shared__ float sh[32];
    long row = blockIdx.x;
    const float* xr = x + row * CC;
    float s = 0.f;
    for (int c = threadIdx.x; c < CC; c += blockDim.x) s += xr[c];
    float mu = block_reduce_sum(s, sh) * (1.0f / CC);
    float s2 = 0.f;
    for (int c = threadIdx.x; c < CC; c += blockDim.x) { float d = xr[c] - mu; s2 += d * d; }
    float var = block_reduce_sum(s2, sh) * (1.0f / CC);
    float mult = 1e-5f + rsqrtf(var);
    for (int c = threadIdx.x; c < CC; c += blockDim.x)
        y[row * CC + c] = __float2half_rn((xr[c] - mu) * mult * g[c] + b[c]);
}

// ---------------- weight transpose + hi/lo split: W[K][N] -> T[N][K] ----------------
template<bool F16>
__global__ void wtrans_kernel(const float* __restrict__ W,
                              uint16_t* __restrict__ Th,
                              uint16_t* __restrict__ Tl,
                              int Kd, int Nd, long wstride, long tstride) {
    __shared__ float t[32][33];
    W  += (long)blockIdx.z * wstride;
    Th += (long)blockIdx.z * tstride;
    Tl += (long)blockIdx.z * tstride;
    int n0 = blockIdx.x * 32, k0 = blockIdx.y * 32;
    int tx = threadIdx.x, ty = threadIdx.y;   // 32 x 8
    #pragma unroll
    for (int r = 0; r < 32; r += 8)
        t[ty + r][tx] = W[(long)(k0 + ty + r) * Nd + (n0 + tx)];
    __syncthreads();
    #pragma unroll
    for (int r = 0; r < 32; r += 8) {
        int nn = n0 + ty + r, kk = k0 + tx;
        float x = t[tx][ty + r];
        if (F16) {
            __half h = __float2half_rn(x);
            Th[(long)nn * Kd + kk] = __half_as_ushort(h);
            Tl[(long)nn * Kd + kk] = __half_as_ushort(__float2half_rn(x - __half2float(h)));
        } else {
            __nv_bfloat16 h = __float2bfloat16_rn(x);
            Th[(long)nn * Kd + kk] = __bfloat16_as_ushort(h);
            Tl[(long)nn * Kd + kk] = __bfloat16_as_ushort(__float2bfloat16_rn(x - __bfloat162float(h)));
        }
    }
}

// ---------------- v transpose per head: qkv split cols [1152,1728) -> fp16 hi/lo [B,NH,DK,S] ----------------
__global__ void vtrans_kernel(const __nv_bfloat16* __restrict__ qh,
                              const __nv_bfloat16* __restrict__ ql,
                              __half* __restrict__ th,
                              __half* __restrict__ tl) {
    long idx = (long)blockIdx.x * blockDim.x + threadIdx.x;
    if (idx >= (long)BB*NH*DK*SS) return;
    int s = (int)(idx % SS);
    long r = idx / SS;
    int d = (int)(r % DK);
    long r2 = r / DK;
    int h = (int)(r2 % NH);
    int b = (int)(r2 / NH);
    long src = (long)(b * SS + s) * QKVN + 2*CC + h * DK + d;
    float x = __bfloat162float(qh[src]) + __bfloat162float(ql[src]);
    __half hh = __float2half_rn(x);
    th[idx] = hh;
    tl[idx] = __float2half_rn(x - __half2float(hh));
}

// =================== fused flash attention ===================
// grid (SS/128, BB*NH). 8 warps, warp tile 16 rows x 128 keys.
// Q/K bf16 hi/lo (3-term scores), V fp16 hi/lo (2-term), fp32 online softmax.
#define FQCH 8192u           // 128 rows x 64B chunk
#define FVCH 5120u           // 80 rows x 64B chunk
#define FQB  24576u          // 3 chunks
#define FVB  20480u          // 4 chunks
#define FSTG (2u*FQB + 2u*FVB)          // 90112: KH KL VH VL
#define FSM  (2u*FQB + 2u*FSTG)         // 229376

__global__ void __launch_bounds__(256, 1)
flash_kernel(const __nv_bfloat16* __restrict__ qkvh,
             const __nv_bfloat16* __restrict__ qkvl,
             const __half* __restrict__ vth,
             const __half* __restrict__ vtl,
             __half* __restrict__ af, float scale) {
    extern __shared__ char smem[];
    uint32_t sb = smem_u32(smem);
    int tid = threadIdx.x, lane = tid & 31, wid = tid >> 5;
    int mi = blockIdx.x;
    int z = blockIdx.y, zb = z / NH, zh = z % NH;
    int m0 = mi * 128;

    const __nv_bfloat16* qhb = qkvh + (long)(zb * SS + m0) * QKVN + zh * DK;
    const __nv_bfloat16* qlb = qkvl + (long)(zb * SS + m0) * QKVN + zh * DK;
    const __nv_bfloat16* khb = qkvh + (long)(zb * SS) * QKVN + CC + zh * DK;
    const __nv_bfloat16* klb = qkvl + (long)(zb * SS) * QKVN + CC + zh * DK;
    const __half* vhb = vth + ((long)(zb * NH + zh) * DK) * SS;
    const __half* vlb = vtl + ((long)(zb * NH + zh) * DK) * SS;

    // ---- load Q (once) ----
    for (int idx = tid; idx < 128 * 12; idx += 256) {
        int row = idx / 12, rem = idx % 12;
        int c = rem >> 2, g = rem & 3;
        int d0 = c * 32 + g * 8;
        int sz = (d0 + 8 <= DK) ? 16 : 0;
        uint32_t doff = (uint32_t)c * FQCH + swz64((uint32_t)row * 64u + (uint32_t)g * 16u);
        cpasync16(sb + doff, qhb + (long)row * QKVN + d0, sz);
        cpasync16(sb + FQB + doff, qlb + (long)row * QKVN + d0, sz);
    }

    auto load_kv = [&](int jt) {
        uint32_t st = sb + 2u*FQB + (uint32_t)(jt & 1) * FSTG;
        int kbase = jt * 128;
        for (int idx = tid; idx < 1536 + 1280; idx += 256) {
            if (idx < 1536) {   // K: 128 keys x 3 chunks x 4 groups
                int row = idx / 12, rem = idx % 12;
                int c = rem >> 2, g = rem & 3;
                int d0 = c * 32 + g * 8;
                int sz = (d0 + 8 <= DK) ? 16 : 0;
                long src = (long)(kbase + row) * QKVN + d0;
                uint32_t doff = (uint32_t)c * FQCH + swz64((uint32_t)row * 64u + (uint32_t)g * 16u);
                cpasync16(st + doff, khb + src, sz);
                cpasync16(st + FQB + doff, klb + src, sz);
            } else {            // V: 80 dim-rows x 4 chunks x 4 groups
                int j = idx - 1536;
                int row = j / 16, rem = j % 16;
                int c = rem >> 2, g = rem & 3;
                int k0 = c * 32 + g * 8;
                int sz = (row < DK) ? 16 : 0;
                long src = (long)row * SS + kbase + k0;
                uint32_t doff = (uint32_t)c * FVCH + swz64((uint32_t)row * 64u + (uint32_t)g * 16u);
                cpasync16(st + 2u*FQB + doff, vhb + src, sz);
                cpasync16(st + 2u*FQB + FVB + doff, vlb + src, sz);
            }
        }
    };

    load_kv(0);
    CP_COMMIT();

    const int lr = lane & 15, lcq = lane >> 4;
    const float NEGINF = __int_as_float(0xff800000);
    float oacc[9][4] = {};
    float rm0 = NEGINF, rm1 = NEGINF, rl0 = 0.f, rl1 = 0.f;
    int qrow0 = m0 + wid * 16 + (lane >> 2);
    int qrow1 = qrow0 + 8;

    for (int jt = 0; jt <= mi; jt++) {
        if (jt < mi) { load_kv(jt + 1); CP_COMMIT(); CP_WAIT(1); }
        else CP_WAIT(0);
        __syncthreads();

        uint32_t kst = sb + 2u*FQB + (uint32_t)(jt & 1) * FSTG;
        uint32_t vst = kst + 2u*FQB;

        // ---- S = q @ k^T (3-term bf16) ----
        float sacc[16][4] = {};
        #pragma unroll
        for (int c = 0; c < 3; c++) {
            #pragma unroll
            for (int ks = 0; ks < 2; ks++) {
                if (c == 2 && ks == 1) continue;   // dims 80..95 all zero
                uint32_t aoff = (uint32_t)c * FQCH
                    + swz64((uint32_t)(wid*16 + lr) * 64u + (uint32_t)(ks*32 + lcq*16));
                uint32_t qh[4], ql[4];
                ldsm4(qh, sb + aoff);
                ldsm4(ql, sb + FQB + aoff);
                #pragma unroll
                for (int np = 0; np < 8; np++) {
                    uint32_t boff = (uint32_t)c * FQCH
                        + swz64((uint32_t)(np*16 + lr) * 64u + (uint32_t)(ks*32 + lcq*16));
                    uint32_t th[4], tl[4];
                    ldsm4(th, kst + boff);
                    ldsm4(tl, kst + FQB + boff);
                    mma16816<false>(sacc[2*np],   qh, th[0], th[2]);
                    mma16816<false>(sacc[2*np+1], qh, th[1], th[3]);
                    mma16816<false>(sacc[2*np],   qh, tl[0], tl[2]);
                    mma16816<false>(sacc[2*np+1], qh, tl[1], tl[3]);
                    mma16816<false>(sacc[2*np],   ql, th[0], th[2]);
                    mma16816<false>(sacc[2*np+1], ql, th[1], th[3]);
                }
            }
        }

        // ---- scale + causal mask + online softmax ----
        bool diag = (jt == mi);
        int kb = jt * 128 + (lane & 3) * 2;
        float tm0 = NEGINF, tm1 = NEGINF;
        #pragma unroll
        for (int nt = 0; nt < 16; nt++) {
            int k0 = kb + nt * 8, k1 = k0 + 1;
            float s00 = sacc[nt][0] * scale, s01 = sacc[nt][1] * scale;
            float s10 = sacc[nt][2] * scale, s11 = sacc[nt][3] * scale;
            if (diag) {
                if (k0 > qrow0) s00 = NEGINF;
                if (k1 > qrow0) s01 = NEGINF;
                if (k0 > qrow1) s10 = NEGINF;
                if (k1 > qrow1) s11 = NEGINF;
            }
            sacc[nt][0] = s00; sacc[nt][1] = s01; sacc[nt][2] = s10; sacc[nt][3] = s11;
            tm0 = fmaxf(tm0, fmaxf(s00, s01));
            tm1 = fmaxf(tm1, fmaxf(s10, s11));
        }
        tm0 = fmaxf(tm0, __shfl_xor_sync(0xffffffffu, tm0, 1));
        tm0 = fmaxf(tm0, __shfl_xor_sync(0xffffffffu, tm0, 2));
        tm1 = fmaxf(tm1, __shfl_xor_sync(0xffffffffu, tm1, 1));
        tm1 = fmaxf(tm1, __shfl_xor_sync(0xffffffffu, tm1, 2));
        float nm0 = fmaxf(rm0, tm0), nm1 = fmaxf(rm1, tm1);
        float cor0 = __expf(rm0 - nm0), cor1 = __expf(rm1 - nm1);
        rm0 = nm0; rm1 = nm1;

        uint32_t ph[16][2];
        float rs0 = 0.f, rs1 = 0.f;
        #pragma unroll
        for (int nt = 0; nt < 16; nt++) {
            float p00 = __expf(sacc[nt][0] - nm0);
            float p01 = __expf(sacc[nt][1] - nm0);
            float p10 = __expf(sacc[nt][2] - nm1);
            float p11 = __expf(sacc[nt][3] - nm1);
            rs0 += p00 + p01; rs1 += p10 + p11;
            ph[nt][0] = packh2(p00, p01);
            ph[nt][1] = packh2(p10, p11);
        }
        rl0 = rl0 * cor0 + rs0;
        rl1 = rl1 * cor1 + rs1;
        #pragma unroll
        for (int nt = 0; nt < 9; nt++) {
            oacc[nt][0] *= cor0; oacc[nt][1] *= cor0;
            oacc[nt][2] *= cor1; oacc[nt][3] *= cor1;
        }

        // ---- O += P @ V (2-term fp16) ----
        #pragma unroll
        for (int kc = 0; kc < 8; kc++) {
            uint32_t pa[4] = { ph[2*kc][0], ph[2*kc][1], ph[2*kc+1][0], ph[2*kc+1][1] };
            #pragma unroll
            for (int np = 0; np < 5; np++) {
                uint32_t voff = (uint32_t)(kc >> 1) * FVCH
                    + swz64((uint32_t)(np*16 + lr) * 64u + (uint32_t)((kc & 1)*32 + lcq*16));
                uint32_t tv[4], tw[4];
                ldsm4(tv, vst + voff);
                ldsm4(tw, vst + FVB + voff);
                mma16816<true>(oacc[2*np], pa, tv[0], tv[2]);
                mma16816<true>(oacc[2*np], pa, tw[0], tw[2]);
                if (2*np + 1 < 9) {
                    mma16816<true>(oacc[2*np+1], pa, tv[1], tv[3]);
                    mma16816<true>(oacc[2*np+1], pa, tw[1], tw[3]);
                }
            }
        }
        __syncthreads();
    }

    // ---- finalize: l across quad, normalize, write fp16 ----
    rl0 += __shfl_xor_sync(0xffffffffu, rl0, 1);
    rl0 += __shfl_xor_sync(0xffffffffu, rl0, 2);
    rl1 += __shfl_xor_sync(0xffffffffu, rl1, 1);
    rl1 += __shfl_xor_sync(0xffffffffu, rl1, 2);
    float inv0 = 1.0f / rl0, inv1 = 1.0f / rl1;
    long base0 = (long)(zb * SS + qrow0) * CC + zh * DK;
    int c0 = (lane & 3) * 2;
    #pragma unroll
    for (int nt = 0; nt < 9; nt++) {
        int d = nt * 8 + c0;
        *(__half2*)&af[base0 + d] =
            __floats2half2_rn(oacc[nt][0] * inv0, oacc[nt][1] * inv0);
        *(__half2*)&af[base0 + 8 * CC + d] =
            __floats2half2_rn(oacc[nt][2] * inv1, oacc[nt][3] * inv1);
    }
}

// =================== HMMA split GEMM ===================
// C[z] = alpha * (Ah[+Al]) @ (Bh[+Bl])^T (+ epilogue), A:[M][K], B:[N][K]
// EPI: 1 split-bf16 out, 3 +bias+resid fp32 out, 6 +bias+GeLU2 fp16 out
template<int EPI, bool A2, bool B2, bool FP16, int NT>
__global__ void __launch_bounds__(256, 1)
hmma_gemm(const uint16_t* __restrict__ Ah, const uint16_t* __restrict__ Al, int lda,
          const uint16_t* __restrict__ Bh, const uint16_t* __restrict__ Bl, int ldb,
          float* __restrict__ C, __nv_bfloat16* __restrict__ Ch, __nv_bfloat16* __restrict__ Cl,
          int ldc,
          const float* __restrict__ bias, const float* __restrict__ resid,
          int M, int N, int K, float alpha) {
    constexpr int BN = 32 * NT;
    constexpr uint32_t OPA = 8192;
    constexpr uint32_t OPB = (uint32_t)BN * 64;
    constexpr uint32_t OFF_AL = OPA;
    constexpr uint32_t OFF_BH = OPA * (A2 ? 2 : 1);
    constexpr uint32_t OFF_BL = OFF_BH + OPB;
    constexpr uint32_t STAGE = OFF_BH + OPB * (B2 ? 2 : 1);

    int m0 = blockIdx.y * BM, n0 = blockIdx.x * BN;

    extern __shared__ char smem[];
    uint32_t sb = smem_u32(smem);
    int tid = threadIdx.x;

    int nch = (K + BK - 1) / BK;

    auto fill = [&](int chunk) {
        int k0 = chunk * BK;
        uint32_t sbase = sb + (uint32_t)(chunk % STAGES) * STAGE;
        const int ATOT = BM * 4, BTOT = BN * 4;
        for (int idx = tid; idx < ATOT + BTOT; idx += 256) {
            if (idx < ATOT) {
                int row = idx >> 2, gr = idx & 3;
                int kk = k0 + gr * 8;
                int ksz = (kk + 8 <= K) ? 16 : 0;
                uint32_t doff = swz64((uint32_t)row * 64u + (uint32_t)gr * 16u);
                long aoff = (long)(m0 + row) * lda + kk;
                cpasync16(sbase + doff, Ah + aoff, ksz);
                if (A2) cpasync16(sbase + OFF_AL + doff, Al + aoff, ksz);
            } else {
                int j = idx - ATOT;
                int row = j >> 2, gr = j & 3;
                int kk = k0 + gr * 8;
                int nn = n0 + row;
                int bsz = (nn < N && kk + 8 <= K) ? 16 : 0;
                long boff = (long)min(nn, N - 1) * ldb + kk;
                uint32_t doff = swz64((uint32_t)row * 64u + (uint32_t)gr * 16u);
                cpasync16(sbase + OFF_BH + doff, Bh + boff, bsz);
                if (B2) cpasync16(sbase + OFF_BL + doff, Bl + boff, bsz);
            }
        }
    };

    fill(0); CP_COMMIT();
    if (nch > 1) fill(1);
    CP_COMMIT();

    int lane = tid & 31, wid = tid >> 5;
    int wm = wid & 1, wn = wid >> 1;
    int lr = lane & 15, lc = lane >> 4;

    float acc[4][NT][4] = {};

    for (int c = 0; c < nch; c++) {
        if (c + 2 < nch) fill(c + 2);
        CP_COMMIT();
        CP_WAIT(2);
        __syncthreads();
        uint32_t sbase = sb + (uint32_t)(c % STAGES) * STAGE;
        #pragma unroll
        for (int ks = 0; ks < 2; ks++) {
            uint32_t ah[4][4], al[4][4], bh[NT][2], bl[NT][2];
            #pragma unroll
            for (int mt = 0; mt < 4; mt++) {
                uint32_t off = swz64((uint32_t)(wm*64 + mt*16 + lr) * 64u
                                     + (uint32_t)(ks*32 + lc*16));
                ldsm4(ah[mt], sbase + off);
                if (A2) ldsm4(al[mt], sbase + OFF_AL + off);
            }
            #pragma unroll
            for (int np = 0; np < NT/2; np++) {
                uint32_t off = swz64((uint32_t)(wn*(8*NT) + np*16 + lr) * 64u
                                     + (uint32_t)(ks*32 + lc*16));
                uint32_t t[4];
                ldsm4(t, sbase + OFF_BH + off);
                bh[2*np][0] = t[0]; bh[2*np+1][0] = t[1];
                bh[2*np][1] = t[2]; bh[2*np+1][1] = t[3];
                if (B2) {
                    ldsm4(t, sbase + OFF_BL + off);
                    bl[2*np][0] = t[0]; bl[2*np+1][0] = t[1];
                    bl[2*np][1] = t[2]; bl[2*np+1][1] = t[3];
                }
            }
            #pragma unroll
            for (int mt = 0; mt < 4; mt++)
                #pragma unroll
                for (int nt = 0; nt < NT; nt++) {
                    mma16816<FP16>(acc[mt][nt], ah[mt], bh[nt][0], bh[nt][1]);
                    if (B2) mma16816<FP16>(acc[mt][nt], ah[mt], bl[nt][0], bl[nt][1]);
                    if (A2) mma16816<FP16>(acc[mt][nt], al[mt], bh[nt][0], bh[nt][1]);
                }
        }
        __syncthreads();
    }

    __half* Cf16 = (__half*)C;
    int r0 = lane >> 2, c0 = (lane & 3) * 2;
    #pragma unroll
    for (int mt = 0; mt < 4; mt++) {
        #pragma unroll
        for (int nt = 0; nt < NT; nt++) {
            int gn = n0 + wn*(8*NT) + nt*8 + c0;
            if (gn >= N) continue;
            int gmb = m0 + wm*64 + mt*16 + r0;
            float* ac = acc[mt][nt];
            #pragma unroll
            for (int h2 = 0; h2 < 2; h2++) {
                int gm = gmb + h2 * 8;
                float v0 = ac[h2*2 + 0] * alpha;
                float v1 = ac[h2*2 + 1] * alpha;
                long off = (long)gm * ldc + gn;
                if (EPI == 1) {
                    __nv_bfloat162 hv, lv;
                    hv.x = __float2bfloat16_rn(v0);
                    hv.y = __float2bfloat16_rn(v1);
                    lv.x = __float2bfloat16_rn(v0 - __bfloat162float(hv.x));
                    lv.y = __float2bfloat16_rn(v1 - __bfloat162float(hv.y));
                    *(__nv_bfloat162*)&Ch[off] = hv;
                    *(__nv_bfloat162*)&Cl[off] = lv;
                } else if (EPI == 3) {
                    float2 r = *(const float2*)&resid[off];
                    v0 += bias[gn] + r.x;
                    v1 += bias[gn + 1] + r.y;
                    *(float2*)&C[off] = make_float2(v0, v1);
                } else if (EPI == 6) {
                    v0 += bias[gn]; v1 += bias[gn + 1];
                    v0 = v0 / (1.f + __expf(-1.702f * v0));
                    v1 = v1 / (1.f + __expf(-1.702f * v1));
                    __half2 o2;
                    o2.x = __float2half_rn(v0);
                    o2.y = __float2half_rn(v1);
                    *(__half2*)&Cf16[off] = o2;
                }
            }
        }
    }
}

#define SM_QKV  98304   // 3*(2*8192 + 2*8192)    A2 B2 NT4
#define SM_N2   49152   // 3*(8192 + 2*4096)      A1 B2 NT2
#define SM_F1   73728   // 3*(8192 + 2*8192)      A1 B2 NT4

// ---------------- host orchestration ----------------
extern "C" void kernel_launch(void* const* d_in, const int* in_sizes, int n_in,
                              void* d_out, int out_size) {
    (void)in_sizes; (void)n_in; (void)out_size;
    const float* x     = (const float*)d_in[0];
    const float* pos0  = (const float*)d_in[1];
    const float* pos1  = (const float*)d_in[2];
    const float* pos2  = (const float*)d_in[3];
    const float* ln1_g = (const float*)d_in[4];
    const float* ln1_b = (const float*)d_in[5];
    const float* wq    = (const float*)d_in[6];
    const float* wk    = (const float*)d_in[7];
    const float* wv    = (const float*)d_in[8];
    const float* wo    = (const float*)d_in[9];
    const float* wo_b  = (const float*)d_in[10];
    const float* ln2_g = (const float*)d_in[11];
    const float* ln2_b = (const float*)d_in[12];
    const float* w1    = (const float*)d_in[13];
    const float* b1    = (const float*)d_in[14];
    const float* w2    = (const float*)d_in[15];
    const float* b2    = (const float*)d_in[16];

    float *xf;
    __nv_bfloat16 *hh,*hl,*qkvh,*qkvl,*wth,*wtl;
    __half *h2p,*af,*vth,*vtl,*ffn,*fwh,*fwl;
    cudaGetSymbolAddress((void**)&xf,   g_xf);
    cudaGetSymbolAddress((void**)&hh,   g_hh);   cudaGetSymbolAddress((void**)&hl,   g_hl);
    cudaGetSymbolAddress((void**)&h2p,  g_h2);
    cudaGetSymbolAddress((void**)&qkvh, g_qkvh); cudaGetSymbolAddress((void**)&qkvl, g_qkvl);
    cudaGetSymbolAddress((void**)&af,   g_af);
    cudaGetSymbolAddress((void**)&vth,  g_vth);  cudaGetSymbolAddress((void**)&vtl,  g_vtl);
    cudaGetSymbolAddress((void**)&ffn,  g_ffn);
    cudaGetSymbolAddress((void**)&wth,  g_wth);  cudaGetSymbolAddress((void**)&wtl,  g_wtl);
    cudaGetSymbolAddress((void**)&fwh,  g_fwh);  cudaGetSymbolAddress((void**)&fwl,  g_fwl);

    auto kQKV   = hmma_gemm<1,true ,true ,false,4>;  // split bf16 out
    auto kWO    = hmma_gemm<3,false,true ,true ,2>;  // fp32 +bias+resid
    auto kFFN1  = hmma_gemm<6,false,true ,true ,4>;  // fp16 +bias+gelu
    auto kFFN2  = hmma_gemm<3,false,true ,true ,2>;  // fp32 +bias+resid

    cudaFuncSetAttribute(kQKV,  cudaFuncAttributeMaxDynamicSharedMemorySize, SM_QKV);
    cudaFuncSetAttribute(kWO,   cudaFuncAttributeMaxDynamicSharedMemorySize, SM_N2);
    cudaFuncSetAttribute(kFFN1, cudaFuncAttributeMaxDynamicSharedMemorySize, SM_F1);
    cudaFuncSetAttribute(kFFN2, cudaFuncAttributeMaxDynamicSharedMemorySize, SM_N2);
    cudaFuncSetAttribute(flash_kernel, cudaFuncAttributeMaxDynamicSharedMemorySize, FSM);

    const float scale = 1.0f / sqrtf((float)DK);
    long n_elem = (long)MM * CC;
    int nb = (int)((n_elem + 255) / 256);

    shiftpos_kernel<<<nb, 256>>>(x, pos0, pos1, pos2, xf);

    dim3 thr(32, 8);
    wtrans_kernel<false><<<dim3(CC/32, CC/32, LL), thr>>>(wq, (uint16_t*)wth + 0,       (uint16_t*)wtl + 0,       CC, CC, (long)CC*CC, WLAYER);
    wtrans_kernel<false><<<dim3(CC/32, CC/32, LL), thr>>>(wk, (uint16_t*)wth + CC*CC,   (uint16_t*)wtl + CC*CC,   CC, CC, (long)CC*CC, WLAYER);
    wtrans_kernel<false><<<dim3(CC/32, CC/32, LL), thr>>>(wv, (uint16_t*)wth + 2*CC*CC, (uint16_t*)wtl + 2*CC*CC, CC, CC, (long)CC*CC, WLAYER);
    wtrans_kernel<true ><<<dim3(CC/32, CC/32, LL), thr>>>(wo, (uint16_t*)fwh + WO2_OFF, (uint16_t*)fwl + WO2_OFF, CC, CC, (long)CC*CC, W2LAYER);
    wtrans_kernel<true ><<<dim3(FF/32, CC/32, LL), thr>>>(w1, (uint16_t*)fwh + W12_OFF, (uint16_t*)fwl + W12_OFF, CC, FF, (long)CC*FF, W2LAYER);
    wtrans_kernel<true ><<<dim3(CC/32, FF/32, LL), thr>>>(w2, (uint16_t*)fwh + W22_OFF, (uint16_t*)fwl + W22_OFF, FF, CC, (long)CC*FF, W2LAYER);

    dim3 gQKV((QKVN + 127)/128, MM/BM, 1);     // (14, 32)
    dim3 gFlash(SS/128, BB*NH);                // (8, 32)
    dim3 gN2(CC/64, MM/BM, 1);                 // (9, 32)
    dim3 gF1(FF/128, MM/BM, 1);                // (18, 32)

    for (int l = 0; l < LL; l++) {
        long wb = (long)l * WLAYER;
        long fb = (long)l * W2LAYER;
        // --- attention ---
        layernorm_split_kernel<<<MM, 256>>>(xf, ln1_g + l*CC, ln1_b + l*CC, hh, hl);
        kQKV<<<gQKV, 256, SM_QKV>>>(
            (const uint16_t*)hh, (const uint16_t*)hl, CC,
            (const uint16_t*)(wth + wb), (const uint16_t*)(wtl + wb), CC,
            nullptr, qkvh, qkvl, QKVN, nullptr, nullptr, MM, QKVN, CC, 1.f);
        vtrans_kernel<<<(int)(((long)BB*NH*DK*SS + 255)/256), 256>>>(qkvh, qkvl, vth, vtl);
        flash_kernel<<<gFlash, 256, FSM>>>(qkvh, qkvl, vth, vtl, af, scale);
        kWO<<<gN2, 256, SM_N2>>>(
            (const uint16_t*)af, nullptr, CC,
            (const uint16_t*)(fwh + fb + WO2_OFF), (const uint16_t*)(fwl + fb + WO2_OFF), CC,
            xf, nullptr, nullptr, CC, wo_b + l*CC, xf, MM, CC, CC, 1.f);

        // --- FFN ---
        layernorm_f16_kernel<<<MM, 256>>>(xf, ln2_g + l*CC, ln2_b + l*CC, h2p);
        kFFN1<<<gF1, 256, SM_F1>>>(
            (const uint16_t*)h2p, nullptr, CC,
            (const uint16_t*)(fwh + fb + W12_OFF), (const uint16_t*)(fwl + fb + W12_OFF), CC,
            (float*)ffn, nullptr, nullptr, FF, b1 + (long)l*FF, nullptr, MM, FF, CC, 1.f);
        float* outp = (l == LL - 1) ? (float*)d_out : xf;
        kFFN2<<<gN2, 256, SM_N2>>>(
            (const uint16_t*)ffn, nullptr, FF,
            (const uint16_t*)(fwh + fb + W22_OFF), (const uint16_t*)(fwl + fb + W22_OFF), FF,
            outp, nullptr, nullptr, CC, b2 + (long)l*CC, xf, MM, CC, FF, 1.f);
    }
}

// round 9
// speedup vs baseline: 9.5106x; 1.1241x over previous
#include <cuda_runtime.h>
#include <cuda_bf16.h>
#include <cuda_fp16.h>
#include <math.h>
#include <stdint.h>

#define BB 4
#define SS 1024
#define CC 576
#define NH 8
#define DK 72
#define LL 4
#define PD 192
#define FF 2304
#define MM (BB*SS)
#define QKVN (3*CC)          // 1728

#define BM 128
#define BK 32
#define STAGES 3

// ---------------- scratch (device globals; no runtime allocation) ----------------
__device__ __align__(16) float g_xf[MM*CC];

__device__ __align__(16) __half g_hh[MM*CC],  g_hl[MM*CC];    // ln1 out (split fp16)
__device__ __align__(16) __half g_h2[MM*CC];                  // ln2 out (fp16)
__device__ __align__(16) __half g_qkvh[(long)MM*QKVN], g_qkvl[(long)MM*QKVN];
__device__ __align__(16) __half g_af[MM*CC];                  // attention out (fp16)
__device__ __align__(16) __half g_vth[BB*NH*DK*SS], g_vtl[BB*NH*DK*SS];
__device__ __align__(16) __half g_ffn[(long)MM*FF];           // gelu out (fp16)

// qkv weights transposed [N][K] fp16 hi/lo (3-term path)
#define WLAYER  (3*CC*CC)
__device__ __align__(16) __half g_wth[(long)LL*WLAYER];
__device__ __align__(16) __half g_wtl[(long)LL*WLAYER];
// wo/w1/w2 transposed single fp16 (1-term path)
#define WO2_OFF 0
#define W12_OFF (CC*CC)
#define W22_OFF (CC*CC + CC*FF)
#define W2LAYER (CC*CC + 2*CC*FF)
__device__ __align__(16) __half g_fwh[(long)LL*W2LAYER];

// ================= PTX helpers =================
__device__ __forceinline__ uint32_t smem_u32(const void* p) {
    uint32_t a;
    asm("{ .reg .u64 t; cvta.to.shared.u64 t, %1; cvt.u32.u64 %0, t; }" : "=r"(a) : "l"(p));
    return a;
}
__device__ __forceinline__ void cpasync16(uint32_t dst, const void* src, int sz) {
    asm volatile("cp.async.cg.shared.global [%0], [%1], 16, %2;"
                 :: "r"(dst), "l"(src), "r"(sz) : "memory");
}
#define CP_COMMIT() asm volatile("cp.async.commit_group;" ::: "memory")
#define CP_WAIT(n)  asm volatile("cp.async.wait_group %0;" :: "n"(n) : "memory")

__device__ __forceinline__ void ldsm4(uint32_t (&r)[4], uint32_t addr) {
    asm volatile("ldmatrix.sync.aligned.m8n8.x4.shared.b16 {%0,%1,%2,%3}, [%4];"
        : "=r"(r[0]), "=r"(r[1]), "=r"(r[2]), "=r"(r[3]) : "r"(addr));
}
template<bool FP16>
__device__ __forceinline__ void mma16816(float (&d)[4], const uint32_t (&a)[4],
                                         uint32_t b0, uint32_t b1) {
    if (FP16)
        asm volatile("mma.sync.aligned.m16n8k16.row.col.f32.f16.f16.f32 "
            "{%0,%1,%2,%3}, {%4,%5,%6,%7}, {%8,%9}, {%0,%1,%2,%3};"
            : "+f"(d[0]), "+f"(d[1]), "+f"(d[2]), "+f"(d[3])
            : "r"(a[0]), "r"(a[1]), "r"(a[2]), "r"(a[3]), "r"(b0), "r"(b1));
    else
        asm volatile("mma.sync.aligned.m16n8k16.row.col.f32.bf16.bf16.f32 "
            "{%0,%1,%2,%3}, {%4,%5,%6,%7}, {%8,%9}, {%0,%1,%2,%3};"
            : "+f"(d[0]), "+f"(d[1]), "+f"(d[2]), "+f"(d[3])
            : "r"(a[0]), "r"(a[1]), "r"(a[2]), "r"(a[3]), "r"(b0), "r"(b1));
}
__device__ __forceinline__ uint32_t swz64(uint32_t o) { return o ^ ((o >> 3) & 0x30); }
__device__ __forceinline__ uint32_t packh2(float a, float b) {
    __half2 h; h.x = __float2half_rn(a); h.y = __float2half_rn(b);
    return *(uint32_t*)&h;
}

// ---------------- shift + positional embedding ----------------
__global__ void shiftpos_kernel(const float* __restrict__ x,
                                const float* __restrict__ p0,
                                const float* __restrict__ p1,
                                const float* __restrict__ p2,
                                float* __restrict__ xf) {
    long idx = (long)blockIdx.x * blockDim.x + threadIdx.x;
    if (idx >= (long)MM*CC) return;
    int c = (int)(idx % CC);
    long bs = idx / CC;
    int s = (int)(bs % SS);
    float v = (s == 0) ? 0.f : x[idx - CC];
    int t = s >> 8, hh = (s >> 4) & 15, w = s & 15;
    float p;
    if (c < PD)          p = p0[t * PD + c];
    else if (c < 2 * PD) p = p1[hh * PD + (c - PD)];
    else                 p = p2[w * PD + (c - 2 * PD)];
    xf[idx] = v + p;
}

// ---------------- reductions ----------------
__device__ __forceinline__ float block_reduce_sum(float v, float* sh) {
    int lane = threadIdx.x & 31, warp = threadIdx.x >> 5;
    #pragma unroll
    for (int o = 16; o; o >>= 1) v += __shfl_down_sync(0xffffffffu, v, o);
    if (lane == 0) sh[warp] = v;
    __syncthreads();
    if (warp == 0) {
        v = (lane < (int)(blockDim.x >> 5)) ? sh[lane] : 0.f;
        #pragma unroll
        for (int o = 16; o; o >>= 1) v += __shfl_down_sync(0xffffffffu, v, o);
        if (lane == 0) sh[0] = v;
    }
    __syncthreads();
    float r = sh[0];
    __syncthreads();
    return r;
}

// ---------------- layernorm -> split fp16 (QKV path) ----------------
__global__ void layernorm_split_kernel(const float* __restrict__ x,
                                       const float* __restrict__ g,
                                       const float* __restrict__ b,
                                       __half* __restrict__ yh,
                                       __half* __restrict__ yl) {
    __shared__ float sh[32];
    long row = blockIdx.x;
    const float* xr = x + row * CC;
    float s = 0.f;
    for (int c = threadIdx.x; c < CC; c += blockDim.x) s += xr[c];
    float mu = block_reduce_sum(s, sh) * (1.0f / CC);
    float s2 = 0.f;
    for (int c = threadIdx.x; c < CC; c += blockDim.x) { float d = xr[c] - mu; s2 += d * d; }
    float var = block_reduce_sum(s2, sh) * (1.0f / CC);
    float mult = 1e-5f + rsqrtf(var);
    for (int c = threadIdx.x; c < CC; c += blockDim.x) {
        float y = (xr[c] - mu) * mult * g[c] + b[c];
        __half h = __float2half_rn(y);
        yh[row * CC + c] = h;
        yl[row * CC + c] = __float2half_rn(y - __half2float(h));
    }
}

// ---------------- layernorm -> single fp16 (FFN path) ----------------
__global__ void layernorm_f16_kernel(const float* __restrict__ x,
                                     const float* __restrict__ g,
                                     const float* __restrict__ b,
                                     __half* __restrict__ y) {
    __shared__ float sh[32];
    long row = blockIdx.x;
    const float* xr = x + row * CC;
    float s = 0.f;
    for (int c = threadIdx.x; c < CC; c += blockDim.x) s += xr[c];
    float mu = block_reduce_sum(s, sh) * (1.0f / CC);
    float s2 = 0.f;
    for (int c = threadIdx.x; c < CC; c += blockDim.x) { float d = xr[c] - mu; s2 += d * d; }
    float var = block_reduce_sum(s2, sh) * (1.0f / CC);
    float mult = 1e-5f + rsqrtf(var);
    for (int c = threadIdx.x; c < CC; c += blockDim.x)
        y[row * CC + c] = __float2half_rn((xr[c] - mu) * mult * g[c] + b[c]);
}

// ---------------- ALL weight transposes in one launch ----------------
// per-layer tiles: [0,1296) wq/wk/wv/wo (324 each), [1296,2592) w1, [2592,3888) w2
#define TPL 3888
__global__ void wtrans_all_kernel(const float* __restrict__ wq, const float* __restrict__ wk,
                                  const float* __restrict__ wv, const float* __restrict__ wo,
                                  const float* __restrict__ w1, const float* __restrict__ w2,
                                  __half* __restrict__ qkvTh, __half* __restrict__ qkvTl,
                                  __half* __restrict__ fwh) {
    __shared__ float t[32][33];
    int bid = blockIdx.x;
    int layer = bid / TPL;
    int r = bid % TPL;
    const float* W; __half* Th; __half* Tl = nullptr;
    int Kd, Nd, n0, k0;
    if (r < 1296) {
        int widx = r / 324, tt = r % 324;
        Kd = CC; Nd = CC;
        n0 = (tt % 18) * 32; k0 = (tt / 18) * 32;
        const float* srcs0 = (widx == 0) ? wq : (widx == 1) ? wk : (widx == 2) ? wv : wo;
        W = srcs0 + (long)layer * CC * CC;
        if (widx < 3) {
            Th = qkvTh + (long)layer * WLAYER + (long)widx * CC * CC;
            Tl = qkvTl + (long)layer * WLAYER + (long)widx * CC * CC;
        } else {
            Th = fwh + (long)layer * W2LAYER + WO2_OFF;
        }
    } else if (r < 2592) {
        int tt = r - 1296;
        Kd = CC; Nd = FF;
        n0 = (tt % 72) * 32; k0 = (tt / 72) * 32;
        W = w1 + (long)layer * CC * FF;
        Th = fwh + (long)layer * W2LAYER + W12_OFF;
    } else {
        int tt = r - 2592;
        Kd = FF; Nd = CC;
        n0 = (tt % 18) * 32; k0 = (tt / 18) * 32;
        W = w2 + (long)layer * CC * FF;
        Th = fwh + (long)layer * W2LAYER + W22_OFF;
    }
    int tx = threadIdx.x, ty = threadIdx.y;   // 32 x 8
    #pragma unroll
    for (int rr = 0; rr < 32; rr += 8)
        t[ty + rr][tx] = W[(long)(k0 + ty + rr) * Nd + (n0 + tx)];
    __syncthreads();
    #pragma unroll
    for (int rr = 0; rr < 32; rr += 8) {
        int nn = n0 + ty + rr, kk = k0 + tx;
        float xv = t[tx][ty + rr];
        __half h = __float2half_rn(xv);
        Th[(long)nn * Kd + kk] = h;
        if (Tl) Tl[(long)nn * Kd + kk] = __float2half_rn(xv - __half2float(h));
    }
}

// ---------------- v transpose per head: qkv cols [1152,1728) -> fp16 hi/lo [B,NH,DK,S] ----------------
__global__ void vtrans_kernel(const __half* __restrict__ qh,
                              const __half* __restrict__ ql,
                              __half* __restrict__ th,
                              __half* __restrict__ tl) {
    long idx = (long)blockIdx.x * blockDim.x + threadIdx.x;
    if (idx >= (long)BB*NH*DK*SS) return;
    int s = (int)(idx % SS);
    long r = idx / SS;
    int d = (int)(r % DK);
    long r2 = r / DK;
    int h = (int)(r2 % NH);
    int b = (int)(r2 / NH);
    long src = (long)(b * SS + s) * QKVN + 2*CC + h * DK + d;
    float x = __half2float(qh[src]) + __half2float(ql[src]);
    __half hh = __float2half_rn(x);
    th[idx] = hh;
    tl[idx] = __float2half_rn(x - __half2float(hh));
}

// =================== fused flash attention ===================
// grid (SS/128, BB*NH). 8 warps, warp tile 16 rows x 128 keys.
// Q/K fp16 hi/lo (3-term), V fp16 hi/lo (2-term), fp32 online softmax.
#define FQCH 8192u           // 128 rows x 64B chunk
#define FVCH 5120u           // 80 rows x 64B chunk
#define FQB  24576u          // 3 chunks
#define FVB  20480u          // 4 chunks
#define FSTG (2u*FQB + 2u*FVB)          // 90112: KH KL VH VL
#define FSM  (2u*FQB + 2u*FSTG)         // 229376

__global__ void __launch_bounds__(256, 1)
flash_kernel(const __half* __restrict__ qkvh,
             const __half* __restrict__ qkvl,
             const __half* __restrict__ vth,
             const __half* __restrict__ vtl,
             __half* __restrict__ af, float scale) {
    extern __shared__ char smem[];
    uint32_t sb = smem_u32(smem);
    int tid = threadIdx.x, lane = tid & 31, wid = tid >> 5;
    int mi = blockIdx.x;
    int z = blockIdx.y, zb = z / NH, zh = z % NH;
    int m0 = mi * 128;

    const __half* qhb = qkvh + (long)(zb * SS + m0) * QKVN + zh * DK;
    const __half* qlb = qkvl + (long)(zb * SS + m0) * QKVN + zh * DK;
    const __half* khb = qkvh + (long)(zb * SS) * QKVN + CC + zh * DK;
    const __half* klb = qkvl + (long)(zb * SS) * QKVN + CC + zh * DK;
    const __half* vhb = vth + ((long)(zb * NH + zh) * DK) * SS;
    const __half* vlb = vtl + ((long)(zb * NH + zh) * DK) * SS;

    // ---- load Q (once) ----
    for (int idx = tid; idx < 128 * 12; idx += 256) {
        int row = idx / 12, rem = idx % 12;
        int c = rem >> 2, g = rem & 3;
        int d0 = c * 32 + g * 8;
        int sz = (d0 + 8 <= DK) ? 16 : 0;
        uint32_t doff = (uint32_t)c * FQCH + swz64((uint32_t)row * 64u + (uint32_t)g * 16u);
        cpasync16(sb + doff, qhb + (long)row * QKVN + d0, sz);
        cpasync16(sb + FQB + doff, qlb + (long)row * QKVN + d0, sz);
    }

    auto load_kv = [&](int jt) {
        uint32_t st = sb + 2u*FQB + (uint32_t)(jt & 1) * FSTG;
        int kbase = jt * 128;
        for (int idx = tid; idx < 1536 + 1280; idx += 256) {
            if (idx < 1536) {
                int row = idx / 12, rem = idx % 12;
                int c = rem >> 2, g = rem & 3;
                int d0 = c * 32 + g * 8;
                int sz = (d0 + 8 <= DK) ? 16 : 0;
                long src = (long)(kbase + row) * QKVN + d0;
                uint32_t doff = (uint32_t)c * FQCH + swz64((uint32_t)row * 64u + (uint32_t)g * 16u);
                cpasync16(st + doff, khb + src, sz);
                cpasync16(st + FQB + doff, klb + src, sz);
            } else {
                int j = idx - 1536;
                int row = j / 16, rem = j % 16;
                int c = rem >> 2, g = rem & 3;
                int k0 = c * 32 + g * 8;
                int sz = (row < DK) ? 16 : 0;
                long src = (long)row * SS + kbase + k0;
                uint32_t doff = (uint32_t)c * FVCH + swz64((uint32_t)row * 64u + (uint32_t)g * 16u);
                cpasync16(st + 2u*FQB + doff, vhb + src, sz);
                cpasync16(st + 2u*FQB + FVB + doff, vlb + src, sz);
            }
        }
    };

    load_kv(0);
    CP_COMMIT();

    const int lr = lane & 15, lcq = lane >> 4;
    const float NEGINF = __int_as_float(0xff800000);
    float oacc[9][4] = {};
    float rm0 = NEGINF, rm1 = NEGINF, rl0 = 0.f, rl1 = 0.f;
    int qrow0 = m0 + wid * 16 + (lane >> 2);
    int qrow1 = qrow0 + 8;

    for (int jt = 0; jt <= mi; jt++) {
        if (jt < mi) { load_kv(jt + 1); CP_COMMIT(); CP_WAIT(1); }
        else CP_WAIT(0);
        __syncthreads();

        uint32_t kst = sb + 2u*FQB + (uint32_t)(jt & 1) * FSTG;
        uint32_t vst = kst + 2u*FQB;

        // ---- S = q @ k^T (3-term fp16) ----
        float sacc[16][4] = {};
        #pragma unroll
        for (int c = 0; c < 3; c++) {
            #pragma unroll
            for (int ks = 0; ks < 2; ks++) {
                if (c == 2 && ks == 1) continue;   // dims 80..95 all zero
                uint32_t aoff = (uint32_t)c * FQCH
                    + swz64((uint32_t)(wid*16 + lr) * 64u + (uint32_t)(ks*32 + lcq*16));
                uint32_t qh[4], ql[4];
                ldsm4(qh, sb + aoff);
                ldsm4(ql, sb + FQB + aoff);
                #pragma unroll
                for (int np = 0; np < 8; np++) {
                    uint32_t boff = (uint32_t)c * FQCH
                        + swz64((uint32_t)(np*16 + lr) * 64u + (uint32_t)(ks*32 + lcq*16));
                    uint32_t th[4], tl[4];
                    ldsm4(th, kst + boff);
                    ldsm4(tl, kst + FQB + boff);
                    mma16816<true>(sacc[2*np],   qh, th[0], th[2]);
                    mma16816<true>(sacc[2*np+1], qh, th[1], th[3]);
                    mma16816<true>(sacc[2*np],   qh, tl[0], tl[2]);
                    mma16816<true>(sacc[2*np+1], qh, tl[1], tl[3]);
                    mma16816<true>(sacc[2*np],   ql, th[0], th[2]);
                    mma16816<true>(sacc[2*np+1], ql, th[1], th[3]);
                }
            }
        }

        // ---- scale + causal mask + online softmax ----
        bool diag = (jt == mi);
        int kb = jt * 128 + (lane & 3) * 2;
        float tm0 = NEGINF, tm1 = NEGINF;
        #pragma unroll
        for (int nt = 0; nt < 16; nt++) {
            int k0 = kb + nt * 8, k1 = k0 + 1;
            float s00 = sacc[nt][0] * scale, s01 = sacc[nt][1] * scale;
            float s10 = sacc[nt][2] * scale, s11 = sacc[nt][3] * scale;
            if (diag) {
                if (k0 > qrow0) s00 = NEGINF;
                if (k1 > qrow0) s01 = NEGINF;
                if (k0 > qrow1) s10 = NEGINF;
                if (k1 > qrow1) s11 = NEGINF;
            }
            sacc[nt][0] = s00; sacc[nt][1] = s01; sacc[nt][2] = s10; sacc[nt][3] = s11;
            tm0 = fmaxf(tm0, fmaxf(s00, s01));
            tm1 = fmaxf(tm1, fmaxf(s10, s11));
        }
        tm0 = fmaxf(tm0, __shfl_xor_sync(0xffffffffu, tm0, 1));
        tm0 = fmaxf(tm0, __shfl_xor_sync(0xffffffffu, tm0, 2));
        tm1 = fmaxf(tm1, __shfl_xor_sync(0xffffffffu, tm1, 1));
        tm1 = fmaxf(tm1, __shfl_xor_sync(0xffffffffu, tm1, 2));
        float nm0 = fmaxf(rm0, tm0), nm1 = fmaxf(rm1, tm1);
        float cor0 = __expf(rm0 - nm0), cor1 = __expf(rm1 - nm1);
        rm0 = nm0; rm1 = nm1;

        uint32_t ph[16][2];
        float rs0 = 0.f, rs1 = 0.f;
        #pragma unroll
        for (int nt = 0; nt < 16; nt++) {
            float p00 = __expf(sacc[nt][0] - nm0);
            float p01 = __expf(sacc[nt][1] - nm0);
            float p10 = __expf(sacc[nt][2] - nm1);
            float p11 = __expf(sacc[nt][3] - nm1);
            rs0 += p00 + p01; rs1 += p10 + p11;
            ph[nt][0] = packh2(p00, p01);
            ph[nt][1] = packh2(p10, p11);
        }
        rl0 = rl0 * cor0 + rs0;
        rl1 = rl1 * cor1 + rs1;
        #pragma unroll
        for (int nt = 0; nt < 9; nt++) {
            oacc[nt][0] *= cor0; oacc[nt][1] *= cor0;
            oacc[nt][2] *= cor1; oacc[nt][3] *= cor1;
        }

        // ---- O += P @ V (2-term fp16) ----
        #pragma unroll
        for (int kc = 0; kc < 8; kc++) {
            uint32_t pa[4] = { ph[2*kc][0], ph[2*kc][1], ph[2*kc+1][0], ph[2*kc+1][1] };
            #pragma unroll
            for (int np = 0; np < 5; np++) {
                uint32_t voff = (uint32_t)(kc >> 1) * FVCH
                    + swz64((uint32_t)(np*16 + lr) * 64u + (uint32_t)((kc & 1)*32 + lcq*16));
                uint32_t tv[4], tw[4];
                ldsm4(tv, vst + voff);
                ldsm4(tw, vst + FVB + voff);
                mma16816<true>(oacc[2*np], pa, tv[0], tv[2]);
                mma16816<true>(oacc[2*np], pa, tw[0], tw[2]);
                if (2*np + 1 < 9) {
                    mma16816<true>(oacc[2*np+1], pa, tv[1], tv[3]);
                    mma16816<true>(oacc[2*np+1], pa, tw[1], tw[3]);
                }
            }
        }
        __syncthreads();
    }

    // ---- finalize ----
    rl0 += __shfl_xor_sync(0xffffffffu, rl0, 1);
    rl0 += __shfl_xor_sync(0xffffffffu, rl0, 2);
    rl1 += __shfl_xor_sync(0xffffffffu, rl1, 1);
    rl1 += __shfl_xor_sync(0xffffffffu, rl1, 2);
    float inv0 = 1.0f / rl0, inv1 = 1.0f / rl1;
    long base0 = (long)(zb * SS + qrow0) * CC + zh * DK;
    int c0 = (lane & 3) * 2;
    #pragma unroll
    for (int nt = 0; nt < 9; nt++) {
        int d = nt * 8 + c0;
        *(__half2*)&af[base0 + d] =
            __floats2half2_rn(oacc[nt][0] * inv0, oacc[nt][1] * inv0);
        *(__half2*)&af[base0 + 8 * CC + d] =
            __floats2half2_rn(oacc[nt][2] * inv1, oacc[nt][3] * inv1);
    }
}

// =================== HMMA split GEMM ===================
// C = alpha * (Ah[+Al]) @ (Bh[+Bl])^T (+ epilogue), A:[M][K], B:[N][K]
// EPI: 3 +bias+resid fp32 out, 5 split-fp16 out, 6 +bias+GeLU2 fp16 out
template<int EPI, bool A2, bool B2, bool FP16, int NT>
__global__ void __launch_bounds__(256, 1)
hmma_gemm(const uint16_t* __restrict__ Ah, const uint16_t* __restrict__ Al, int lda,
          const uint16_t* __restrict__ Bh, const uint16_t* __restrict__ Bl, int ldb,
          float* __restrict__ C, __half* __restrict__ Ch, __half* __restrict__ Cl,
          int ldc,
          const float* __restrict__ bias, const float* __restrict__ resid,
          int M, int N, int K, float alpha) {
    constexpr int BN = 32 * NT;
    constexpr uint32_t OPA = 8192;
    constexpr uint32_t OPB = (uint32_t)BN * 64;
    constexpr uint32_t OFF_AL = OPA;
    constexpr uint32_t OFF_BH = OPA * (A2 ? 2 : 1);
    constexpr uint32_t OFF_BL = OFF_BH + OPB;
    constexpr uint32_t STAGE = OFF_BH + OPB * (B2 ? 2 : 1);

    int m0 = blockIdx.y * BM, n0 = blockIdx.x * BN;

    extern __shared__ char smem[];
    uint32_t sb = smem_u32(smem);
    int tid = threadIdx.x;

    int nch = (K + BK - 1) / BK;

    auto fill = [&](int chunk) {
        int k0 = chunk * BK;
        uint32_t sbase = sb + (uint32_t)(chunk % STAGES) * STAGE;
        const int ATOT = BM * 4, BTOT = BN * 4;
        for (int idx = tid; idx < ATOT + BTOT; idx += 256) {
            if (idx < ATOT) {
                int row = idx >> 2, gr = idx & 3;
                int kk = k0 + gr * 8;
                int ksz = (kk + 8 <= K) ? 16 : 0;
                uint32_t doff = swz64((uint32_t)row * 64u + (uint32_t)gr * 16u);
                long aoff = (long)(m0 + row) * lda + kk;
                cpasync16(sbase + doff, Ah + aoff, ksz);
                if (A2) cpasync16(sbase + OFF_AL + doff, Al + aoff, ksz);
            } else {
                int j = idx - ATOT;
                int row = j >> 2, gr = j & 3;
                int kk = k0 + gr * 8;
                int nn = n0 + row;
                int bsz = (nn < N && kk + 8 <= K) ? 16 : 0;
                long boff = (long)min(nn, N - 1) * ldb + kk;
                uint32_t doff = swz64((uint32_t)row * 64u + (uint32_t)gr * 16u);
                cpasync16(sbase + OFF_BH + doff, Bh + boff, bsz);
                if (B2) cpasync16(sbase + OFF_BL + doff, Bl + boff, bsz);
            }
        }
    };

    fill(0); CP_COMMIT();
    if (nch > 1) fill(1);
    CP_COMMIT();

    int lane = tid & 31, wid = tid >> 5;
    int wm = wid & 1, wn = wid >> 1;
    int lr = lane & 15, lc = lane >> 4;

    float acc[4][NT][4] = {};

    for (int c = 0; c < nch; c++) {
        if (c + 2 < nch) fill(c + 2);
        CP_COMMIT();
        CP_WAIT(2);
        __syncthreads();
        uint32_t sbase = sb + (uint32_t)(c % STAGES) * STAGE;
        #pragma unroll
        for (int ks = 0; ks < 2; ks++) {
            uint32_t ah[4][4], al[4][4], bh[NT][2], bl[NT][2];
            #pragma unroll
            for (int mt = 0; mt < 4; mt++) {
                uint32_t off = swz64((uint32_t)(wm*64 + mt*16 + lr) * 64u
                                     + (uint32_t)(ks*32 + lc*16));
                ldsm4(ah[mt], sbase + off);
                if (A2) ldsm4(al[mt], sbase + OFF_AL + off);
            }
            #pragma unroll
            for (int np = 0; np < NT/2; np++) {
                uint32_t off = swz64((uint32_t)(wn*(8*NT) + np*16 + lr) * 64u
                                     + (uint32_t)(ks*32 + lc*16));
                uint32_t t[4];
                ldsm4(t, sbase + OFF_BH + off);
                bh[2*np][0] = t[0]; bh[2*np+1][0] = t[1];
                bh[2*np][1] = t[2]; bh[2*np+1][1] = t[3];
                if (B2) {
                    ldsm4(t, sbase + OFF_BL + off);
                    bl[2*np][0] = t[0]; bl[2*np+1][0] = t[1];
                    bl[2*np][1] = t[2]; bl[2*np+1][1] = t[3];
                }
            }
            #pragma unroll
            for (int mt = 0; mt < 4; mt++)
                #pragma unroll
                for (int nt = 0; nt < NT; nt++) {
                    mma16816<FP16>(acc[mt][nt], ah[mt], bh[nt][0], bh[nt][1]);
                    if (B2) mma16816<FP16>(acc[mt][nt], ah[mt], bl[nt][0], bl[nt][1]);
                    if (A2) mma16816<FP16>(acc[mt][nt], al[mt], bh[nt][0], bh[nt][1]);
                }
        }
        __syncthreads();
    }

    int r0 = lane >> 2, c0 = (lane & 3) * 2;
    #pragma unroll
    for (int mt = 0; mt < 4; mt++) {
        #pragma unroll
        for (int nt = 0; nt < NT; nt++) {
            int gn = n0 + wn*(8*NT) + nt*8 + c0;
            if (gn >= N) continue;
            int gmb = m0 + wm*64 + mt*16 + r0;
            float* ac = acc[mt][nt];
            #pragma unroll
            for (int h2 = 0; h2 < 2; h2++) {
                int gm = gmb + h2 * 8;
                float v0 = ac[h2*2 + 0] * alpha;
                float v1 = ac[h2*2 + 1] * alpha;
                long off = (long)gm * ldc + gn;
                if (EPI == 3) {
                    float2 r = *(const float2*)&resid[off];
                    v0 += bias[gn] + r.x;
                    v1 += bias[gn + 1] + r.y;
                    *(float2*)&C[off] = make_float2(v0, v1);
                } else if (EPI == 5) {
                    __half2 hv, lv;
                    hv.x = __float2half_rn(v0);
                    hv.y = __float2half_rn(v1);
                    lv.x = __float2half_rn(v0 - __half2float(hv.x));
                    lv.y = __float2half_rn(v1 - __half2float(hv.y));
                    *(__half2*)&Ch[off] = hv;
                    *(__half2*)&Cl[off] = lv;
                } else if (EPI == 6) {
                    v0 += bias[gn]; v1 += bias[gn + 1];
                    v0 = v0 / (1.f + __expf(-1.702f * v0));
                    v1 = v1 / (1.f + __expf(-1.702f * v1));
                    __half2 o2;
                    o2.x = __float2half_rn(v0);
                    o2.y = __float2half_rn(v1);
                    *(__half2*)&((__half*)C)[off] = o2;
                }
            }
        }
    }
}

#define SM_QKV  98304   // 3*(2*8192 + 2*8192)    A2 B2 NT4
#define SM_N2   36864   // 3*(8192 + 4096)        A1 B1 NT2
#define SM_F1   49152   // 3*(8192 + 8192)        A1 B1 NT4

// ---------------- host orchestration ----------------
extern "C" void kernel_launch(void* const* d_in, const int* in_sizes, int n_in,
                              void* d_out, int out_size) {
    (void)in_sizes; (void)n_in; (void)out_size;
    const float* x     = (const float*)d_in[0];
    const float* pos0  = (const float*)d_in[1];
    const float* pos1  = (const float*)d_in[2];
    const float* pos2  = (const float*)d_in[3];
    const float* ln1_g = (const float*)d_in[4];
    const float* ln1_b = (const float*)d_in[5];
    const float* wq    = (const float*)d_in[6];
    const float* wk    = (const float*)d_in[7];
    const float* wv    = (const float*)d_in[8];
    const float* wo    = (const float*)d_in[9];
    const float* wo_b  = (const float*)d_in[10];
    const float* ln2_g = (const float*)d_in[11];
    const float* ln2_b = (const float*)d_in[12];
    const float* w1    = (const float*)d_in[13];
    const float* b1    = (const float*)d_in[14];
    const float* w2    = (const float*)d_in[15];
    const float* b2    = (const float*)d_in[16];

    float *xf;
    __half *hh,*hl,*h2p,*qkvh,*qkvl,*af,*vth,*vtl,*ffn,*wth,*wtl,*fwh;
    cudaGetSymbolAddress((void**)&xf,   g_xf);
    cudaGetSymbolAddress((void**)&hh,   g_hh);   cudaGetSymbolAddress((void**)&hl,   g_hl);
    cudaGetSymbolAddress((void**)&h2p,  g_h2);
    cudaGetSymbolAddress((void**)&qkvh, g_qkvh); cudaGetSymbolAddress((void**)&qkvl, g_qkvl);
    cudaGetSymbolAddress((void**)&af,   g_af);
    cudaGetSymbolAddress((void**)&vth,  g_vth);  cudaGetSymbolAddress((void**)&vtl,  g_vtl);
    cudaGetSymbolAddress((void**)&ffn,  g_ffn);
    cudaGetSymbolAddress((void**)&wth,  g_wth);  cudaGetSymbolAddress((void**)&wtl,  g_wtl);
    cudaGetSymbolAddress((void**)&fwh,  g_fwh);

    auto kQKV   = hmma_gemm<5,true ,true ,true,4>;   // split fp16 out, 3-term
    auto kWO    = hmma_gemm<3,false,false,true,2>;   // fp32 +bias+resid, 1-term
    auto kFFN1  = hmma_gemm<6,false,false,true,4>;   // fp16 +bias+gelu, 1-term
    auto kFFN2  = hmma_gemm<3,false,false,true,2>;   // fp32 +bias+resid, 1-term

    cudaFuncSetAttribute(kQKV,  cudaFuncAttributeMaxDynamicSharedMemorySize, SM_QKV);
    cudaFuncSetAttribute(kWO,   cudaFuncAttributeMaxDynamicSharedMemorySize, SM_N2);
    cudaFuncSetAttribute(kFFN1, cudaFuncAttributeMaxDynamicSharedMemorySize, SM_F1);
    cudaFuncSetAttribute(kFFN2, cudaFuncAttributeMaxDynamicSharedMemorySize, SM_N2);
    cudaFuncSetAttribute(flash_kernel, cudaFuncAttributeMaxDynamicSharedMemorySize, FSM);

    const float scale = 1.0f / sqrtf((float)DK);
    long n_elem = (long)MM * CC;
    int nb = (int)((n_elem + 255) / 256);

    shiftpos_kernel<<<nb, 256>>>(x, pos0, pos1, pos2, xf);
    wtrans_all_kernel<<<LL * TPL, dim3(32, 8)>>>(wq, wk, wv, wo, w1, w2, wth, wtl, fwh);

    dim3 gQKV((QKVN + 127)/128, MM/BM, 1);     // (14, 32)
    dim3 gFlash(SS/128, BB*NH);                // (8, 32)
    dim3 gN2(CC/64, MM/BM, 1);                 // (9, 32)
    dim3 gF1(FF/128, MM/BM, 1);                // (18, 32)

    for (int l = 0; l < LL; l++) {
        long wb = (long)l * WLAYER;
        long fb = (long)l * W2LAYER;
        // --- attention ---
        layernorm_split_kernel<<<MM, 256>>>(xf, ln1_g + l*CC, ln1_b + l*CC, hh, hl);
        kQKV<<<gQKV, 256, SM_QKV>>>(
            (const uint16_t*)hh, (const uint16_t*)hl, CC,
            (const uint16_t*)(wth + wb), (const uint16_t*)(wtl + wb), CC,
            nullptr, qkvh, qkvl, QKVN, nullptr, nullptr, MM, QKVN, CC, 1.f);
        vtrans_kernel<<<(int)(((long)BB*NH*DK*SS + 255)/256), 256>>>(qkvh, qkvl, vth, vtl);
        flash_kernel<<<gFlash, 256, FSM>>>(qkvh, qkvl, vth, vtl, af, scale);
        kWO<<<gN2, 256, SM_N2>>>(
            (const uint16_t*)af, nullptr, CC,
            (const uint16_t*)(fwh + fb + WO2_OFF), nullptr, CC,
            xf, nullptr, nullptr, CC, wo_b + l*CC, xf, MM, CC, CC, 1.f);

        // --- FFN ---
        layernorm_f16_kernel<<<MM, 256>>>(xf, ln2_g + l*CC, ln2_b + l*CC, h2p);
        kFFN1<<<gF1, 256, SM_F1>>>(
            (const uint16_t*)h2p, nullptr, CC,
            (const uint16_t*)(fwh + fb + W12_OFF), nullptr, CC,
            (float*)ffn, nullptr, nullptr, FF, b1 + (long)l*FF, nullptr, MM, FF, CC, 1.f);
        float* outp = (l == LL - 1) ? (float*)d_out : xf;
        kFFN2<<<gN2, 256, SM_N2>>>(
            (const uint16_t*)ffn, nullptr, FF,
            (const uint16_t*)(fwh + fb + W22_OFF), nullptr, FF,
            outp, nullptr, nullptr, CC, b2 + (long)l*CC, xf, MM, CC, FF, 1.f);
    }
}

// round 10
// speedup vs baseline: 10.7199x; 1.1272x over previous
#include <cuda_runtime.h>
#include <cuda_bf16.h>
#include <cuda_fp16.h>
#include <math.h>
#include <stdint.h>

#define BB 4
#define SS 1024
#define CC 576
#define NH 8
#define DK 72
#define LL 4
#define PD 192
#define FF 2304
#define MM (BB*SS)
#define QKVN (3*CC)          // 1728

#define BM 128
#define BK 32
#define STAGES 3

// ---------------- scratch (device globals; no runtime allocation) ----------------
__device__ __align__(16) float g_xf[MM*CC];

__device__ __align__(16) __half g_hh[MM*CC],  g_hl[MM*CC];    // ln1 out (split fp16)
__device__ __align__(16) __half g_h2[MM*CC];                  // ln2 out (fp16)
__device__ __align__(16) __half g_qkvh[(long)MM*QKVN], g_qkvl[(long)MM*QKVN];
__device__ __align__(16) __half g_af[MM*CC];                  // attention out (fp16)
__device__ __align__(16) __half g_ffn[(long)MM*FF];           // gelu out (fp16)

// qkv weights transposed [N][K] fp16 hi/lo (3-term path)
#define WLAYER  (3*CC*CC)
__device__ __align__(16) __half g_wth[(long)LL*WLAYER];
__device__ __align__(16) __half g_wtl[(long)LL*WLAYER];
// wo/w1/w2 transposed single fp16 (1-term path)
#define WO2_OFF 0
#define W12_OFF (CC*CC)
#define W22_OFF (CC*CC + CC*FF)
#define W2LAYER (CC*CC + 2*CC*FF)
__device__ __align__(16) __half g_fwh[(long)LL*W2LAYER];

// ================= PTX helpers =================
__device__ __forceinline__ uint32_t smem_u32(const void* p) {
    uint32_t a;
    asm("{ .reg .u64 t; cvta.to.shared.u64 t, %1; cvt.u32.u64 %0, t; }" : "=r"(a) : "l"(p));
    return a;
}
__device__ __forceinline__ void cpasync16(uint32_t dst, const void* src, int sz) {
    asm volatile("cp.async.cg.shared.global [%0], [%1], 16, %2;"
                 :: "r"(dst), "l"(src), "r"(sz) : "memory");
}
#define CP_COMMIT() asm volatile("cp.async.commit_group;" ::: "memory")
#define CP_WAIT(n)  asm volatile("cp.async.wait_group %0;" :: "n"(n) : "memory")

__device__ __forceinline__ void ldsm4(uint32_t (&r)[4], uint32_t addr) {
    asm volatile("ldmatrix.sync.aligned.m8n8.x4.shared.b16 {%0,%1,%2,%3}, [%4];"
        : "=r"(r[0]), "=r"(r[1]), "=r"(r[2]), "=r"(r[3]) : "r"(addr));
}
__device__ __forceinline__ void ldsm4t(uint32_t (&r)[4], uint32_t addr) {
    asm volatile("ldmatrix.sync.aligned.m8n8.x4.trans.shared.b16 {%0,%1,%2,%3}, [%4];"
        : "=r"(r[0]), "=r"(r[1]), "=r"(r[2]), "=r"(r[3]) : "r"(addr));
}
template<bool FP16>
__device__ __forceinline__ void mma16816(float (&d)[4], const uint32_t (&a)[4],
                                         uint32_t b0, uint32_t b1) {
    if (FP16)
        asm volatile("mma.sync.aligned.m16n8k16.row.col.f32.f16.f16.f32 "
            "{%0,%1,%2,%3}, {%4,%5,%6,%7}, {%8,%9}, {%0,%1,%2,%3};"
            : "+f"(d[0]), "+f"(d[1]), "+f"(d[2]), "+f"(d[3])
            : "r"(a[0]), "r"(a[1]), "r"(a[2]), "r"(a[3]), "r"(b0), "r"(b1));
    else
        asm volatile("mma.sync.aligned.m16n8k16.row.col.f32.bf16.bf16.f32 "
            "{%0,%1,%2,%3}, {%4,%5,%6,%7}, {%8,%9}, {%0,%1,%2,%3};"
            : "+f"(d[0]), "+f"(d[1]), "+f"(d[2]), "+f"(d[3])
            : "r"(a[0]), "r"(a[1]), "r"(a[2]), "r"(a[3]), "r"(b0), "r"(b1));
}
__device__ __forceinline__ uint32_t swz64(uint32_t o) { return o ^ ((o >> 3) & 0x30); }
__device__ __forceinline__ uint32_t packh2(float a, float b) {
    __half2 h; h.x = __float2half_rn(a); h.y = __float2half_rn(b);
    return *(uint32_t*)&h;
}

// ---------------- shift + positional embedding ----------------
__global__ void shiftpos_kernel(const float* __restrict__ x,
                                const float* __restrict__ p0,
                                const float* __restrict__ p1,
                                const float* __restrict__ p2,
                                float* __restrict__ xf) {
    long idx = (long)blockIdx.x * blockDim.x + threadIdx.x;
    if (idx >= (long)MM*CC) return;
    int c = (int)(idx % CC);
    long bs = idx / CC;
    int s = (int)(bs % SS);
    float v = (s == 0) ? 0.f : x[idx - CC];
    int t = s >> 8, hh = (s >> 4) & 15, w = s & 15;
    float p;
    if (c < PD)          p = p0[t * PD + c];
    else if (c < 2 * PD) p = p1[hh * PD + (c - PD)];
    else                 p = p2[w * PD + (c - 2 * PD)];
    xf[idx] = v + p;
}

// ---------------- reductions ----------------
__device__ __forceinline__ float block_reduce_sum(float v, float* sh) {
    int lane = threadIdx.x & 31, warp = threadIdx.x >> 5;
    #pragma unroll
    for (int o = 16; o; o >>= 1) v += __shfl_down_sync(0xffffffffu, v, o);
    if (lane == 0) sh[warp] = v;
    __syncthreads();
    if (warp == 0) {
        v = (lane < (int)(blockDim.x >> 5)) ? sh[lane] : 0.f;
        #pragma unroll
        for (int o = 16; o; o >>= 1) v += __shfl_down_sync(0xffffffffu, v, o);
        if (lane == 0) sh[0] = v;
    }
    __syncthreads();
    float r = sh[0];
    __syncthreads();
    return r;
}

// ---------------- layernorm -> split fp16 (QKV path) ----------------
__global__ void layernorm_split_kernel(const float* __restrict__ x,
                                       const float* __restrict__ g,
                                       const float* __restrict__ b,
                                       __half* __restrict__ yh,
                                       __half* __restrict__ yl) {
    __shared__ float sh[32];
    long row = blockIdx.x;
    const float* xr = x + row * CC;
    float s = 0.f;
    for (int c = threadIdx.x; c < CC; c += blockDim.x) s += xr[c];
    float mu = block_reduce_sum(s, sh) * (1.0f / CC);
    float s2 = 0.f;
    for (int c = threadIdx.x; c < CC; c += blockDim.x) { float d = xr[c] - mu; s2 += d * d; }
    float var = block_reduce_sum(s2, sh) * (1.0f / CC);
    float mult = 1e-5f + rsqrtf(var);
    for (int c = threadIdx.x; c < CC; c += blockDim.x) {
        float y = (xr[c] - mu) * mult * g[c] + b[c];
        __half h = __float2half_rn(y);
        yh[row * CC + c] = h;
        yl[row * CC + c] = __float2half_rn(y - __half2float(h));
    }
}

// ---------------- layernorm -> single fp16 (FFN path) ----------------
__global__ void layernorm_f16_kernel(const float* __restrict__ x,
                                     const float* __restrict__ g,
                                     const float* __restrict__ b,
                                     __half* __restrict__ y) {
    __shared__ float sh[32];
    long row = blockIdx.x;
    const float* xr = x + row * CC;
    float s = 0.f;
    for (int c = threadIdx.x; c < CC; c += blockDim.x) s += xr[c];
    float mu = block_reduce_sum(s, sh) * (1.0f / CC);
    float s2 = 0.f;
    for (int c = threadIdx.x; c < CC; c += blockDim.x) { float d = xr[c] - mu; s2 += d * d; }
    float var = block_reduce_sum(s2, sh) * (1.0f / CC);
    float mult = 1e-5f + rsqrtf(var);
    for (int c = threadIdx.x; c < CC; c += blockDim.x)
        y[row * CC + c] = __float2half_rn((xr[c] - mu) * mult * g[c] + b[c]);
}

// ---------------- ALL weight transposes in one launch ----------------
#define TPL 3888
__global__ void wtrans_all_kernel(const float* __restrict__ wq, const float* __restrict__ wk,
                                  const float* __restrict__ wv, const float* __restrict__ wo,
                                  const float* __restrict__ w1, const float* __restrict__ w2,
                                  __half* __restrict__ qkvTh, __half* __restrict__ qkvTl,
                                  __half* __restrict__ fwh) {
    __shared__ float t[32][33];
    int bid = blockIdx.x;
    int layer = bid / TPL;
    int r = bid % TPL;
    const float* W; __half* Th; __half* Tl = nullptr;
    int Kd, Nd, n0, k0;
    if (r < 1296) {
        int widx = r / 324, tt = r % 324;
        Kd = CC; Nd = CC;
        n0 = (tt % 18) * 32; k0 = (tt / 18) * 32;
        const float* srcs0 = (widx == 0) ? wq : (widx == 1) ? wk : (widx == 2) ? wv : wo;
        W = srcs0 + (long)layer * CC * CC;
        if (widx < 3) {
            Th = qkvTh + (long)layer * WLAYER + (long)widx * CC * CC;
            Tl = qkvTl + (long)layer * WLAYER + (long)widx * CC * CC;
        } else {
            Th = fwh + (long)layer * W2LAYER + WO2_OFF;
        }
    } else if (r < 2592) {
        int tt = r - 1296;
        Kd = CC; Nd = FF;
        n0 = (tt % 72) * 32; k0 = (tt / 72) * 32;
        W = w1 + (long)layer * CC * FF;
        Th = fwh + (long)layer * W2LAYER + W12_OFF;
    } else {
        int tt = r - 2592;
        Kd = FF; Nd = CC;
        n0 = (tt % 18) * 32; k0 = (tt / 18) * 32;
        W = w2 + (long)layer * CC * FF;
        Th = fwh + (long)layer * W2LAYER + W22_OFF;
    }
    int tx = threadIdx.x, ty = threadIdx.y;   // 32 x 8
    #pragma unroll
    for (int rr = 0; rr < 32; rr += 8)
        t[ty + rr][tx] = W[(long)(k0 + ty + rr) * Nd + (n0 + tx)];
    __syncthreads();
    #pragma unroll
    for (int rr = 0; rr < 32; rr += 8) {
        int nn = n0 + ty + rr, kk = k0 + tx;
        float xv = t[tx][ty + rr];
        __half h = __float2half_rn(xv);
        Th[(long)nn * Kd + kk] = h;
        if (Tl) Tl[(long)nn * Kd + kk] = __float2half_rn(xv - __half2float(h));
    }
}

// =================== fused flash attention v2 ===================
// grid (SS/128, BB*NH), heavy-first. 8 warps, warp tile 16 rows x 128 keys.
// Q/K fp16 hi/lo (3-term), V single fp16 DIRECT from qkv (ldmatrix.trans), fp32 softmax.
#define FQCH 8192u           // 128 rows x 64B chunk
#define FQB  24576u          // 3 chunks
#define FSTG (3u*FQB)        // 73728: KH KL VH
#define FSM  (2u*FQB + 2u*FSTG)   // 196608

__global__ void __launch_bounds__(256, 1)
flash_kernel(const __half* __restrict__ qkvh,
             const __half* __restrict__ qkvl,
             __half* __restrict__ af, float scale) {
    extern __shared__ char smem[];
    uint32_t sb = smem_u32(smem);
    int tid = threadIdx.x, lane = tid & 31, wid = tid >> 5;
    int mi = (int)(gridDim.x - 1 - blockIdx.x);     // heavy-first
    int z = blockIdx.y, zb = z / NH, zh = z % NH;
    int m0 = mi * 128;

    const __half* qhb = qkvh + (long)(zb * SS + m0) * QKVN + zh * DK;
    const __half* qlb = qkvl + (long)(zb * SS + m0) * QKVN + zh * DK;
    const __half* khb = qkvh + (long)(zb * SS) * QKVN + CC + zh * DK;
    const __half* klb = qkvl + (long)(zb * SS) * QKVN + CC + zh * DK;
    const __half* vhb = qkvh + (long)(zb * SS) * QKVN + 2*CC + zh * DK;

    // ---- load Q (once) ----
    for (int idx = tid; idx < 128 * 12; idx += 256) {
        int row = idx / 12, rem = idx % 12;
        int c = rem >> 2, g = rem & 3;
        int d0 = c * 32 + g * 8;
        int sz = (d0 + 8 <= DK) ? 16 : 0;
        uint32_t doff = (uint32_t)c * FQCH + swz64((uint32_t)row * 64u + (uint32_t)g * 16u);
        cpasync16(sb + doff, qhb + (long)row * QKVN + d0, sz);
        cpasync16(sb + FQB + doff, qlb + (long)row * QKVN + d0, sz);
    }

    auto load_kv = [&](int jt) {
        uint32_t st = sb + 2u*FQB + (uint32_t)(jt & 1) * FSTG;
        int kbase = jt * 128;
        for (int idx = tid; idx < 1536; idx += 256) {
            int row = idx / 12, rem = idx % 12;
            int c = rem >> 2, g = rem & 3;
            int d0 = c * 32 + g * 8;
            int sz = (d0 + 8 <= DK) ? 16 : 0;
            long src = (long)(kbase + row) * QKVN + d0;
            uint32_t doff = (uint32_t)c * FQCH + swz64((uint32_t)row * 64u + (uint32_t)g * 16u);
            cpasync16(st + doff, khb + src, sz);
            cpasync16(st + FQB + doff, klb + src, sz);
            cpasync16(st + 2u*FQB + doff, vhb + src, sz);
        }
    };

    load_kv(0);
    CP_COMMIT();

    const int lr = lane & 15, lcq = lane >> 4;
    const float NEGINF = __int_as_float(0xff800000);
    float oacc[9][4] = {};
    float rm0 = NEGINF, rm1 = NEGINF, rl0 = 0.f, rl1 = 0.f;
    int qrow0 = m0 + wid * 16 + (lane >> 2);
    int qrow1 = qrow0 + 8;

    for (int jt = 0; jt <= mi; jt++) {
        if (jt < mi) { load_kv(jt + 1); CP_COMMIT(); CP_WAIT(1); }
        else CP_WAIT(0);
        __syncthreads();

        uint32_t kst = sb + 2u*FQB + (uint32_t)(jt & 1) * FSTG;
        uint32_t vst = kst + 2u*FQB;

        // ---- S = q @ k^T (3-term fp16) ----
        float sacc[16][4] = {};
        #pragma unroll
        for (int c = 0; c < 3; c++) {
            #pragma unroll
            for (int ks = 0; ks < 2; ks++) {
                if (c == 2 && ks == 1) continue;   // dims 80..95 all zero
                uint32_t aoff = (uint32_t)c * FQCH
                    + swz64((uint32_t)(wid*16 + lr) * 64u + (uint32_t)(ks*32 + lcq*16));
                uint32_t qh[4], ql[4];
                ldsm4(qh, sb + aoff);
                ldsm4(ql, sb + FQB + aoff);
                #pragma unroll
                for (int np = 0; np < 8; np++) {
                    uint32_t boff = (uint32_t)c * FQCH
                        + swz64((uint32_t)(np*16 + lr) * 64u + (uint32_t)(ks*32 + lcq*16));
                    uint32_t th[4], tl[4];
                    ldsm4(th, kst + boff);
                    ldsm4(tl, kst + FQB + boff);
                    mma16816<true>(sacc[2*np],   qh, th[0], th[2]);
                    mma16816<true>(sacc[2*np+1], qh, th[1], th[3]);
                    mma16816<true>(sacc[2*np],   qh, tl[0], tl[2]);
                    mma16816<true>(sacc[2*np+1], qh, tl[1], tl[3]);
                    mma16816<true>(sacc[2*np],   ql, th[0], th[2]);
                    mma16816<true>(sacc[2*np+1], ql, th[1], th[3]);
                }
            }
        }

        // ---- scale + causal mask + online softmax ----
        bool diag = (jt == mi);
        int kb = jt * 128 + (lane & 3) * 2;
        float tm0 = NEGINF, tm1 = NEGINF;
        #pragma unroll
        for (int nt = 0; nt < 16; nt++) {
            int k0 = kb + nt * 8, k1 = k0 + 1;
            float s00 = sacc[nt][0] * scale, s01 = sacc[nt][1] * scale;
            float s10 = sacc[nt][2] * scale, s11 = sacc[nt][3] * scale;
            if (diag) {
                if (k0 > qrow0) s00 = NEGINF;
                if (k1 > qrow0) s01 = NEGINF;
                if (k0 > qrow1) s10 = NEGINF;
                if (k1 > qrow1) s11 = NEGINF;
            }
            sacc[nt][0] = s00; sacc[nt][1] = s01; sacc[nt][2] = s10; sacc[nt][3] = s11;
            tm0 = fmaxf(tm0, fmaxf(s00, s01));
            tm1 = fmaxf(tm1, fmaxf(s10, s11));
        }
        tm0 = fmaxf(tm0, __shfl_xor_sync(0xffffffffu, tm0, 1));
        tm0 = fmaxf(tm0, __shfl_xor_sync(0xffffffffu, tm0, 2));
        tm1 = fmaxf(tm1, __shfl_xor_sync(0xffffffffu, tm1, 1));
        tm1 = fmaxf(tm1, __shfl_xor_sync(0xffffffffu, tm1, 2));
        float nm0 = fmaxf(rm0, tm0), nm1 = fmaxf(rm1, tm1);
        float cor0 = __expf(rm0 - nm0), cor1 = __expf(rm1 - nm1);
        rm0 = nm0; rm1 = nm1;

        uint32_t ph[16][2];
        float rs0 = 0.f, rs1 = 0.f;
        #pragma unroll
        for (int nt = 0; nt < 16; nt++) {
            float p00 = __expf(sacc[nt][0] - nm0);
            float p01 = __expf(sacc[nt][1] - nm0);
            float p10 = __expf(sacc[nt][2] - nm1);
            float p11 = __expf(sacc[nt][3] - nm1);
            rs0 += p00 + p01; rs1 += p10 + p11;
            ph[nt][0] = packh2(p00, p01);
            ph[nt][1] = packh2(p10, p11);
        }
        rl0 = rl0 * cor0 + rs0;
        rl1 = rl1 * cor1 + rs1;
        #pragma unroll
        for (int nt = 0; nt < 9; nt++) {
            oacc[nt][0] *= cor0; oacc[nt][1] *= cor0;
            oacc[nt][2] *= cor1; oacc[nt][3] *= cor1;
        }

        // ---- O += P @ V (1-term fp16, V direct via ldmatrix.trans) ----
        #pragma unroll
        for (int kc = 0; kc < 8; kc++) {
            uint32_t pa[4] = { ph[2*kc][0], ph[2*kc][1], ph[2*kc+1][0], ph[2*kc+1][1] };
            #pragma unroll
            for (int dg = 0; dg < 5; dg++) {
                uint32_t addr = vst + (uint32_t)(dg >> 1) * FQCH
                    + swz64((uint32_t)(kc*16 + lr) * 64u
                            + (uint32_t)((dg & 1) * 32 + lcq * 16));
                uint32_t t[4];
                ldsm4t(t, addr);
                mma16816<true>(oacc[2*dg], pa, t[0], t[1]);
                if (2*dg + 1 < 9)
                    mma16816<true>(oacc[2*dg+1], pa, t[2], t[3]);
            }
        }
        __syncthreads();
    }

    // ---- finalize ----
    rl0 += __shfl_xor_sync(0xffffffffu, rl0, 1);
    rl0 += __shfl_xor_sync(0xffffffffu, rl0, 2);
    rl1 += __shfl_xor_sync(0xffffffffu, rl1, 1);
    rl1 += __shfl_xor_sync(0xffffffffu, rl1, 2);
    float inv0 = 1.0f / rl0, inv1 = 1.0f / rl1;
    long base0 = (long)(zb * SS + qrow0) * CC + zh * DK;
    int c0 = (lane & 3) * 2;
    #pragma unroll
    for (int nt = 0; nt < 9; nt++) {
        int d = nt * 8 + c0;
        *(__half2*)&af[base0 + d] =
            __floats2half2_rn(oacc[nt][0] * inv0, oacc[nt][1] * inv0);
        *(__half2*)&af[base0 + 8 * CC + d] =
            __floats2half2_rn(oacc[nt][2] * inv1, oacc[nt][3] * inv1);
    }
}

// =================== HMMA split GEMM ===================
// EPI: 3 +bias+resid fp32 out, 5 split-fp16 out, 6 +bias+GeLU2 fp16 out
template<int EPI, bool A2, bool B2, bool FP16, int NT>
__global__ void __launch_bounds__(256, 1)
hmma_gemm(const uint16_t* __restrict__ Ah, const uint16_t* __restrict__ Al, int lda,
          const uint16_t* __restrict__ Bh, const uint16_t* __restrict__ Bl, int ldb,
          float* __restrict__ C, __half* __restrict__ Ch, __half* __restrict__ Cl,
          int ldc,
          const float* __restrict__ bias, const float* __restrict__ resid,
          int M, int N, int K, float alpha) {
    constexpr int BN = 32 * NT;
    constexpr uint32_t OPA = 8192;
    constexpr uint32_t OPB = (uint32_t)BN * 64;
    constexpr uint32_t OFF_AL = OPA;
    constexpr uint32_t OFF_BH = OPA * (A2 ? 2 : 1);
    constexpr uint32_t OFF_BL = OFF_BH + OPB;
    constexpr uint32_t STAGE = OFF_BH + OPB * (B2 ? 2 : 1);

    int m0 = blockIdx.y * BM, n0 = blockIdx.x * BN;

    extern __shared__ char smem[];
    uint32_t sb = smem_u32(smem);
    int tid = threadIdx.x;

    int nch = (K + BK - 1) / BK;

    auto fill = [&](int chunk) {
        int k0 = chunk * BK;
        uint32_t sbase = sb + (uint32_t)(chunk % STAGES) * STAGE;
        const int ATOT = BM * 4, BTOT = BN * 4;
        for (int idx = tid; idx < ATOT + BTOT; idx += 256) {
            if (idx < ATOT) {
                int row = idx >> 2, gr = idx & 3;
                int kk = k0 + gr * 8;
                int ksz = (kk + 8 <= K) ? 16 : 0;
                uint32_t doff = swz64((uint32_t)row * 64u + (uint32_t)gr * 16u);
                long aoff = (long)(m0 + row) * lda + kk;
                cpasync16(sbase + doff, Ah + aoff, ksz);
                if (A2) cpasync16(sbase + OFF_AL + doff, Al + aoff, ksz);
            } else {
                int j = idx - ATOT;
                int row = j >> 2, gr = j & 3;
                int kk = k0 + gr * 8;
                int nn = n0 + row;
                int bsz = (nn < N && kk + 8 <= K) ? 16 : 0;
                long boff = (long)min(nn, N - 1) * ldb + kk;
                uint32_t doff = swz64((uint32_t)row * 64u + (uint32_t)gr * 16u);
                cpasync16(sbase + OFF_BH + doff, Bh + boff, bsz);
                if (B2) cpasync16(sbase + OFF_BL + doff, Bl + boff, bsz);
            }
        }
    };

    fill(0); CP_COMMIT();
    if (nch > 1) fill(1);
    CP_COMMIT();

    int lane = tid & 31, wid = tid >> 5;
    int wm = wid & 1, wn = wid >> 1;
    int lr = lane & 15, lc = lane >> 4;

    float acc[4][NT][4] = {};

    for (int c = 0; c < nch; c++) {
        if (c + 2 < nch) fill(c + 2);
        CP_COMMIT();
        CP_WAIT(2);
        __syncthreads();
        uint32_t sbase = sb + (uint32_t)(c % STAGES) * STAGE;
        #pragma unroll
        for (int ks = 0; ks < 2; ks++) {
            uint32_t ah[4][4], al[4][4], bh[NT][2], bl[NT][2];
            #pragma unroll
            for (int mt = 0; mt < 4; mt++) {
                uint32_t off = swz64((uint32_t)(wm*64 + mt*16 + lr) * 64u
                                     + (uint32_t)(ks*32 + lc*16));
                ldsm4(ah[mt], sbase + off);
                if (A2) ldsm4(al[mt], sbase + OFF_AL + off);
            }
            #pragma unroll
            for (int np = 0; np < NT/2; np++) {
                uint32_t off = swz64((uint32_t)(wn*(8*NT) + np*16 + lr) * 64u
                                     + (uint32_t)(ks*32 + lc*16));
                uint32_t t[4];
                ldsm4(t, sbase + OFF_BH + off);
                bh[2*np][0] = t[0]; bh[2*np+1][0] = t[1];
                bh[2*np][1] = t[2]; bh[2*np+1][1] = t[3];
                if (B2) {
                    ldsm4(t, sbase + OFF_BL + off);
                    bl[2*np][0] = t[0]; bl[2*np+1][0] = t[1];
                    bl[2*np][1] = t[2]; bl[2*np+1][1] = t[3];
                }
            }
            #pragma unroll
            for (int mt = 0; mt < 4; mt++)
                #pragma unroll
                for (int nt = 0; nt < NT; nt++) {
                    mma16816<FP16>(acc[mt][nt], ah[mt], bh[nt][0], bh[nt][1]);
                    if (B2) mma16816<FP16>(acc[mt][nt], ah[mt], bl[nt][0], bl[nt][1]);
                    if (A2) mma16816<FP16>(acc[mt][nt], al[mt], bh[nt][0], bh[nt][1]);
                }
        }
        __syncthreads();
    }

    int r0 = lane >> 2, c0 = (lane & 3) * 2;
    #pragma unroll
    for (int mt = 0; mt < 4; mt++) {
        #pragma unroll
        for (int nt = 0; nt < NT; nt++) {
            int gn = n0 + wn*(8*NT) + nt*8 + c0;
            if (gn >= N) continue;
            int gmb = m0 + wm*64 + mt*16 + r0;
            float* ac = acc[mt][nt];
            #pragma unroll
            for (int h2 = 0; h2 < 2; h2++) {
                int gm = gmb + h2 * 8;
                float v0 = ac[h2*2 + 0] * alpha;
                float v1 = ac[h2*2 + 1] * alpha;
                long off = (long)gm * ldc + gn;
                if (EPI == 3) {
                    float2 r = *(const float2*)&resid[off];
                    v0 += bias[gn] + r.x;
                    v1 += bias[gn + 1] + r.y;
                    *(float2*)&C[off] = make_float2(v0, v1);
                } else if (EPI == 5) {
                    __half2 hv, lv;
                    hv.x = __float2half_rn(v0);
                    hv.y = __float2half_rn(v1);
                    lv.x = __float2half_rn(v0 - __half2float(hv.x));
                    lv.y = __float2half_rn(v1 - __half2float(hv.y));
                    *(__half2*)&Ch[off] = hv;
                    *(__half2*)&Cl[off] = lv;
                } else if (EPI == 6) {
                    v0 += bias[gn]; v1 += bias[gn + 1];
                    v0 = v0 / (1.f + __expf(-1.702f * v0));
                    v1 = v1 / (1.f + __expf(-1.702f * v1));
                    __half2 o2;
                    o2.x = __float2half_rn(v0);
                    o2.y = __float2half_rn(v1);
                    *(__half2*)&((__half*)C)[off] = o2;
                }
            }
        }
    }
}

#define SM_QKV  98304   // 3*(2*8192 + 2*8192)    A2 B2 NT4
#define SM_N2   36864   // 3*(8192 + 4096)        A1 B1 NT2
#define SM_F1   49152   // 3*(8192 + 8192)        A1 B1 NT4

// ---------------- host orchestration ----------------
extern "C" void kernel_launch(void* const* d_in, const int* in_sizes, int n_in,
                              void* d_out, int out_size) {
    (void)in_sizes; (void)n_in; (void)out_size;
    const float* x     = (const float*)d_in[0];
    const float* pos0  = (const float*)d_in[1];
    const float* pos1  = (const float*)d_in[2];
    const float* pos2  = (const float*)d_in[3];
    const float* ln1_g = (const float*)d_in[4];
    const float* ln1_b = (const float*)d_in[5];
    const float* wq    = (const float*)d_in[6];
    const float* wk    = (const float*)d_in[7];
    const float* wv    = (const float*)d_in[8];
    const float* wo    = (const float*)d_in[9];
    const float* wo_b  = (const float*)d_in[10];
    const float* ln2_g = (const float*)d_in[11];
    const float* ln2_b = (const float*)d_in[12];
    const float* w1    = (const float*)d_in[13];
    const float* b1    = (const float*)d_in[14];
    const float* w2    = (const float*)d_in[15];
    const float* b2    = (const float*)d_in[16];

    float *xf;
    __half *hh,*hl,*h2p,*qkvh,*qkvl,*af,*ffn,*wth,*wtl,*fwh;
    cudaGetSymbolAddress((void**)&xf,   g_xf);
    cudaGetSymbolAddress((void**)&hh,   g_hh);   cudaGetSymbolAddress((void**)&hl,   g_hl);
    cudaGetSymbolAddress((void**)&h2p,  g_h2);
    cudaGetSymbolAddress((void**)&qkvh, g_qkvh); cudaGetSymbolAddress((void**)&qkvl, g_qkvl);
    cudaGetSymbolAddress((void**)&af,   g_af);
    cudaGetSymbolAddress((void**)&ffn,  g_ffn);
    cudaGetSymbolAddress((void**)&wth,  g_wth);  cudaGetSymbolAddress((void**)&wtl,  g_wtl);
    cudaGetSymbolAddress((void**)&fwh,  g_fwh);

    auto kQKV   = hmma_gemm<5,true ,true ,true,4>;   // split fp16 out, 3-term
    auto kWO    = hmma_gemm<3,false,false,true,2>;   // fp32 +bias+resid, 1-term
    auto kFFN1  = hmma_gemm<6,false,false,true,4>;   // fp16 +bias+gelu, 1-term
    auto kFFN2  = hmma_gemm<3,false,false,true,2>;   // fp32 +bias+resid, 1-term

    cudaFuncSetAttribute(kQKV,  cudaFuncAttributeMaxDynamicSharedMemorySize, SM_QKV);
    cudaFuncSetAttribute(kWO,   cudaFuncAttributeMaxDynamicSharedMemorySize, SM_N2);
    cudaFuncSetAttribute(kFFN1, cudaFuncAttributeMaxDynamicSharedMemorySize, SM_F1);
    cudaFuncSetAttribute(kFFN2, cudaFuncAttributeMaxDynamicSharedMemorySize, SM_N2);
    cudaFuncSetAttribute(flash_kernel, cudaFuncAttributeMaxDynamicSharedMemorySize, FSM);

    const float scale = 1.0f / sqrtf((float)DK);
    long n_elem = (long)MM * CC;
    int nb = (int)((n_elem + 255) / 256);

    shiftpos_kernel<<<nb, 256>>>(x, pos0, pos1, pos2, xf);
    wtrans_all_kernel<<<LL * TPL, dim3(32, 8)>>>(wq, wk, wv, wo, w1, w2, wth, wtl, fwh);

    dim3 gQKV((QKVN + 127)/128, MM/BM, 1);     // (14, 32)
    dim3 gFlash(SS/128, BB*NH);                // (8, 32)
    dim3 gN2(CC/64, MM/BM, 1);                 // (9, 32)
    dim3 gF1(FF/128, MM/BM, 1);                // (18, 32)

    for (int l = 0; l < LL; l++) {
        long wb = (long)l * WLAYER;
        long fb = (long)l * W2LAYER;
        // --- attention ---
        layernorm_split_kernel<<<MM, 256>>>(xf, ln1_g + l*CC, ln1_b + l*CC, hh, hl);
        kQKV<<<gQKV, 256, SM_QKV>>>(
            (const uint16_t*)hh, (const uint16_t*)hl, CC,
            (const uint16_t*)(wth + wb), (const uint16_t*)(wtl + wb), CC,
            nullptr, qkvh, qkvl, QKVN, nullptr, nullptr, MM, QKVN, CC, 1.f);
        flash_kernel<<<gFlash, 256, FSM>>>(qkvh, qkvl, af, scale);
        kWO<<<gN2, 256, SM_N2>>>(
            (const uint16_t*)af, nullptr, CC,
            (const uint16_t*)(fwh + fb + WO2_OFF), nullptr, CC,
            xf, nullptr, nullptr, CC, wo_b + l*CC, xf, MM, CC, CC, 1.f);

        // --- FFN ---
        layernorm_f16_kernel<<<MM, 256>>>(xf, ln2_g + l*CC, ln2_b + l*CC, h2p);
        kFFN1<<<gF1, 256, SM_F1>>>(
            (const uint16_t*)h2p, nullptr, CC,
            (const uint16_t*)(fwh + fb + W12_OFF), nullptr, CC,
            (float*)ffn, nullptr, nullptr, FF, b1 + (long)l*FF, nullptr, MM, FF, CC, 1.f);
        float* outp = (l == LL - 1) ? (float*)d_out : xf;
        kFFN2<<<gN2, 256, SM_N2>>>(
            (const uint16_t*)ffn, nullptr, FF,
            (const uint16_t*)(fwh + fb + W22_OFF), nullptr, FF,
            outp, nullptr, nullptr, CC, b2 + (long)l*CC, xf, MM, CC, FF, 1.f);
    }
}

// round 11
// speedup vs baseline: 11.3091x; 1.0550x over previous
#include <cuda_runtime.h>
#include <cuda_bf16.h>
#include <cuda_fp16.h>
#include <math.h>
#include <stdint.h>

#define BB 4
#define SS 1024
#define CC 576
#define NH 8
#define DK 72
#define LL 4
#define PD 192
#define FF 2304
#define MM (BB*SS)
#define QKN (2*CC)           // 1152

#define BM 128
#define BK 32
#define STAGES 3

// ---------------- scratch (device globals; no runtime allocation) ----------------
__device__ __align__(16) float g_xf[MM*CC];

__device__ __align__(16) __half g_hh[MM*CC],  g_hl[MM*CC];    // ln1 out (split fp16)
__device__ __align__(16) __half g_h2[MM*CC];                  // ln2 out (fp16)
__device__ __align__(16) __half g_qkh[(long)MM*QKN], g_qkl[(long)MM*QKN];
__device__ __align__(16) __half g_vf[MM*CC];                  // v (fp16)
__device__ __align__(16) __half g_af[MM*CC];                  // attention out (fp16)
__device__ __align__(16) __half g_ffn[(long)MM*FF];           // gelu out (fp16)

// wq,wk transposed [N][K] fp16 hi/lo (3-term path)
#define WLAYER  (2*CC*CC)
__device__ __align__(16) __half g_wth[(long)LL*WLAYER];
__device__ __align__(16) __half g_wtl[(long)LL*WLAYER];
// wo/wv/w1/w2 transposed single fp16 (1-term path)
#define WO2_OFF 0
#define WV2_OFF (CC*CC)
#define W12_OFF (2*CC*CC)
#define W22_OFF (2*CC*CC + CC*FF)
#define W2LAYER (2*CC*CC + 2*CC*FF)
__device__ __align__(16) __half g_fwh[(long)LL*W2LAYER];

// ================= PTX helpers =================
__device__ __forceinline__ uint32_t smem_u32(const void* p) {
    uint32_t a;
    asm("{ .reg .u64 t; cvta.to.shared.u64 t, %1; cvt.u32.u64 %0, t; }" : "=r"(a) : "l"(p));
    return a;
}
__device__ __forceinline__ void cpasync16(uint32_t dst, const void* src, int sz) {
    asm volatile("cp.async.cg.shared.global [%0], [%1], 16, %2;"
                 :: "r"(dst), "l"(src), "r"(sz) : "memory");
}
#define CP_COMMIT() asm volatile("cp.async.commit_group;" ::: "memory")
#define CP_WAIT(n)  asm volatile("cp.async.wait_group %0;" :: "n"(n) : "memory")

__device__ __forceinline__ void ldsm4(uint32_t (&r)[4], uint32_t addr) {
    asm volatile("ldmatrix.sync.aligned.m8n8.x4.shared.b16 {%0,%1,%2,%3}, [%4];"
        : "=r"(r[0]), "=r"(r[1]), "=r"(r[2]), "=r"(r[3]) : "r"(addr));
}
__device__ __forceinline__ void ldsm4t(uint32_t (&r)[4], uint32_t addr) {
    asm volatile("ldmatrix.sync.aligned.m8n8.x4.trans.shared.b16 {%0,%1,%2,%3}, [%4];"
        : "=r"(r[0]), "=r"(r[1]), "=r"(r[2]), "=r"(r[3]) : "r"(addr));
}
__device__ __forceinline__ void mma16816(float (&d)[4], const uint32_t (&a)[4],
                                         uint32_t b0, uint32_t b1) {
    asm volatile("mma.sync.aligned.m16n8k16.row.col.f32.f16.f16.f32 "
        "{%0,%1,%2,%3}, {%4,%5,%6,%7}, {%8,%9}, {%0,%1,%2,%3};"
        : "+f"(d[0]), "+f"(d[1]), "+f"(d[2]), "+f"(d[3])
        : "r"(a[0]), "r"(a[1]), "r"(a[2]), "r"(a[3]), "r"(b0), "r"(b1));
}
__device__ __forceinline__ uint32_t swz64(uint32_t o) { return o ^ ((o >> 3) & 0x30); }
__device__ __forceinline__ uint32_t packh2(float a, float b) {
    __half2 h; h.x = __float2half_rn(a); h.y = __float2half_rn(b);
    return *(uint32_t*)&h;
}

// ---------------- shift + positional embedding ----------------
__global__ void shiftpos_kernel(const float* __restrict__ x,
                                const float* __restrict__ p0,
                                const float* __restrict__ p1,
                                const float* __restrict__ p2,
                                float* __restrict__ xf) {
    long idx = (long)blockIdx.x * blockDim.x + threadIdx.x;
    if (idx >= (long)MM*CC) return;
    int c = (int)(idx % CC);
    long bs = idx / CC;
    int s = (int)(bs % SS);
    float v = (s == 0) ? 0.f : x[idx - CC];
    int t = s >> 8, hh = (s >> 4) & 15, w = s & 15;
    float p;
    if (c < PD)          p = p0[t * PD + c];
    else if (c < 2 * PD) p = p1[hh * PD + (c - PD)];
    else                 p = p2[w * PD + (c - 2 * PD)];
    xf[idx] = v + p;
}

// ---------------- layernorm, warp-per-row (8 rows / 256-thr block) ----------------
// CC = 576 = 32 lanes * 18
template<bool SPLIT>
__global__ void layernorm_kernel(const float* __restrict__ x,
                                 const float* __restrict__ g,
                                 const float* __restrict__ b,
                                 __half* __restrict__ yh,
                                 __half* __restrict__ yl) {
    int warp = threadIdx.x >> 5, lane = threadIdx.x & 31;
    long row = (long)blockIdx.x * 8 + warp;
    const float* xr = x + row * CC;
    float v[18];
    float s = 0.f;
    #pragma unroll
    for (int i = 0; i < 18; i++) { v[i] = xr[lane + i * 32]; s += v[i]; }
    #pragma unroll
    for (int o = 16; o; o >>= 1) s += __shfl_xor_sync(0xffffffffu, s, o);
    float mu = s * (1.0f / CC);
    float s2 = 0.f;
    #pragma unroll
    for (int i = 0; i < 18; i++) { float d = v[i] - mu; s2 += d * d; }
    #pragma unroll
    for (int o = 16; o; o >>= 1) s2 += __shfl_xor_sync(0xffffffffu, s2, o);
    float mult = 1e-5f + rsqrtf(s2 * (1.0f / CC));
    #pragma unroll
    for (int i = 0; i < 18; i++) {
        int c = lane + i * 32;
        float y = (v[i] - mu) * mult * g[c] + b[c];
        __half h = __float2half_rn(y);
        yh[row * CC + c] = h;
        if (SPLIT) yl[row * CC + c] = __float2half_rn(y - __half2float(h));
    }
}

// ---------------- ALL weight transposes in one launch ----------------
// per-layer tiles: [0,1296) wq/wk/wv/wo (324 each), [1296,2592) w1, [2592,3888) w2
#define TPL 3888
__global__ void wtrans_all_kernel(const float* __restrict__ wq, const float* __restrict__ wk,
                                  const float* __restrict__ wv, const float* __restrict__ wo,
                                  const float* __restrict__ w1, const float* __restrict__ w2,
                                  __half* __restrict__ qkTh, __half* __restrict__ qkTl,
                                  __half* __restrict__ fwh) {
    __shared__ float t[32][33];
    int bid = blockIdx.x;
    int layer = bid / TPL;
    int r = bid % TPL;
    const float* W; __half* Th; __half* Tl = nullptr;
    int Kd, Nd, n0, k0;
    if (r < 1296) {
        int widx = r / 324, tt = r % 324;
        Kd = CC; Nd = CC;
        n0 = (tt % 18) * 32; k0 = (tt / 18) * 32;
        const float* srcs0 = (widx == 0) ? wq : (widx == 1) ? wk : (widx == 2) ? wv : wo;
        W = srcs0 + (long)layer * CC * CC;
        if (widx < 2) {
            Th = qkTh + (long)layer * WLAYER + (long)widx * CC * CC;
            Tl = qkTl + (long)layer * WLAYER + (long)widx * CC * CC;
        } else if (widx == 2) {
            Th = fwh + (long)layer * W2LAYER + WV2_OFF;
        } else {
            Th = fwh + (long)layer * W2LAYER + WO2_OFF;
        }
    } else if (r < 2592) {
        int tt = r - 1296;
        Kd = CC; Nd = FF;
        n0 = (tt % 72) * 32; k0 = (tt / 72) * 32;
        W = w1 + (long)layer * CC * FF;
        Th = fwh + (long)layer * W2LAYER + W12_OFF;
    } else {
        int tt = r - 2592;
        Kd = FF; Nd = CC;
        n0 = (tt % 18) * 32; k0 = (tt / 18) * 32;
        W = w2 + (long)layer * CC * FF;
        Th = fwh + (long)layer * W2LAYER + W22_OFF;
    }
    int tx = threadIdx.x, ty = threadIdx.y;   // 32 x 8
    #pragma unroll
    for (int rr = 0; rr < 32; rr += 8)
        t[ty + rr][tx] = W[(long)(k0 + ty + rr) * Nd + (n0 + tx)];
    __syncthreads();
    #pragma unroll
    for (int rr = 0; rr < 32; rr += 8) {
        int nn = n0 + ty + rr, kk = k0 + tx;
        float xv = t[tx][ty + rr];
        __half h = __float2half_rn(xv);
        Th[(long)nn * Kd + kk] = h;
        if (Tl) Tl[(long)nn * Kd + kk] = __float2half_rn(xv - __half2float(h));
    }
}

// =================== fused flash attention v3 ===================
// grid (SS/128, BB*NH), heavy-first. 8 warps, warp tile 16 rows x 128 keys.
// Q/K fp16 hi/lo from qk buffer (3-term), V fp16 from vf (ldmatrix.trans), fp32 softmax.
#define FQCH 8192u           // 128 rows x 64B chunk
#define FQB  24576u          // 3 chunks
#define FSTG (3u*FQB)        // 73728: KH KL VH
#define FSM  (2u*FQB + 2u*FSTG)   // 196608

__global__ void __launch_bounds__(256, 1)
flash_kernel(const __half* __restrict__ qkh,
             const __half* __restrict__ qkl,
             const __half* __restrict__ vf,
             __half* __restrict__ af, float scale) {
    extern __shared__ char smem[];
    uint32_t sb = smem_u32(smem);
    int tid = threadIdx.x, lane = tid & 31, wid = tid >> 5;
    int mi = (int)(gridDim.x - 1 - blockIdx.x);     // heavy-first
    int z = blockIdx.y, zb = z / NH, zh = z % NH;
    int m0 = mi * 128;

    const __half* qhb = qkh + (long)(zb * SS + m0) * QKN + zh * DK;
    const __half* qlb = qkl + (long)(zb * SS + m0) * QKN + zh * DK;
    const __half* khb = qkh + (long)(zb * SS) * QKN + CC + zh * DK;
    const __half* klb = qkl + (long)(zb * SS) * QKN + CC + zh * DK;
    const __half* vhb = vf + (long)(zb * SS) * CC + zh * DK;

    // ---- load Q (once) ----
    for (int idx = tid; idx < 128 * 12; idx += 256) {
        int row = idx / 12, rem = idx % 12;
        int c = rem >> 2, g = rem & 3;
        int d0 = c * 32 + g * 8;
        int sz = (d0 + 8 <= DK) ? 16 : 0;
        uint32_t doff = (uint32_t)c * FQCH + swz64((uint32_t)row * 64u + (uint32_t)g * 16u);
        cpasync16(sb + doff, qhb + (long)row * QKN + d0, sz);
        cpasync16(sb + FQB + doff, qlb + (long)row * QKN + d0, sz);
    }

    auto load_kv = [&](int jt) {
        uint32_t st = sb + 2u*FQB + (uint32_t)(jt & 1) * FSTG;
        int kbase = jt * 128;
        for (int idx = tid; idx < 1536; idx += 256) {
            int row = idx / 12, rem = idx % 12;
            int c = rem >> 2, g = rem & 3;
            int d0 = c * 32 + g * 8;
            int sz = (d0 + 8 <= DK) ? 16 : 0;
            uint32_t doff = (uint32_t)c * FQCH + swz64((uint32_t)row * 64u + (uint32_t)g * 16u);
            cpasync16(st + doff, khb + (long)(kbase + row) * QKN + d0, sz);
            cpasync16(st + FQB + doff, klb + (long)(kbase + row) * QKN + d0, sz);
            cpasync16(st + 2u*FQB + doff, vhb + (long)(kbase + row) * CC + d0, sz);
        }
    };

    load_kv(0);
    CP_COMMIT();

    const int lr = lane & 15, lcq = lane >> 4;
    const float NEGINF = __int_as_float(0xff800000);
    float oacc[9][4] = {};
    float rm0 = NEGINF, rm1 = NEGINF, rl0 = 0.f, rl1 = 0.f;
    int qrow0 = m0 + wid * 16 + (lane >> 2);
    int qrow1 = qrow0 + 8;

    for (int jt = 0; jt <= mi; jt++) {
        if (jt < mi) { load_kv(jt + 1); CP_COMMIT(); CP_WAIT(1); }
        else CP_WAIT(0);
        __syncthreads();

        uint32_t kst = sb + 2u*FQB + (uint32_t)(jt & 1) * FSTG;
        uint32_t vst = kst + 2u*FQB;

        // ---- S = q @ k^T (3-term fp16) ----
        float sacc[16][4] = {};
        #pragma unroll
        for (int c = 0; c < 3; c++) {
            #pragma unroll
            for (int ks = 0; ks < 2; ks++) {
                if (c == 2 && ks == 1) continue;   // dims 80..95 all zero
                uint32_t aoff = (uint32_t)c * FQCH
                    + swz64((uint32_t)(wid*16 + lr) * 64u + (uint32_t)(ks*32 + lcq*16));
                uint32_t qh[4], ql[4];
                ldsm4(qh, sb + aoff);
                ldsm4(ql, sb + FQB + aoff);
                #pragma unroll
                for (int np = 0; np < 8; np++) {
                    uint32_t boff = (uint32_t)c * FQCH
                        + swz64((uint32_t)(np*16 + lr) * 64u + (uint32_t)(ks*32 + lcq*16));
                    uint32_t th[4], tl[4];
                    ldsm4(th, kst + boff);
                    ldsm4(tl, kst + FQB + boff);
                    mma16816(sacc[2*np],   qh, th[0], th[2]);
                    mma16816(sacc[2*np+1], qh, th[1], th[3]);
                    mma16816(sacc[2*np],   qh, tl[0], tl[2]);
                    mma16816(sacc[2*np+1], qh, tl[1], tl[3]);
                    mma16816(sacc[2*np],   ql, th[0], th[2]);
                    mma16816(sacc[2*np+1], ql, th[1], th[3]);
                }
            }
        }

        // ---- scale + causal mask + online softmax ----
        bool diag = (jt == mi);
        int kb = jt * 128 + (lane & 3) * 2;
        float tm0 = NEGINF, tm1 = NEGINF;
        #pragma unroll
        for (int nt = 0; nt < 16; nt++) {
            int k0 = kb + nt * 8, k1 = k0 + 1;
            float s00 = sacc[nt][0] * scale, s01 = sacc[nt][1] * scale;
            float s10 = sacc[nt][2] * scale, s11 = sacc[nt][3] * scale;
            if (diag) {
                if (k0 > qrow0) s00 = NEGINF;
                if (k1 > qrow0) s01 = NEGINF;
                if (k0 > qrow1) s10 = NEGINF;
                if (k1 > qrow1) s11 = NEGINF;
            }
            sacc[nt][0] = s00; sacc[nt][1] = s01; sacc[nt][2] = s10; sacc[nt][3] = s11;
            tm0 = fmaxf(tm0, fmaxf(s00, s01));
            tm1 = fmaxf(tm1, fmaxf(s10, s11));
        }
        tm0 = fmaxf(tm0, __shfl_xor_sync(0xffffffffu, tm0, 1));
        tm0 = fmaxf(tm0, __shfl_xor_sync(0xffffffffu, tm0, 2));
        tm1 = fmaxf(tm1, __shfl_xor_sync(0xffffffffu, tm1, 1));
        tm1 = fmaxf(tm1, __shfl_xor_sync(0xffffffffu, tm1, 2));
        float nm0 = fmaxf(rm0, tm0), nm1 = fmaxf(rm1, tm1);
        float cor0 = __expf(rm0 - nm0), cor1 = __expf(rm1 - nm1);
        rm0 = nm0; rm1 = nm1;

        uint32_t ph[16][2];
        float rs0 = 0.f, rs1 = 0.f;
        #pragma unroll
        for (int nt = 0; nt < 16; nt++) {
            float p00 = __expf(sacc[nt][0] - nm0);
            float p01 = __expf(sacc[nt][1] - nm0);
            float p10 = __expf(sacc[nt][2] - nm1);
            float p11 = __expf(sacc[nt][3] - nm1);
            rs0 += p00 + p01; rs1 += p10 + p11;
            ph[nt][0] = packh2(p00, p01);
            ph[nt][1] = packh2(p10, p11);
        }
        rl0 = rl0 * cor0 + rs0;
        rl1 = rl1 * cor1 + rs1;
        #pragma unroll
        for (int nt = 0; nt < 9; nt++) {
            oacc[nt][0] *= cor0; oacc[nt][1] *= cor0;
            oacc[nt][2] *= cor1; oacc[nt][3] *= cor1;
        }

        // ---- O += P @ V (fp16, V direct via ldmatrix.trans) ----
        #pragma unroll
        for (int kc = 0; kc < 8; kc++) {
            uint32_t pa[4] = { ph[2*kc][0], ph[2*kc][1], ph[2*kc+1][0], ph[2*kc+1][1] };
            #pragma unroll
            for (int dg = 0; dg < 5; dg++) {
                uint32_t addr = vst + (uint32_t)(dg >> 1) * FQCH
                    + swz64((uint32_t)(kc*16 + lr) * 64u
                            + (uint32_t)((dg & 1) * 32 + lcq * 16));
                uint32_t t[4];
                ldsm4t(t, addr);
                mma16816(oacc[2*dg], pa, t[0], t[1]);
                if (2*dg + 1 < 9)
                    mma16816(oacc[2*dg+1], pa, t[2], t[3]);
            }
        }
        __syncthreads();
    }

    // ---- finalize ----
    rl0 += __shfl_xor_sync(0xffffffffu, rl0, 1);
    rl0 += __shfl_xor_sync(0xffffffffu, rl0, 2);
    rl1 += __shfl_xor_sync(0xffffffffu, rl1, 1);
    rl1 += __shfl_xor_sync(0xffffffffu, rl1, 2);
    float inv0 = 1.0f / rl0, inv1 = 1.0f / rl1;
    long base0 = (long)(zb * SS + qrow0) * CC + zh * DK;
    int c0 = (lane & 3) * 2;
    #pragma unroll
    for (int nt = 0; nt < 9; nt++) {
        int d = nt * 8 + c0;
        *(__half2*)&af[base0 + d] =
            __floats2half2_rn(oacc[nt][0] * inv0, oacc[nt][1] * inv0);
        *(__half2*)&af[base0 + 8 * CC + d] =
            __floats2half2_rn(oacc[nt][2] * inv1, oacc[nt][3] * inv1);
    }
}

// =================== HMMA split GEMM ===================
// EPI: 3 +bias+resid fp32 out, 4 plain fp16 out, 5 split-fp16 out, 6 +bias+GeLU2 fp16 out
template<int EPI, bool A2, bool B2, int NT>
__global__ void __launch_bounds__(256, 1)
hmma_gemm(const uint16_t* __restrict__ Ah, const uint16_t* __restrict__ Al, int lda,
          const uint16_t* __restrict__ Bh, const uint16_t* __restrict__ Bl, int ldb,
          float* __restrict__ C, __half* __restrict__ Ch, __half* __restrict__ Cl,
          int ldc,
          const float* __restrict__ bias, const float* __restrict__ resid,
          int M, int N, int K) {
    constexpr int BN = 32 * NT;
    constexpr uint32_t OPA = 8192;
    constexpr uint32_t OPB = (uint32_t)BN * 64;
    constexpr uint32_t OFF_AL = OPA;
    constexpr uint32_t OFF_BH = OPA * (A2 ? 2 : 1);
    constexpr uint32_t OFF_BL = OFF_BH + OPB;
    constexpr uint32_t STAGE = OFF_BH + OPB * (B2 ? 2 : 1);

    int m0 = blockIdx.y * BM, n0 = blockIdx.x * BN;

    extern __shared__ char smem[];
    uint32_t sb = smem_u32(smem);
    int tid = threadIdx.x;

    int nch = (K + BK - 1) / BK;

    auto fill = [&](int chunk) {
        int k0 = chunk * BK;
        uint32_t sbase = sb + (uint32_t)(chunk % STAGES) * STAGE;
        const int ATOT = BM * 4, BTOT = BN * 4;
        for (int idx = tid; idx < ATOT + BTOT; idx += 256) {
            if (idx < ATOT) {
                int row = idx >> 2, gr = idx & 3;
                int kk = k0 + gr * 8;
                int ksz = (kk + 8 <= K) ? 16 : 0;
                uint32_t doff = swz64((uint32_t)row * 64u + (uint32_t)gr * 16u);
                long aoff = (long)(m0 + row) * lda + kk;
                cpasync16(sbase + doff, Ah + aoff, ksz);
                if (A2) cpasync16(sbase + OFF_AL + doff, Al + aoff, ksz);
            } else {
                int j = idx - ATOT;
                int row = j >> 2, gr = j & 3;
                int kk = k0 + gr * 8;
                int nn = n0 + row;
                int bsz = (nn < N && kk + 8 <= K) ? 16 : 0;
                long boff = (long)min(nn, N - 1) * ldb + kk;
                uint32_t doff = swz64((uint32_t)row * 64u + (uint32_t)gr * 16u);
                cpasync16(sbase + OFF_BH + doff, Bh + boff, bsz);
                if (B2) cpasync16(sbase + OFF_BL + doff, Bl + boff, bsz);
            }
        }
    };

    fill(0); CP_COMMIT();
    if (nch > 1) fill(1);
    CP_COMMIT();

    int lane = tid & 31, wid = tid >> 5;
    int wm = wid & 1, wn = wid >> 1;
    int lr = lane & 15, lc = lane >> 4;

    float acc[4][NT][4] = {};

    for (int c = 0; c < nch; c++) {
        if (c + 2 < nch) fill(c + 2);
        CP_COMMIT();
        CP_WAIT(2);
        __syncthreads();
        uint32_t sbase = sb + (uint32_t)(c % STAGES) * STAGE;
        #pragma unroll
        for (int ks = 0; ks < 2; ks++) {
            uint32_t ah[4][4], al[4][4], bh[NT][2], bl[NT][2];
            #pragma unroll
            for (int mt = 0; mt < 4; mt++) {
                uint32_t off = swz64((uint32_t)(wm*64 + mt*16 + lr) * 64u
                                     + (uint32_t)(ks*32 + lc*16));
                ldsm4(ah[mt], sbase + off);
                if (A2) ldsm4(al[mt], sbase + OFF_AL + off);
            }
            #pragma unroll
            for (int np = 0; np < NT/2; np++) {
                uint32_t off = swz64((uint32_t)(wn*(8*NT) + np*16 + lr) * 64u
                                     + (uint32_t)(ks*32 + lc*16));
                uint32_t t[4];
                ldsm4(t, sbase + OFF_BH + off);
                bh[2*np][0] = t[0]; bh[2*np+1][0] = t[1];
                bh[2*np][1] = t[2]; bh[2*np+1][1] = t[3];
                if (B2) {
                    ldsm4(t, sbase + OFF_BL + off);
                    bl[2*np][0] = t[0]; bl[2*np+1][0] = t[1];
                    bl[2*np][1] = t[2]; bl[2*np+1][1] = t[3];
                }
            }
            #pragma unroll
            for (int mt = 0; mt < 4; mt++)
                #pragma unroll
                for (int nt = 0; nt < NT; nt++) {
                    mma16816(acc[mt][nt], ah[mt], bh[nt][0], bh[nt][1]);
                    if (B2) mma16816(acc[mt][nt], ah[mt], bl[nt][0], bl[nt][1]);
                    if (A2) mma16816(acc[mt][nt], al[mt], bh[nt][0], bh[nt][1]);
                }
        }
        __syncthreads();
    }

    int r0 = lane >> 2, c0 = (lane & 3) * 2;
    #pragma unroll
    for (int mt = 0; mt < 4; mt++) {
        #pragma unroll
        for (int nt = 0; nt < NT; nt++) {
            int gn = n0 + wn*(8*NT) + nt*8 + c0;
            if (gn >= N) continue;
            int gmb = m0 + wm*64 + mt*16 + r0;
            float* ac = acc[mt][nt];
            #pragma unroll
            for (int h2 = 0; h2 < 2; h2++) {
                int gm = gmb + h2 * 8;
                float v0 = ac[h2*2 + 0];
                float v1 = ac[h2*2 + 1];
                long off = (long)gm * ldc + gn;
                if (EPI == 3) {
                    float2 r = *(const float2*)&resid[off];
                    v0 += bias[gn] + r.x;
                    v1 += bias[gn + 1] + r.y;
                    *(float2*)&C[off] = make_float2(v0, v1);
                } else if (EPI == 4) {
                    __half2 o2;
                    o2.x = __float2half_rn(v0);
                    o2.y = __float2half_rn(v1);
                    *(__half2*)&Ch[off] = o2;
                } else if (EPI == 5) {
                    __half2 hv, lv;
                    hv.x = __float2half_rn(v0);
                    hv.y = __float2half_rn(v1);
                    lv.x = __float2half_rn(v0 - __half2float(hv.x));
                    lv.y = __float2half_rn(v1 - __half2float(hv.y));
                    *(__half2*)&Ch[off] = hv;
                    *(__half2*)&Cl[off] = lv;
                } else if (EPI == 6) {
                    v0 += bias[gn]; v1 += bias[gn + 1];
                    v0 = v0 / (1.f + __expf(-1.702f * v0));
                    v1 = v1 / (1.f + __expf(-1.702f * v1));
                    __half2 o2;
                    o2.x = __float2half_rn(v0);
                    o2.y = __float2half_rn(v1);
                    *(__half2*)&((__half*)C)[off] = o2;
                }
            }
        }
    }
}

#define SM_QK   98304   // 3*(2*8192 + 2*8192)    A2 B2 NT4
#define SM_N2   36864   // 3*(8192 + 4096)        A1 B1 NT2
#define SM_F1   49152   // 3*(8192 + 8192)        A1 B1 NT4

// ---------------- host orchestration ----------------
extern "C" void kernel_launch(void* const* d_in, const int* in_sizes, int n_in,
                              void* d_out, int out_size) {
    (void)in_sizes; (void)n_in; (void)out_size;
    const float* x     = (const float*)d_in[0];
    const float* pos0  = (const float*)d_in[1];
    const float* pos1  = (const float*)d_in[2];
    const float* pos2  = (const float*)d_in[3];
    const float* ln1_g = (const float*)d_in[4];
    const float* ln1_b = (const float*)d_in[5];
    const float* wq    = (const float*)d_in[6];
    const float* wk    = (const float*)d_in[7];
    const float* wv    = (const float*)d_in[8];
    const float* wo    = (const float*)d_in[9];
    const float* wo_b  = (const float*)d_in[10];
    const float* ln2_g = (const float*)d_in[11];
    const float* ln2_b = (const float*)d_in[12];
    const float* w1    = (const float*)d_in[13];
    const float* b1    = (const float*)d_in[14];
    const float* w2    = (const float*)d_in[15];
    const float* b2    = (const float*)d_in[16];

    float *xf;
    __half *hh,*hl,*h2p,*qkh,*qkl,*vf,*af,*ffn,*wth,*wtl,*fwh;
    cudaGetSymbolAddress((void**)&xf,   g_xf);
    cudaGetSymbolAddress((void**)&hh,   g_hh);   cudaGetSymbolAddress((void**)&hl,   g_hl);
    cudaGetSymbolAddress((void**)&h2p,  g_h2);
    cudaGetSymbolAddress((void**)&qkh,  g_qkh);  cudaGetSymbolAddress((void**)&qkl,  g_qkl);
    cudaGetSymbolAddress((void**)&vf,   g_vf);
    cudaGetSymbolAddress((void**)&af,   g_af);
    cudaGetSymbolAddress((void**)&ffn,  g_ffn);
    cudaGetSymbolAddress((void**)&wth,  g_wth);  cudaGetSymbolAddress((void**)&wtl,  g_wtl);
    cudaGetSymbolAddress((void**)&fwh,  g_fwh);

    auto kQK    = hmma_gemm<5,true ,true ,4>;   // split fp16 out, 3-term
    auto kV     = hmma_gemm<4,false,false,4>;   // fp16 out, 1-term
    auto kWO    = hmma_gemm<3,false,false,2>;   // fp32 +bias+resid, 1-term
    auto kFFN1  = hmma_gemm<6,false,false,4>;   // fp16 +bias+gelu, 1-term
    auto kFFN2  = hmma_gemm<3,false,false,2>;   // fp32 +bias+resid, 1-term

    cudaFuncSetAttribute(kQK,   cudaFuncAttributeMaxDynamicSharedMemorySize, SM_QK);
    cudaFuncSetAttribute(kV,    cudaFuncAttributeMaxDynamicSharedMemorySize, SM_F1);
    cudaFuncSetAttribute(kWO,   cudaFuncAttributeMaxDynamicSharedMemorySize, SM_N2);
    cudaFuncSetAttribute(kFFN1, cudaFuncAttributeMaxDynamicSharedMemorySize, SM_F1);
    cudaFuncSetAttribute(kFFN2, cudaFuncAttributeMaxDynamicSharedMemorySize, SM_N2);
    cudaFuncSetAttribute(flash_kernel, cudaFuncAttributeMaxDynamicSharedMemorySize, FSM);

    const float scale = 1.0f / sqrtf((float)DK);
    long n_elem = (long)MM * CC;
    int nb = (int)((n_elem + 255) / 256);

    shiftpos_kernel<<<nb, 256>>>(x, pos0, pos1, pos2, xf);
    wtrans_all_kernel<<<LL * TPL, dim3(32, 8)>>>(wq, wk, wv, wo, w1, w2, wth, wtl, fwh);

    dim3 gQK(QKN/128, MM/BM, 1);               // (9, 32) — 288 CTAs, ~1 wave
    dim3 gV((CC + 127)/128, MM/BM, 1);         // (5, 32)
    dim3 gFlash(SS/128, BB*NH);                // (8, 32)
    dim3 gN2(CC/64, MM/BM, 1);                 // (9, 32)
    dim3 gF1(FF/128, MM/BM, 1);                // (18, 32)

    for (int l = 0; l < LL; l++) {
        long wb = (long)l * WLAYER;
        long fb = (long)l * W2LAYER;
        // --- attention ---
        layernorm_kernel<true><<<MM/8, 256>>>(xf, ln1_g + l*CC, ln1_b + l*CC, hh, hl);
        kQK<<<gQK, 256, SM_QK>>>(
            (const uint16_t*)hh, (const uint16_t*)hl, CC,
            (const uint16_t*)(wth + wb), (const uint16_t*)(wtl + wb), CC,
            nullptr, qkh, qkl, QKN, nullptr, nullptr, MM, QKN, CC);
        kV<<<gV, 256, SM_F1>>>(
            (const uint16_t*)hh, nullptr, CC,
            (const uint16_t*)(fwh + fb + WV2_OFF), nullptr, CC,
            nullptr, vf, nullptr, CC, nullptr, nullptr, MM, CC, CC);
        flash_kernel<<<gFlash, 256, FSM>>>(qkh, qkl, vf, af, scale);
        kWO<<<gN2, 256, SM_N2>>>(
            (const uint16_t*)af, nullptr, CC,
            (const uint16_t*)(fwh + fb + WO2_OFF), nullptr, CC,
            xf, nullptr, nullptr, CC, wo_b + l*CC, xf, MM, CC, CC);

        // --- FFN ---
        layernorm_kernel<false><<<MM/8, 256>>>(xf, ln2_g + l*CC, ln2_b + l*CC, h2p, nullptr);
        kFFN1<<<gF1, 256, SM_F1>>>(
            (const uint16_t*)h2p, nullptr, CC,
            (const uint16_t*)(fwh + fb + W12_OFF), nullptr, CC,
            (float*)ffn, nullptr, nullptr, FF, b1 + (long)l*FF, nullptr, MM, FF, CC);
        float* outp = (l == LL - 1) ? (float*)d_out : xf;
        kFFN2<<<gN2, 256, SM_N2>>>(
            (const uint16_t*)ffn, nullptr, FF,
            (const uint16_t*)(fwh + fb + W22_OFF), nullptr, FF,
            outp, nullptr, nullptr, CC, b2 + (long)l*CC, xf, MM, CC, FF);
    }
}

// round 12
// speedup vs baseline: 12.0104x; 1.0620x over previous
#include <cuda_runtime.h>
#include <cuda_bf16.h>
#include <cuda_fp16.h>
#include <math.h>
#include <stdint.h>

#define BB 4
#define SS 1024
#define CC 576
#define NH 8
#define DK 72
#define LL 4
#define PD 192
#define FF 2304
#define MM (BB*SS)
#define QKN (2*CC)           // 1152

#define BM 128
#define BK 32
#define STAGES 3

// ---------------- scratch (device globals; no runtime allocation) ----------------
__device__ __align__(16) float g_xf[MM*CC];

__device__ __align__(16) __half g_hh[MM*CC],  g_hl[MM*CC];    // ln1 out (split fp16)
__device__ __align__(16) __half g_h2[MM*CC];                  // ln2 out (fp16)
__device__ __align__(16) __half g_qkh[(long)MM*QKN], g_qkl[(long)MM*QKN];
__device__ __align__(16) __half g_vf[MM*CC];                  // v (fp16)
__device__ __align__(16) __half g_af[MM*CC];                  // attention out (fp16)
__device__ __align__(16) __half g_ffn[(long)MM*FF];           // gelu out (fp16)

// wq,wk transposed [N][K] fp16 hi/lo (3-term path)
#define WLAYER  (2*CC*CC)
__device__ __align__(16) __half g_wth[(long)LL*WLAYER];
__device__ __align__(16) __half g_wtl[(long)LL*WLAYER];
// wo/wv/w1/w2 transposed single fp16 (1-term path)
#define WO2_OFF 0
#define WV2_OFF (CC*CC)
#define W12_OFF (2*CC*CC)
#define W22_OFF (2*CC*CC + CC*FF)
#define W2LAYER (2*CC*CC + 2*CC*FF)
__device__ __align__(16) __half g_fwh[(long)LL*W2LAYER];

// ================= PTX helpers =================
__device__ __forceinline__ uint32_t smem_u32(const void* p) {
    uint32_t a;
    asm("{ .reg .u64 t; cvta.to.shared.u64 t, %1; cvt.u32.u64 %0, t; }" : "=r"(a) : "l"(p));
    return a;
}
__device__ __forceinline__ void cpasync16(uint32_t dst, const void* src, int sz) {
    asm volatile("cp.async.cg.shared.global [%0], [%1], 16, %2;"
                 :: "r"(dst), "l"(src), "r"(sz) : "memory");
}
#define CP_COMMIT() asm volatile("cp.async.commit_group;" ::: "memory")
#define CP_WAIT(n)  asm volatile("cp.async.wait_group %0;" :: "n"(n) : "memory")

__device__ __forceinline__ void ldsm4(uint32_t (&r)[4], uint32_t addr) {
    asm volatile("ldmatrix.sync.aligned.m8n8.x4.shared.b16 {%0,%1,%2,%3}, [%4];"
        : "=r"(r[0]), "=r"(r[1]), "=r"(r[2]), "=r"(r[3]) : "r"(addr));
}
__device__ __forceinline__ void ldsm4t(uint32_t (&r)[4], uint32_t addr) {
    asm volatile("ldmatrix.sync.aligned.m8n8.x4.trans.shared.b16 {%0,%1,%2,%3}, [%4];"
        : "=r"(r[0]), "=r"(r[1]), "=r"(r[2]), "=r"(r[3]) : "r"(addr));
}
__device__ __forceinline__ void mma16816(float (&d)[4], const uint32_t (&a)[4],
                                         uint32_t b0, uint32_t b1) {
    asm volatile("mma.sync.aligned.m16n8k16.row.col.f32.f16.f16.f32 "
        "{%0,%1,%2,%3}, {%4,%5,%6,%7}, {%8,%9}, {%0,%1,%2,%3};"
        : "+f"(d[0]), "+f"(d[1]), "+f"(d[2]), "+f"(d[3])
        : "r"(a[0]), "r"(a[1]), "r"(a[2]), "r"(a[3]), "r"(b0), "r"(b1));
}
__device__ __forceinline__ uint32_t swz64(uint32_t o) { return o ^ ((o >> 3) & 0x30); }
__device__ __forceinline__ uint32_t packh2(float a, float b) {
    __half2 h; h.x = __float2half_rn(a); h.y = __float2half_rn(b);
    return *(uint32_t*)&h;
}

// ---------------- shift + positional embedding ----------------
__global__ void shiftpos_kernel(const float* __restrict__ x,
                                const float* __restrict__ p0,
                                const float* __restrict__ p1,
                                const float* __restrict__ p2,
                                float* __restrict__ xf) {
    long idx = (long)blockIdx.x * blockDim.x + threadIdx.x;
    if (idx >= (long)MM*CC) return;
    int c = (int)(idx % CC);
    long bs = idx / CC;
    int s = (int)(bs % SS);
    float v = (s == 0) ? 0.f : x[idx - CC];
    int t = s >> 8, hh = (s >> 4) & 15, w = s & 15;
    float p;
    if (c < PD)          p = p0[t * PD + c];
    else if (c < 2 * PD) p = p1[hh * PD + (c - PD)];
    else                 p = p2[w * PD + (c - 2 * PD)];
    xf[idx] = v + p;
}

// ---------------- layernorm, warp-per-row (8 rows / 256-thr block) ----------------
template<bool SPLIT>
__global__ void layernorm_kernel(const float* __restrict__ x,
                                 const float* __restrict__ g,
                                 const float* __restrict__ b,
                                 __half* __restrict__ yh,
                                 __half* __restrict__ yl) {
    int warp = threadIdx.x >> 5, lane = threadIdx.x & 31;
    long row = (long)blockIdx.x * 8 + warp;
    const float* xr = x + row * CC;
    float v[18];
    float s = 0.f;
    #pragma unroll
    for (int i = 0; i < 18; i++) { v[i] = xr[lane + i * 32]; s += v[i]; }
    #pragma unroll
    for (int o = 16; o; o >>= 1) s += __shfl_xor_sync(0xffffffffu, s, o);
    float mu = s * (1.0f / CC);
    float s2 = 0.f;
    #pragma unroll
    for (int i = 0; i < 18; i++) { float d = v[i] - mu; s2 += d * d; }
    #pragma unroll
    for (int o = 16; o; o >>= 1) s2 += __shfl_xor_sync(0xffffffffu, s2, o);
    float mult = 1e-5f + rsqrtf(s2 * (1.0f / CC));
    #pragma unroll
    for (int i = 0; i < 18; i++) {
        int c = lane + i * 32;
        float y = (v[i] - mu) * mult * g[c] + b[c];
        __half h = __float2half_rn(y);
        yh[row * CC + c] = h;
        if (SPLIT) yl[row * CC + c] = __float2half_rn(y - __half2float(h));
    }
}

// ---------------- ALL weight transposes in one launch ----------------
#define TPL 3888
__global__ void wtrans_all_kernel(const float* __restrict__ wq, const float* __restrict__ wk,
                                  const float* __restrict__ wv, const float* __restrict__ wo,
                                  const float* __restrict__ w1, const float* __restrict__ w2,
                                  __half* __restrict__ qkTh, __half* __restrict__ qkTl,
                                  __half* __restrict__ fwh) {
    __shared__ float t[32][33];
    int bid = blockIdx.x;
    int layer = bid / TPL;
    int r = bid % TPL;
    const float* W; __half* Th; __half* Tl = nullptr;
    int Kd, Nd, n0, k0;
    if (r < 1296) {
        int widx = r / 324, tt = r % 324;
        Kd = CC; Nd = CC;
        n0 = (tt % 18) * 32; k0 = (tt / 18) * 32;
        const float* srcs0 = (widx == 0) ? wq : (widx == 1) ? wk : (widx == 2) ? wv : wo;
        W = srcs0 + (long)layer * CC * CC;
        if (widx < 2) {
            Th = qkTh + (long)layer * WLAYER + (long)widx * CC * CC;
            Tl = qkTl + (long)layer * WLAYER + (long)widx * CC * CC;
        } else if (widx == 2) {
            Th = fwh + (long)layer * W2LAYER + WV2_OFF;
        } else {
            Th = fwh + (long)layer * W2LAYER + WO2_OFF;
        }
    } else if (r < 2592) {
        int tt = r - 1296;
        Kd = CC; Nd = FF;
        n0 = (tt % 72) * 32; k0 = (tt / 72) * 32;
        W = w1 + (long)layer * CC * FF;
        Th = fwh + (long)layer * W2LAYER + W12_OFF;
    } else {
        int tt = r - 2592;
        Kd = FF; Nd = CC;
        n0 = (tt % 18) * 32; k0 = (tt / 18) * 32;
        W = w2 + (long)layer * CC * FF;
        Th = fwh + (long)layer * W2LAYER + W22_OFF;
    }
    int tx = threadIdx.x, ty = threadIdx.y;   // 32 x 8
    #pragma unroll
    for (int rr = 0; rr < 32; rr += 8)
        t[ty + rr][tx] = W[(long)(k0 + ty + rr) * Nd + (n0 + tx)];
    __syncthreads();
    #pragma unroll
    for (int rr = 0; rr < 32; rr += 8) {
        int nn = n0 + ty + rr, kk = k0 + tx;
        float xv = t[tx][ty + rr];
        __half h = __float2half_rn(xv);
        Th[(long)nn * Kd + kk] = h;
        if (Tl) Tl[(long)nn * Kd + kk] = __float2half_rn(xv - __half2float(h));
    }
}

// =================== fused flash attention v4 (balanced pairs) ===================
// grid (4, BB*NH): CTA pi handles q-tiles (7-pi) then (pi) -> uniform 9 KV-units/CTA,
// 128 CTAs = one wave. 8 warps, warp tile 16 rows x 128 keys.
// Q/K fp16 hi/lo (3-term), V fp16 direct (ldmatrix.trans), fp32 online softmax.
#define FQCH 8192u           // 128 rows x 64B chunk
#define FQB  24576u          // 3 chunks
#define FSTG (3u*FQB)        // 73728: KH KL VH
#define FSM  (2u*FQB + 2u*FSTG)   // 196608

__global__ void __launch_bounds__(256, 1)
flash_kernel(const __half* __restrict__ qkh,
             const __half* __restrict__ qkl,
             const __half* __restrict__ vf,
             __half* __restrict__ af, float scale) {
    extern __shared__ char smem[];
    uint32_t sb = smem_u32(smem);
    int tid = threadIdx.x, lane = tid & 31, wid = tid >> 5;
    int z = blockIdx.y, zb = z / NH, zh = z % NH;

    const __half* khb = qkh + (long)(zb * SS) * QKN + CC + zh * DK;
    const __half* klb = qkl + (long)(zb * SS) * QKN + CC + zh * DK;
    const __half* vhb = vf + (long)(zb * SS) * CC + zh * DK;

    auto load_kv = [&](int jt) {
        uint32_t st = sb + 2u*FQB + (uint32_t)(jt & 1) * FSTG;
        int kbase = jt * 128;
        for (int idx = tid; idx < 1536; idx += 256) {
            int row = idx / 12, rem = idx % 12;
            int c = rem >> 2, g = rem & 3;
            int d0 = c * 32 + g * 8;
            int sz = (d0 + 8 <= DK) ? 16 : 0;
            uint32_t doff = (uint32_t)c * FQCH + swz64((uint32_t)row * 64u + (uint32_t)g * 16u);
            cpasync16(st + doff, khb + (long)(kbase + row) * QKN + d0, sz);
            cpasync16(st + FQB + doff, klb + (long)(kbase + row) * QKN + d0, sz);
            cpasync16(st + 2u*FQB + doff, vhb + (long)(kbase + row) * CC + d0, sz);
        }
    };

    const int lr = lane & 15, lcq = lane >> 4;
    const float NEGINF = __int_as_float(0xff800000);

    #pragma unroll 1
    for (int half = 0; half < 2; half++) {
        int mi = half == 0 ? (7 - (int)blockIdx.x) : (int)blockIdx.x;   // heavy tile first
        int m0 = mi * 128;
        const __half* qhb = qkh + (long)(zb * SS + m0) * QKN + zh * DK;
        const __half* qlb = qkl + (long)(zb * SS + m0) * QKN + zh * DK;

        // ---- load Q (once per tile) ----
        for (int idx = tid; idx < 128 * 12; idx += 256) {
            int row = idx / 12, rem = idx % 12;
            int c = rem >> 2, g = rem & 3;
            int d0 = c * 32 + g * 8;
            int sz = (d0 + 8 <= DK) ? 16 : 0;
            uint32_t doff = (uint32_t)c * FQCH + swz64((uint32_t)row * 64u + (uint32_t)g * 16u);
            cpasync16(sb + doff, qhb + (long)row * QKN + d0, sz);
            cpasync16(sb + FQB + doff, qlb + (long)row * QKN + d0, sz);
        }
        load_kv(0);
        CP_COMMIT();

        float oacc[9][4] = {};
        float rm0 = NEGINF, rm1 = NEGINF, rl0 = 0.f, rl1 = 0.f;
        int qrow0 = m0 + wid * 16 + (lane >> 2);
        int qrow1 = qrow0 + 8;

        for (int jt = 0; jt <= mi; jt++) {
            if (jt < mi) { load_kv(jt + 1); CP_COMMIT(); CP_WAIT(1); }
            else CP_WAIT(0);
            __syncthreads();

            uint32_t kst = sb + 2u*FQB + (uint32_t)(jt & 1) * FSTG;
            uint32_t vst = kst + 2u*FQB;

            // ---- S = q @ k^T (3-term fp16) ----
            float sacc[16][4] = {};
            #pragma unroll
            for (int c = 0; c < 3; c++) {
                #pragma unroll
                for (int ks = 0; ks < 2; ks++) {
                    if (c == 2 && ks == 1) continue;   // dims 80..95 all zero
                    uint32_t aoff = (uint32_t)c * FQCH
                        + swz64((uint32_t)(wid*16 + lr) * 64u + (uint32_t)(ks*32 + lcq*16));
                    uint32_t qh[4], ql[4];
                    ldsm4(qh, sb + aoff);
                    ldsm4(ql, sb + FQB + aoff);
                    #pragma unroll
                    for (int np = 0; np < 8; np++) {
                        uint32_t boff = (uint32_t)c * FQCH
                            + swz64((uint32_t)(np*16 + lr) * 64u + (uint32_t)(ks*32 + lcq*16));
                        uint32_t th[4], tl[4];
                        ldsm4(th, kst + boff);
                        ldsm4(tl, kst + FQB + boff);
                        mma16816(sacc[2*np],   qh, th[0], th[2]);
                        mma16816(sacc[2*np+1], qh, th[1], th[3]);
                        mma16816(sacc[2*np],   qh, tl[0], tl[2]);
                        mma16816(sacc[2*np+1], qh, tl[1], tl[3]);
                        mma16816(sacc[2*np],   ql, th[0], th[2]);
                        mma16816(sacc[2*np+1], ql, th[1], th[3]);
                    }
                }
            }

            // ---- scale + causal mask + online softmax ----
            bool diag = (jt == mi);
            int kb = jt * 128 + (lane & 3) * 2;
            float tm0 = NEGINF, tm1 = NEGINF;
            #pragma unroll
            for (int nt = 0; nt < 16; nt++) {
                int k0 = kb + nt * 8, k1 = k0 + 1;
                float s00 = sacc[nt][0] * scale, s01 = sacc[nt][1] * scale;
                float s10 = sacc[nt][2] * scale, s11 = sacc[nt][3] * scale;
                if (diag) {
                    if (k0 > qrow0) s00 = NEGINF;
                    if (k1 > qrow0) s01 = NEGINF;
                    if (k0 > qrow1) s10 = NEGINF;
                    if (k1 > qrow1) s11 = NEGINF;
                }
                sacc[nt][0] = s00; sacc[nt][1] = s01; sacc[nt][2] = s10; sacc[nt][3] = s11;
                tm0 = fmaxf(tm0, fmaxf(s00, s01));
                tm1 = fmaxf(tm1, fmaxf(s10, s11));
            }
            tm0 = fmaxf(tm0, __shfl_xor_sync(0xffffffffu, tm0, 1));
            tm0 = fmaxf(tm0, __shfl_xor_sync(0xffffffffu, tm0, 2));
            tm1 = fmaxf(tm1, __shfl_xor_sync(0xffffffffu, tm1, 1));
            tm1 = fmaxf(tm1, __shfl_xor_sync(0xffffffffu, tm1, 2));
            float nm0 = fmaxf(rm0, tm0), nm1 = fmaxf(rm1, tm1);
            float cor0 = __expf(rm0 - nm0), cor1 = __expf(rm1 - nm1);
            rm0 = nm0; rm1 = nm1;

            uint32_t ph[16][2];
            float rs0 = 0.f, rs1 = 0.f;
            #pragma unroll
            for (int nt = 0; nt < 16; nt++) {
                float p00 = __expf(sacc[nt][0] - nm0);
                float p01 = __expf(sacc[nt][1] - nm0);
                float p10 = __expf(sacc[nt][2] - nm1);
                float p11 = __expf(sacc[nt][3] - nm1);
                rs0 += p00 + p01; rs1 += p10 + p11;
                ph[nt][0] = packh2(p00, p01);
                ph[nt][1] = packh2(p10, p11);
            }
            rl0 = rl0 * cor0 + rs0;
            rl1 = rl1 * cor1 + rs1;
            #pragma unroll
            for (int nt = 0; nt < 9; nt++) {
                oacc[nt][0] *= cor0; oacc[nt][1] *= cor0;
                oacc[nt][2] *= cor1; oacc[nt][3] *= cor1;
            }

            // ---- O += P @ V (fp16, V direct via ldmatrix.trans) ----
            #pragma unroll
            for (int kc = 0; kc < 8; kc++) {
                uint32_t pa[4] = { ph[2*kc][0], ph[2*kc][1], ph[2*kc+1][0], ph[2*kc+1][1] };
                #pragma unroll
                for (int dg = 0; dg < 5; dg++) {
                    uint32_t addr = vst + (uint32_t)(dg >> 1) * FQCH
                        + swz64((uint32_t)(kc*16 + lr) * 64u
                                + (uint32_t)((dg & 1) * 32 + lcq * 16));
                    uint32_t t[4];
                    ldsm4t(t, addr);
                    mma16816(oacc[2*dg], pa, t[0], t[1]);
                    if (2*dg + 1 < 9)
                        mma16816(oacc[2*dg+1], pa, t[2], t[3]);
                }
            }
            __syncthreads();
        }

        // ---- finalize tile ----
        rl0 += __shfl_xor_sync(0xffffffffu, rl0, 1);
        rl0 += __shfl_xor_sync(0xffffffffu, rl0, 2);
        rl1 += __shfl_xor_sync(0xffffffffu, rl1, 1);
        rl1 += __shfl_xor_sync(0xffffffffu, rl1, 2);
        float inv0 = 1.0f / rl0, inv1 = 1.0f / rl1;
        long base0 = (long)(zb * SS + qrow0) * CC + zh * DK;
        int c0 = (lane & 3) * 2;
        #pragma unroll
        for (int nt = 0; nt < 9; nt++) {
            int d = nt * 8 + c0;
            *(__half2*)&af[base0 + d] =
                __floats2half2_rn(oacc[nt][0] * inv0, oacc[nt][1] * inv0);
            *(__half2*)&af[base0 + 8 * CC + d] =
                __floats2half2_rn(oacc[nt][2] * inv1, oacc[nt][3] * inv1);
        }
    }
}

// =================== HMMA split GEMM ===================
// EPI: 3 +bias+resid fp32 out, 4 plain fp16 out, 5 split-fp16 out, 6 +bias+GeLU2 fp16 out
template<int EPI, bool A2, bool B2, int NT>
__global__ void __launch_bounds__(256, 1)
hmma_gemm(const uint16_t* __restrict__ Ah, const uint16_t* __restrict__ Al, int lda,
          const uint16_t* __restrict__ Bh, const uint16_t* __restrict__ Bl, int ldb,
          float* __restrict__ C, __half* __restrict__ Ch, __half* __restrict__ Cl,
          int ldc,
          const float* __restrict__ bias, const float* __restrict__ resid,
          int M, int N, int K) {
    constexpr int BN = 32 * NT;
    constexpr uint32_t OPA = 8192;
    constexpr uint32_t OPB = (uint32_t)BN * 64;
    constexpr uint32_t OFF_AL = OPA;
    constexpr uint32_t OFF_BH = OPA * (A2 ? 2 : 1);
    constexpr uint32_t OFF_BL = OFF_BH + OPB;
    constexpr uint32_t STAGE = OFF_BH + OPB * (B2 ? 2 : 1);

    int m0 = blockIdx.y * BM, n0 = blockIdx.x * BN;

    extern __shared__ char smem[];
    uint32_t sb = smem_u32(smem);
    int tid = threadIdx.x;

    int nch = (K + BK - 1) / BK;

    auto fill = [&](int chunk) {
        int k0 = chunk * BK;
        uint32_t sbase = sb + (uint32_t)(chunk % STAGES) * STAGE;
        const int ATOT = BM * 4, BTOT = BN * 4;
        for (int idx = tid; idx < ATOT + BTOT; idx += 256) {
            if (idx < ATOT) {
                int row = idx >> 2, gr = idx & 3;
                int kk = k0 + gr * 8;
                int ksz = (kk + 8 <= K) ? 16 : 0;
                uint32_t doff = swz64((uint32_t)row * 64u + (uint32_t)gr * 16u);
                long aoff = (long)(m0 + row) * lda + kk;
                cpasync16(sbase + doff, Ah + aoff, ksz);
                if (A2) cpasync16(sbase + OFF_AL + doff, Al + aoff, ksz);
            } else {
                int j = idx - ATOT;
                int row = j >> 2, gr = j & 3;
                int kk = k0 + gr * 8;
                int nn = n0 + row;
                int bsz = (nn < N && kk + 8 <= K) ? 16 : 0;
                long boff = (long)min(nn, N - 1) * ldb + kk;
                uint32_t doff = swz64((uint32_t)row * 64u + (uint32_t)gr * 16u);
                cpasync16(sbase + OFF_BH + doff, Bh + boff, bsz);
                if (B2) cpasync16(sbase + OFF_BL + doff, Bl + boff, bsz);
            }
        }
    };

    fill(0); CP_COMMIT();
    if (nch > 1) fill(1);
    CP_COMMIT();

    int lane = tid & 31, wid = tid >> 5;
    int wm = wid & 1, wn = wid >> 1;
    int lr = lane & 15, lc = lane >> 4;

    float acc[4][NT][4] = {};

    for (int c = 0; c < nch; c++) {
        if (c + 2 < nch) fill(c + 2);
        CP_COMMIT();
        CP_WAIT(2);
        __syncthreads();
        uint32_t sbase = sb + (uint32_t)(c % STAGES) * STAGE;
        #pragma unroll
        for (int ks = 0; ks < 2; ks++) {
            uint32_t ah[4][4], al[4][4], bh[NT][2], bl[NT][2];
            #pragma unroll
            for (int mt = 0; mt < 4; mt++) {
                uint32_t off = swz64((uint32_t)(wm*64 + mt*16 + lr) * 64u
                                     + (uint32_t)(ks*32 + lc*16));
                ldsm4(ah[mt], sbase + off);
                if (A2) ldsm4(al[mt], sbase + OFF_AL + off);
            }
            #pragma unroll
            for (int np = 0; np < NT/2; np++) {
                uint32_t off = swz64((uint32_t)(wn*(8*NT) + np*16 + lr) * 64u
                                     + (uint32_t)(ks*32 + lc*16));
                uint32_t t[4];
                ldsm4(t, sbase + OFF_BH + off);
                bh[2*np][0] = t[0]; bh[2*np+1][0] = t[1];
                bh[2*np][1] = t[2]; bh[2*np+1][1] = t[3];
                if (B2) {
                    ldsm4(t, sbase + OFF_BL + off);
                    bl[2*np][0] = t[0]; bl[2*np+1][0] = t[1];
                    bl[2*np][1] = t[2]; bl[2*np+1][1] = t[3];
                }
            }
            #pragma unroll
            for (int mt = 0; mt < 4; mt++)
                #pragma unroll
                for (int nt = 0; nt < NT; nt++) {
                    mma16816(acc[mt][nt], ah[mt], bh[nt][0], bh[nt][1]);
                    if (B2) mma16816(acc[mt][nt], ah[mt], bl[nt][0], bl[nt][1]);
                    if (A2) mma16816(acc[mt][nt], al[mt], bh[nt][0], bh[nt][1]);
                }
        }
        __syncthreads();
    }

    int r0 = lane >> 2, c0 = (lane & 3) * 2;
    #pragma unroll
    for (int mt = 0; mt < 4; mt++) {
        #pragma unroll
        for (int nt = 0; nt < NT; nt++) {
            int gn = n0 + wn*(8*NT) + nt*8 + c0;
            if (gn >= N) continue;
            int gmb = m0 + wm*64 + mt*16 + r0;
            float* ac = acc[mt][nt];
            #pragma unroll
            for (int h2 = 0; h2 < 2; h2++) {
                int gm = gmb + h2 * 8;
                float v0 = ac[h2*2 + 0];
                float v1 = ac[h2*2 + 1];
                long off = (long)gm * ldc + gn;
                if (EPI == 3) {
                    float2 r = *(const float2*)&resid[off];
                    v0 += bias[gn] + r.x;
                    v1 += bias[gn + 1] + r.y;
                    *(float2*)&C[off] = make_float2(v0, v1);
                } else if (EPI == 4) {
                    __half2 o2;
                    o2.x = __float2half_rn(v0);
                    o2.y = __float2half_rn(v1);
                    *(__half2*)&Ch[off] = o2;
                } else if (EPI == 5) {
                    __half2 hv, lv;
                    hv.x = __float2half_rn(v0);
                    hv.y = __float2half_rn(v1);
                    lv.x = __float2half_rn(v0 - __half2float(hv.x));
                    lv.y = __float2half_rn(v1 - __half2float(hv.y));
                    *(__half2*)&Ch[off] = hv;
                    *(__half2*)&Cl[off] = lv;
                } else if (EPI == 6) {
                    v0 += bias[gn]; v1 += bias[gn + 1];
                    v0 = v0 / (1.f + __expf(-1.702f * v0));
                    v1 = v1 / (1.f + __expf(-1.702f * v1));
                    __half2 o2;
                    o2.x = __float2half_rn(v0);
                    o2.y = __float2half_rn(v1);
                    *(__half2*)&((__half*)C)[off] = o2;
                }
            }
        }
    }
}

#define SM_QK   98304   // 3*(2*8192 + 2*8192)    A2 B2 NT4
#define SM_N2   36864   // 3*(8192 + 4096)        A1 B1 NT2
#define SM_F1   49152   // 3*(8192 + 8192)        A1 B1 NT4

// ---------------- host orchestration ----------------
extern "C" void kernel_launch(void* const* d_in, const int* in_sizes, int n_in,
                              void* d_out, int out_size) {
    (void)in_sizes; (void)n_in; (void)out_size;
    const float* x     = (const float*)d_in[0];
    const float* pos0  = (const float*)d_in[1];
    const float* pos1  = (const float*)d_in[2];
    const float* pos2  = (const float*)d_in[3];
    const float* ln1_g = (const float*)d_in[4];
    const float* ln1_b = (const float*)d_in[5];
    const float* wq    = (const float*)d_in[6];
    const float* wk    = (const float*)d_in[7];
    const float* wv    = (const float*)d_in[8];
    const float* wo    = (const float*)d_in[9];
    const float* wo_b  = (const float*)d_in[10];
    const float* ln2_g = (const float*)d_in[11];
    const float* ln2_b = (const float*)d_in[12];
    const float* w1    = (const float*)d_in[13];
    const float* b1    = (const float*)d_in[14];
    const float* w2    = (const float*)d_in[15];
    const float* b2    = (const float*)d_in[16];

    float *xf;
    __half *hh,*hl,*h2p,*qkh,*qkl,*vf,*af,*ffn,*wth,*wtl,*fwh;
    cudaGetSymbolAddress((void**)&xf,   g_xf);
    cudaGetSymbolAddress((void**)&hh,   g_hh);   cudaGetSymbolAddress((void**)&hl,   g_hl);
    cudaGetSymbolAddress((void**)&h2p,  g_h2);
    cudaGetSymbolAddress((void**)&qkh,  g_qkh);  cudaGetSymbolAddress((void**)&qkl,  g_qkl);
    cudaGetSymbolAddress((void**)&vf,   g_vf);
    cudaGetSymbolAddress((void**)&af,   g_af);
    cudaGetSymbolAddress((void**)&ffn,  g_ffn);
    cudaGetSymbolAddress((void**)&wth,  g_wth);  cudaGetSymbolAddress((void**)&wtl,  g_wtl);
    cudaGetSymbolAddress((void**)&fwh,  g_fwh);

    auto kQK    = hmma_gemm<5,true ,true ,4>;   // split fp16 out, 3-term
    auto kV     = hmma_gemm<4,false,false,4>;   // fp16 out, 1-term
    auto kWO    = hmma_gemm<3,false,false,2>;   // fp32 +bias+resid, 1-term
    auto kFFN1  = hmma_gemm<6,false,false,4>;   // fp16 +bias+gelu, 1-term
    auto kFFN2  = hmma_gemm<3,false,false,2>;   // fp32 +bias+resid, 1-term

    cudaFuncSetAttribute(kQK,   cudaFuncAttributeMaxDynamicSharedMemorySize, SM_QK);
    cudaFuncSetAttribute(kV,    cudaFuncAttributeMaxDynamicSharedMemorySize, SM_F1);
    cudaFuncSetAttribute(kWO,   cudaFuncAttributeMaxDynamicSharedMemorySize, SM_N2);
    cudaFuncSetAttribute(kFFN1, cudaFuncAttributeMaxDynamicSharedMemorySize, SM_F1);
    cudaFuncSetAttribute(kFFN2, cudaFuncAttributeMaxDynamicSharedMemorySize, SM_N2);
    cudaFuncSetAttribute(flash_kernel, cudaFuncAttributeMaxDynamicSharedMemorySize, FSM);

    const float scale = 1.0f / sqrtf((float)DK);
    long n_elem = (long)MM * CC;
    int nb = (int)((n_elem + 255) / 256);

    shiftpos_kernel<<<nb, 256>>>(x, pos0, pos1, pos2, xf);
    wtrans_all_kernel<<<LL * TPL, dim3(32, 8)>>>(wq, wk, wv, wo, w1, w2, wth, wtl, fwh);

    dim3 gQK(QKN/128, MM/BM, 1);               // (9, 32) — 288 CTAs
    dim3 gV((CC + 127)/128, MM/BM, 1);         // (5, 32)
    dim3 gFlash(4, BB*NH);                     // (4, 32) — 128 CTAs, balanced pairs
    dim3 gN2(CC/64, MM/BM, 1);                 // (9, 32)
    dim3 gF1(FF/128, MM/BM, 1);                // (18, 32)

    for (int l = 0; l < LL; l++) {
        long wb = (long)l * WLAYER;
        long fb = (long)l * W2LAYER;
        // --- attention ---
        layernorm_kernel<true><<<MM/8, 256>>>(xf, ln1_g + l*CC, ln1_b + l*CC, hh, hl);
        kQK<<<gQK, 256, SM_QK>>>(
            (const uint16_t*)hh, (const uint16_t*)hl, CC,
            (const uint16_t*)(wth + wb), (const uint16_t*)(wtl + wb), CC,
            nullptr, qkh, qkl, QKN, nullptr, nullptr, MM, QKN, CC);
        kV<<<gV, 256, SM_F1>>>(
            (const uint16_t*)hh, nullptr, CC,
            (const uint16_t*)(fwh + fb + WV2_OFF), nullptr, CC,
            nullptr, vf, nullptr, CC, nullptr, nullptr, MM, CC, CC);
        flash_kernel<<<gFlash, 256, FSM>>>(qkh, qkl, vf, af, scale);
        kWO<<<gN2, 256, SM_N2>>>(
            (const uint16_t*)af, nullptr, CC,
            (const uint16_t*)(fwh + fb + WO2_OFF), nullptr, CC,
            xf, nullptr, nullptr, CC, wo_b + l*CC, xf, MM, CC, CC);

        // --- FFN ---
        layernorm_kernel<false><<<MM/8, 256>>>(xf, ln2_g + l*CC, ln2_b + l*CC, h2p, nullptr);
        kFFN1<<<gF1, 256, SM_F1>>>(
            (const uint16_t*)h2p, nullptr, CC,
            (const uint16_t*)(fwh + fb + W12_OFF), nullptr, CC,
            (float*)ffn, nullptr, nullptr, FF, b1 + (long)l*FF, nullptr, MM, FF, CC);
        float* outp = (l == LL - 1) ? (float*)d_out : xf;
        kFFN2<<<gN2, 256, SM_N2>>>(
            (const uint16_t*)ffn, nullptr, FF,
            (const uint16_t*)(fwh + fb + W22_OFF), nullptr, FF,
            outp, nullptr, nullptr, CC, b2 + (long)l*CC, xf, MM, CC, FF);
    }
}

// round 13
// speedup vs baseline: 12.1105x; 1.0083x over previous
#include <cuda_runtime.h>
#include <cuda_bf16.h>
#include <cuda_fp16.h>
#include <math.h>
#include <stdint.h>

#define BB 4
#define SS 1024
#define CC 576
#define NH 8
#define DK 72
#define LL 4
#define PD 192
#define FF 2304
#define MM (BB*SS)
#define QKN (2*CC)           // 1152

#define BM 128
#define BK 32
#define STAGES 3

// ---------------- scratch (device globals; no runtime allocation) ----------------
__device__ __align__(16) float g_xf[MM*CC];

__device__ __align__(16) __half g_hh[MM*CC],  g_hl[MM*CC];    // ln1 out (split fp16)
__device__ __align__(16) __half g_h2[MM*CC];                  // ln2 out (fp16)
__device__ __align__(16) __half g_qkh[(long)MM*QKN], g_qkl[(long)MM*QKN];
__device__ __align__(16) __half g_vf[MM*CC];                  // v (fp16)
__device__ __align__(16) __half g_af[MM*CC];                  // attention out (fp16)
__device__ __align__(16) __half g_ffn[(long)MM*FF];           // gelu out (fp16)

// ones vector for flash row-sum column (dim 72 = 1.0, 73..79 = 0)
__device__ __align__(16) unsigned short g_ones[8] = {0x3C00u, 0, 0, 0, 0, 0, 0, 0};

// wq,wk transposed [N][K] fp16 hi/lo (3-term path)
#define WLAYER  (2*CC*CC)
__device__ __align__(16) __half g_wth[(long)LL*WLAYER];
__device__ __align__(16) __half g_wtl[(long)LL*WLAYER];
// wo/wv/w1/w2 transposed single fp16 (1-term path)
#define WO2_OFF 0
#define WV2_OFF (CC*CC)
#define W12_OFF (2*CC*CC)
#define W22_OFF (2*CC*CC + CC*FF)
#define W2LAYER (2*CC*CC + 2*CC*FF)
__device__ __align__(16) __half g_fwh[(long)LL*W2LAYER];

// ================= PTX helpers =================
__device__ __forceinline__ uint32_t smem_u32(const void* p) {
    uint32_t a;
    asm("{ .reg .u64 t; cvta.to.shared.u64 t, %1; cvt.u32.u64 %0, t; }" : "=r"(a) : "l"(p));
    return a;
}
__device__ __forceinline__ void cpasync16(uint32_t dst, const void* src, int sz) {
    asm volatile("cp.async.cg.shared.global [%0], [%1], 16, %2;"
                 :: "r"(dst), "l"(src), "r"(sz) : "memory");
}
#define CP_COMMIT() asm volatile("cp.async.commit_group;" ::: "memory")
#define CP_WAIT(n)  asm volatile("cp.async.wait_group %0;" :: "n"(n) : "memory")

__device__ __forceinline__ void ldsm4(uint32_t (&r)[4], uint32_t addr) {
    asm volatile("ldmatrix.sync.aligned.m8n8.x4.shared.b16 {%0,%1,%2,%3}, [%4];"
        : "=r"(r[0]), "=r"(r[1]), "=r"(r[2]), "=r"(r[3]) : "r"(addr));
}
__device__ __forceinline__ void ldsm4t(uint32_t (&r)[4], uint32_t addr) {
    asm volatile("ldmatrix.sync.aligned.m8n8.x4.trans.shared.b16 {%0,%1,%2,%3}, [%4];"
        : "=r"(r[0]), "=r"(r[1]), "=r"(r[2]), "=r"(r[3]) : "r"(addr));
}
__device__ __forceinline__ void mma16816(float (&d)[4], const uint32_t (&a)[4],
                                         uint32_t b0, uint32_t b1) {
    asm volatile("mma.sync.aligned.m16n8k16.row.col.f32.f16.f16.f32 "
        "{%0,%1,%2,%3}, {%4,%5,%6,%7}, {%8,%9}, {%0,%1,%2,%3};"
        : "+f"(d[0]), "+f"(d[1]), "+f"(d[2]), "+f"(d[3])
        : "r"(a[0]), "r"(a[1]), "r"(a[2]), "r"(a[3]), "r"(b0), "r"(b1));
}
__device__ __forceinline__ uint32_t swz64(uint32_t o) { return o ^ ((o >> 3) & 0x30); }
__device__ __forceinline__ uint32_t packh2(float a, float b) {
    __half2 h; h.x = __float2half_rn(a); h.y = __float2half_rn(b);
    return *(uint32_t*)&h;
}

// ---------------- shift + positional embedding ----------------
__global__ void shiftpos_kernel(const float* __restrict__ x,
                                const float* __restrict__ p0,
                                const float* __restrict__ p1,
                                const float* __restrict__ p2,
                                float* __restrict__ xf) {
    long idx = (long)blockIdx.x * blockDim.x + threadIdx.x;
    if (idx >= (long)MM*CC) return;
    int c = (int)(idx % CC);
    long bs = idx / CC;
    int s = (int)(bs % SS);
    float v = (s == 0) ? 0.f : x[idx - CC];
    int t = s >> 8, hh = (s >> 4) & 15, w = s & 15;
    float p;
    if (c < PD)          p = p0[t * PD + c];
    else if (c < 2 * PD) p = p1[hh * PD + (c - PD)];
    else                 p = p2[w * PD + (c - 2 * PD)];
    xf[idx] = v + p;
}

// ---------------- layernorm, warp-per-row (8 rows / 256-thr block) ----------------
template<bool SPLIT>
__global__ void layernorm_kernel(const float* __restrict__ x,
                                 const float* __restrict__ g,
                                 const float* __restrict__ b,
                                 __half* __restrict__ yh,
                                 __half* __restrict__ yl) {
    int warp = threadIdx.x >> 5, lane = threadIdx.x & 31;
    long row = (long)blockIdx.x * 8 + warp;
    const float* xr = x + row * CC;
    float v[18];
    float s = 0.f;
    #pragma unroll
    for (int i = 0; i < 18; i++) { v[i] = xr[lane + i * 32]; s += v[i]; }
    #pragma unroll
    for (int o = 16; o; o >>= 1) s += __shfl_xor_sync(0xffffffffu, s, o);
    float mu = s * (1.0f / CC);
    float s2 = 0.f;
    #pragma unroll
    for (int i = 0; i < 18; i++) { float d = v[i] - mu; s2 += d * d; }
    #pragma unroll
    for (int o = 16; o; o >>= 1) s2 += __shfl_xor_sync(0xffffffffu, s2, o);
    float mult = 1e-5f + rsqrtf(s2 * (1.0f / CC));
    #pragma unroll
    for (int i = 0; i < 18; i++) {
        int c = lane + i * 32;
        float y = (v[i] - mu) * mult * g[c] + b[c];
        __half h = __float2half_rn(y);
        yh[row * CC + c] = h;
        if (SPLIT) yl[row * CC + c] = __float2half_rn(y - __half2float(h));
    }
}

// ---------------- ALL weight transposes in one launch ----------------
#define TPL 3888
__global__ void wtrans_all_kernel(const float* __restrict__ wq, const float* __restrict__ wk,
                                  const float* __restrict__ wv, const float* __restrict__ wo,
                                  const float* __restrict__ w1, const float* __restrict__ w2,
                                  __half* __restrict__ qkTh, __half* __restrict__ qkTl,
                                  __half* __restrict__ fwh) {
    __shared__ float t[32][33];
    int bid = blockIdx.x;
    int layer = bid / TPL;
    int r = bid % TPL;
    const float* W; __half* Th; __half* Tl = nullptr;
    int Kd, Nd, n0, k0;
    if (r < 1296) {
        int widx = r / 324, tt = r % 324;
        Kd = CC; Nd = CC;
        n0 = (tt % 18) * 32; k0 = (tt / 18) * 32;
        const float* srcs0 = (widx == 0) ? wq : (widx == 1) ? wk : (widx == 2) ? wv : wo;
        W = srcs0 + (long)layer * CC * CC;
        if (widx < 2) {
            Th = qkTh + (long)layer * WLAYER + (long)widx * CC * CC;
            Tl = qkTl + (long)layer * WLAYER + (long)widx * CC * CC;
        } else if (widx == 2) {
            Th = fwh + (long)layer * W2LAYER + WV2_OFF;
        } else {
            Th = fwh + (long)layer * W2LAYER + WO2_OFF;
        }
    } else if (r < 2592) {
        int tt = r - 1296;
        Kd = CC; Nd = FF;
        n0 = (tt % 72) * 32; k0 = (tt / 72) * 32;
        W = w1 + (long)layer * CC * FF;
        Th = fwh + (long)layer * W2LAYER + W12_OFF;
    } else {
        int tt = r - 2592;
        Kd = FF; Nd = CC;
        n0 = (tt % 18) * 32; k0 = (tt / 18) * 32;
        W = w2 + (long)layer * CC * FF;
        Th = fwh + (long)layer * W2LAYER + W22_OFF;
    }
    int tx = threadIdx.x, ty = threadIdx.y;   // 32 x 8
    #pragma unroll
    for (int rr = 0; rr < 32; rr += 8)
        t[ty + rr][tx] = W[(long)(k0 + ty + rr) * Nd + (n0 + tx)];
    __syncthreads();
    #pragma unroll
    for (int rr = 0; rr < 32; rr += 8) {
        int nn = n0 + ty + rr, kk = k0 + tx;
        float xv = t[tx][ty + rr];
        __half h = __float2half_rn(xv);
        Th[(long)nn * Kd + kk] = h;
        if (Tl) Tl[(long)nn * Kd + kk] = __float2half_rn(xv - __half2float(h));
    }
}

// =================== fused flash attention v5 ===================
// grid (4, BB*NH): CTA pi handles q-tiles (7-pi) then (pi) -> uniform 9 KV-units/CTA.
// S = (qh+ql) @ kh^T (2-term; K unsplit). V fp16 + ones column at dim 72 gives
// the softmax denominator straight out of the PV MMA (oacc[9], col 72).
#define FQCH 8192u           // 128 rows x 64B chunk
#define FQB  24576u          // 3 chunks
#define FSTG (2u*FQB)        // 49152: KH VH
#define FSM  (2u*FQB + 2u*FSTG)   // 147456

__global__ void __launch_bounds__(256, 1)
flash_kernel(const __half* __restrict__ qkh,
             const __half* __restrict__ qkl,
             const __half* __restrict__ vf,
             const unsigned short* __restrict__ onesv,
             __half* __restrict__ af, float scale) {
    extern __shared__ char smem[];
    uint32_t sb = smem_u32(smem);
    int tid = threadIdx.x, lane = tid & 31, wid = tid >> 5;
    int z = blockIdx.y, zb = z / NH, zh = z % NH;

    const __half* khb = qkh + (long)(zb * SS) * QKN + CC + zh * DK;
    const __half* vhb = vf + (long)(zb * SS) * CC + zh * DK;

    auto load_kv = [&](int jt) {
        uint32_t st = sb + 2u*FQB + (uint32_t)(jt & 1) * FSTG;
        int kbase = jt * 128;
        for (int idx = tid; idx < 1536; idx += 256) {
            int row = idx / 12, rem = idx % 12;
            int c = rem >> 2, g = rem & 3;
            int d0 = c * 32 + g * 8;
            int sz = (d0 + 8 <= DK) ? 16 : 0;
            uint32_t doff = (uint32_t)c * FQCH + swz64((uint32_t)row * 64u + (uint32_t)g * 16u);
            cpasync16(st + doff, khb + (long)(kbase + row) * QKN + d0, sz);
            if (d0 == 72)
                cpasync16(st + FQB + doff, onesv, 16);   // ones column for row-sum
            else
                cpasync16(st + FQB + doff, vhb + (long)(kbase + row) * CC + d0, sz);
        }
    };

    const int lr = lane & 15, lcq = lane >> 4;
    const float NEGINF = __int_as_float(0xff800000);

    #pragma unroll 1
    for (int half = 0; half < 2; half++) {
        int mi = half == 0 ? (7 - (int)blockIdx.x) : (int)blockIdx.x;   // heavy tile first
        int m0 = mi * 128;
        const __half* qhb = qkh + (long)(zb * SS + m0) * QKN + zh * DK;
        const __half* qlb = qkl + (long)(zb * SS + m0) * QKN + zh * DK;

        // ---- load Q (once per tile) ----
        for (int idx = tid; idx < 128 * 12; idx += 256) {
            int row = idx / 12, rem = idx % 12;
            int c = rem >> 2, g = rem & 3;
            int d0 = c * 32 + g * 8;
            int sz = (d0 + 8 <= DK) ? 16 : 0;
            uint32_t doff = (uint32_t)c * FQCH + swz64((uint32_t)row * 64u + (uint32_t)g * 16u);
            cpasync16(sb + doff, qhb + (long)row * QKN + d0, sz);
            cpasync16(sb + FQB + doff, qlb + (long)row * QKN + d0, sz);
        }
        load_kv(0);
        CP_COMMIT();

        float oacc[10][4] = {};
        float rm0 = NEGINF, rm1 = NEGINF;
        int qrow0 = m0 + wid * 16 + (lane >> 2);
        int qrow1 = qrow0 + 8;

        for (int jt = 0; jt <= mi; jt++) {
            if (jt < mi) { load_kv(jt + 1); CP_COMMIT(); CP_WAIT(1); }
            else CP_WAIT(0);
            __syncthreads();

            uint32_t kst = sb + 2u*FQB + (uint32_t)(jt & 1) * FSTG;
            uint32_t vst = kst + FQB;

            // ---- S = (qh+ql) @ kh^T (2-term fp16) ----
            float sacc[16][4] = {};
            #pragma unroll
            for (int c = 0; c < 3; c++) {
                #pragma unroll
                for (int ks = 0; ks < 2; ks++) {
                    if (c == 2 && ks == 1) continue;   // dims 80..95 all zero
                    uint32_t aoff = (uint32_t)c * FQCH
                        + swz64((uint32_t)(wid*16 + lr) * 64u + (uint32_t)(ks*32 + lcq*16));
                    uint32_t qh[4], ql[4];
                    ldsm4(qh, sb + aoff);
                    ldsm4(ql, sb + FQB + aoff);
                    #pragma unroll
                    for (int np = 0; np < 8; np++) {
                        uint32_t boff = (uint32_t)c * FQCH
                            + swz64((uint32_t)(np*16 + lr) * 64u + (uint32_t)(ks*32 + lcq*16));
                        uint32_t th[4];
                        ldsm4(th, kst + boff);
                        mma16816(sacc[2*np],   qh, th[0], th[2]);
                        mma16816(sacc[2*np+1], qh, th[1], th[3]);
                        mma16816(sacc[2*np],   ql, th[0], th[2]);
                        mma16816(sacc[2*np+1], ql, th[1], th[3]);
                    }
                }
            }

            // ---- scale + causal mask + online softmax ----
            bool diag = (jt == mi);
            int kb = jt * 128 + (lane & 3) * 2;
            float tm0 = NEGINF, tm1 = NEGINF;
            #pragma unroll
            for (int nt = 0; nt < 16; nt++) {
                int k0 = kb + nt * 8, k1 = k0 + 1;
                float s00 = sacc[nt][0] * scale, s01 = sacc[nt][1] * scale;
                float s10 = sacc[nt][2] * scale, s11 = sacc[nt][3] * scale;
                if (diag) {
                    if (k0 > qrow0) s00 = NEGINF;
                    if (k1 > qrow0) s01 = NEGINF;
                    if (k0 > qrow1) s10 = NEGINF;
                    if (k1 > qrow1) s11 = NEGINF;
                }
                sacc[nt][0] = s00; sacc[nt][1] = s01; sacc[nt][2] = s10; sacc[nt][3] = s11;
                tm0 = fmaxf(tm0, fmaxf(s00, s01));
                tm1 = fmaxf(tm1, fmaxf(s10, s11));
            }
            tm0 = fmaxf(tm0, __shfl_xor_sync(0xffffffffu, tm0, 1));
            tm0 = fmaxf(tm0, __shfl_xor_sync(0xffffffffu, tm0, 2));
            tm1 = fmaxf(tm1, __shfl_xor_sync(0xffffffffu, tm1, 1));
            tm1 = fmaxf(tm1, __shfl_xor_sync(0xffffffffu, tm1, 2));
            float nm0 = fmaxf(rm0, tm0), nm1 = fmaxf(rm1, tm1);
            float cor0 = __expf(rm0 - nm0), cor1 = __expf(rm1 - nm1);
            rm0 = nm0; rm1 = nm1;

            uint32_t ph[16][2];
            #pragma unroll
            for (int nt = 0; nt < 16; nt++) {
                float p00 = __expf(sacc[nt][0] - nm0);
                float p01 = __expf(sacc[nt][1] - nm0);
                float p10 = __expf(sacc[nt][2] - nm1);
                float p11 = __expf(sacc[nt][3] - nm1);
                ph[nt][0] = packh2(p00, p01);
                ph[nt][1] = packh2(p10, p11);
            }
            #pragma unroll
            for (int nt = 0; nt < 10; nt++) {
                oacc[nt][0] *= cor0; oacc[nt][1] *= cor0;
                oacc[nt][2] *= cor1; oacc[nt][3] *= cor1;
            }

            // ---- O += P @ V (fp16; col 72 = ones -> row sum) ----
            #pragma unroll
            for (int kc = 0; kc < 8; kc++) {
                uint32_t pa[4] = { ph[2*kc][0], ph[2*kc][1], ph[2*kc+1][0], ph[2*kc+1][1] };
                #pragma unroll
                for (int dg = 0; dg < 5; dg++) {
                    uint32_t addr = vst + (uint32_t)(dg >> 1) * FQCH
                        + swz64((uint32_t)(kc*16 + lr) * 64u
                                + (uint32_t)((dg & 1) * 32 + lcq * 16));
                    uint32_t t[4];
                    ldsm4t(t, addr);
                    mma16816(oacc[2*dg], pa, t[0], t[1]);
                    mma16816(oacc[2*dg+1], pa, t[2], t[3]);
                }
            }
            __syncthreads();
        }

        // ---- finalize tile: denominator from ones column (col 72, c0==0 lanes) ----
        int qbase = lane & ~3;
        float rl0 = __shfl_sync(0xffffffffu, oacc[9][0], qbase);
        float rl1 = __shfl_sync(0xffffffffu, oacc[9][2], qbase);
        float inv0 = 1.0f / rl0, inv1 = 1.0f / rl1;
        long base0 = (long)(zb * SS + qrow0) * CC + zh * DK;
        int c0 = (lane & 3) * 2;
        #pragma unroll
        for (int nt = 0; nt < 9; nt++) {
            int d = nt * 8 + c0;
            *(__half2*)&af[base0 + d] =
                __floats2half2_rn(oacc[nt][0] * inv0, oacc[nt][1] * inv0);
            *(__half2*)&af[base0 + 8 * CC + d] =
                __floats2half2_rn(oacc[nt][2] * inv1, oacc[nt][3] * inv1);
        }
    }
}

// =================== HMMA split GEMM ===================
// EPI: 3 +bias+resid fp32 out, 4 plain fp16 out, 5 split-fp16 out, 6 +bias+GeLU2 fp16 out
template<int EPI, bool A2, bool B2, int NT>
__global__ void __launch_bounds__(256, 1)
hmma_gemm(const uint16_t* __restrict__ Ah, const uint16_t* __restrict__ Al, int lda,
          const uint16_t* __restrict__ Bh, const uint16_t* __restrict__ Bl, int ldb,
          float* __restrict__ C, __half* __restrict__ Ch, __half* __restrict__ Cl,
          int ldc,
          const float* __restrict__ bias, const float* __restrict__ resid,
          int M, int N, int K) {
    constexpr int BN = 32 * NT;
    constexpr uint32_t OPA = 8192;
    constexpr uint32_t OPB = (uint32_t)BN * 64;
    constexpr uint32_t OFF_AL = OPA;
    constexpr uint32_t OFF_BH = OPA * (A2 ? 2 : 1);
    constexpr uint32_t OFF_BL = OFF_BH + OPB;
    constexpr uint32_t STAGE = OFF_BH + OPB * (B2 ? 2 : 1);

    int m0 = blockIdx.y * BM, n0 = blockIdx.x * BN;

    extern __shared__ char smem[];
    uint32_t sb = smem_u32(smem);
    int tid = threadIdx.x;

    int nch = (K + BK - 1) / BK;

    auto fill = [&](int chunk) {
        int k0 = chunk * BK;
        uint32_t sbase = sb + (uint32_t)(chunk % STAGES) * STAGE;
        const int ATOT = BM * 4, BTOT = BN * 4;
        for (int idx = tid; idx < ATOT + BTOT; idx += 256) {
            if (idx < ATOT) {
                int row = idx >> 2, gr = idx & 3;
                int kk = k0 + gr * 8;
                int ksz = (kk + 8 <= K) ? 16 : 0;
                uint32_t doff = swz64((uint32_t)row * 64u + (uint32_t)gr * 16u);
                long aoff = (long)(m0 + row) * lda + kk;
                cpasync16(sbase + doff, Ah + aoff, ksz);
                if (A2) cpasync16(sbase + OFF_AL + doff, Al + aoff, ksz);
            } else {
                int j = idx - ATOT;
                int row = j >> 2, gr = j & 3;
                int kk = k0 + gr * 8;
                int nn = n0 + row;
                int bsz = (nn < N && kk + 8 <= K) ? 16 : 0;
                long boff = (long)min(nn, N - 1) * ldb + kk;
                uint32_t doff = swz64((uint32_t)row * 64u + (uint32_t)gr * 16u);
                cpasync16(sbase + OFF_BH + doff, Bh + boff, bsz);
                if (B2) cpasync16(sbase + OFF_BL + doff, Bl + boff, bsz);
            }
        }
    };

    fill(0); CP_COMMIT();
    if (nch > 1) fill(1);
    CP_COMMIT();

    int lane = tid & 31, wid = tid >> 5;
    int wm = wid & 1, wn = wid >> 1;
    int lr = lane & 15, lc = lane >> 4;

    float acc[4][NT][4] = {};

    for (int c = 0; c < nch; c++) {
        if (c + 2 < nch) fill(c + 2);
        CP_COMMIT();
        CP_WAIT(2);
        __syncthreads();
        uint32_t sbase = sb + (uint32_t)(c % STAGES) * STAGE;
        #pragma unroll
        for (int ks = 0; ks < 2; ks++) {
            uint32_t ah[4][4], al[4][4], bh[NT][2], bl[NT][2];
            #pragma unroll
            for (int mt = 0; mt < 4; mt++) {
                uint32_t off = swz64((uint32_t)(wm*64 + mt*16 + lr) * 64u
                                     + (uint32_t)(ks*32 + lc*16));
                ldsm4(ah[mt], sbase + off);
                if (A2) ldsm4(al[mt], sbase + OFF_AL + off);
            }
            #pragma unroll
            for (int np = 0; np < NT/2; np++) {
                uint32_t off = swz64((uint32_t)(wn*(8*NT) + np*16 + lr) * 64u
                                     + (uint32_t)(ks*32 + lc*16));
                uint32_t t[4];
                ldsm4(t, sbase + OFF_BH + off);
                bh[2*np][0] = t[0]; bh[2*np+1][0] = t[1];
                bh[2*np][1] = t[2]; bh[2*np+1][1] = t[3];
                if (B2) {
                    ldsm4(t, sbase + OFF_BL + off);
                    bl[2*np][0] = t[0]; bl[2*np+1][0] = t[1];
                    bl[2*np][1] = t[2]; bl[2*np+1][1] = t[3];
                }
            }
            #pragma unroll
            for (int mt = 0; mt < 4; mt++)
                #pragma unroll
                for (int nt = 0; nt < NT; nt++) {
                    mma16816(acc[mt][nt], ah[mt], bh[nt][0], bh[nt][1]);
                    if (B2) mma16816(acc[mt][nt], ah[mt], bl[nt][0], bl[nt][1]);
                    if (A2) mma16816(acc[mt][nt], al[mt], bh[nt][0], bh[nt][1]);
                }
        }
        __syncthreads();
    }

    int r0 = lane >> 2, c0 = (lane & 3) * 2;
    #pragma unroll
    for (int mt = 0; mt < 4; mt++) {
        #pragma unroll
        for (int nt = 0; nt < NT; nt++) {
            int gn = n0 + wn*(8*NT) + nt*8 + c0;
            if (gn >= N) continue;
            int gmb = m0 + wm*64 + mt*16 + r0;
            float* ac = acc[mt][nt];
            #pragma unroll
            for (int h2 = 0; h2 < 2; h2++) {
                int gm = gmb + h2 * 8;
                float v0 = ac[h2*2 + 0];
                float v1 = ac[h2*2 + 1];
                long off = (long)gm * ldc + gn;
                if (EPI == 3) {
                    float2 r = *(const float2*)&resid[off];
                    v0 += bias[gn] + r.x;
                    v1 += bias[gn + 1] + r.y;
                    *(float2*)&C[off] = make_float2(v0, v1);
                } else if (EPI == 4) {
                    __half2 o2;
                    o2.x = __float2half_rn(v0);
                    o2.y = __float2half_rn(v1);
                    *(__half2*)&Ch[off] = o2;
                } else if (EPI == 5) {
                    __half2 hv, lv;
                    hv.x = __float2half_rn(v0);
                    hv.y = __float2half_rn(v1);
                    lv.x = __float2half_rn(v0 - __half2float(hv.x));
                    lv.y = __float2half_rn(v1 - __half2float(hv.y));
                    *(__half2*)&Ch[off] = hv;
                    *(__half2*)&Cl[off] = lv;
                } else if (EPI == 6) {
                    v0 += bias[gn]; v1 += bias[gn + 1];
                    v0 = v0 / (1.f + __expf(-1.702f * v0));
                    v1 = v1 / (1.f + __expf(-1.702f * v1));
                    __half2 o2;
                    o2.x = __float2half_rn(v0);
                    o2.y = __float2half_rn(v1);
                    *(__half2*)&((__half*)C)[off] = o2;
                }
            }
        }
    }
}

#define SM_QK   98304   // 3*(2*8192 + 2*8192)    A2 B2 NT4
#define SM_N2   36864   // 3*(8192 + 4096)        A1 B1 NT2
#define SM_F1   49152   // 3*(8192 + 8192)        A1 B1 NT4

// ---------------- host orchestration ----------------
extern "C" void kernel_launch(void* const* d_in, const int* in_sizes, int n_in,
                              void* d_out, int out_size) {
    (void)in_sizes; (void)n_in; (void)out_size;
    const float* x     = (const float*)d_in[0];
    const float* pos0  = (const float*)d_in[1];
    const float* pos1  = (const float*)d_in[2];
    const float* pos2  = (const float*)d_in[3];
    const float* ln1_g = (const float*)d_in[4];
    const float* ln1_b = (const float*)d_in[5];
    const float* wq    = (const float*)d_in[6];
    const float* wk    = (const float*)d_in[7];
    const float* wv    = (const float*)d_in[8];
    const float* wo    = (const float*)d_in[9];
    const float* wo_b  = (const float*)d_in[10];
    const float* ln2_g = (const float*)d_in[11];
    const float* ln2_b = (const float*)d_in[12];
    const float* w1    = (const float*)d_in[13];
    const float* b1    = (const float*)d_in[14];
    const float* w2    = (const float*)d_in[15];
    const float* b2    = (const float*)d_in[16];

    float *xf;
    __half *hh,*hl,*h2p,*qkh,*qkl,*vf,*af,*ffn,*wth,*wtl,*fwh;
    unsigned short* onesv;
    cudaGetSymbolAddress((void**)&xf,   g_xf);
    cudaGetSymbolAddress((void**)&hh,   g_hh);   cudaGetSymbolAddress((void**)&hl,   g_hl);
    cudaGetSymbolAddress((void**)&h2p,  g_h2);
    cudaGetSymbolAddress((void**)&qkh,  g_qkh);  cudaGetSymbolAddress((void**)&qkl,  g_qkl);
    cudaGetSymbolAddress((void**)&vf,   g_vf);
    cudaGetSymbolAddress((void**)&af,   g_af);
    cudaGetSymbolAddress((void**)&ffn,  g_ffn);
    cudaGetSymbolAddress((void**)&wth,  g_wth);  cudaGetSymbolAddress((void**)&wtl,  g_wtl);
    cudaGetSymbolAddress((void**)&fwh,  g_fwh);
    cudaGetSymbolAddress((void**)&onesv, g_ones);

    auto kQK    = hmma_gemm<5,true ,true ,4>;   // split fp16 out, 3-term
    auto kV     = hmma_gemm<4,false,false,4>;   // fp16 out, 1-term
    auto kWO    = hmma_gemm<3,false,false,2>;   // fp32 +bias+resid, 1-term
    auto kFFN1  = hmma_gemm<6,false,false,4>;   // fp16 +bias+gelu, 1-term
    auto kFFN2  = hmma_gemm<3,false,false,2>;   // fp32 +bias+resid, 1-term

    cudaFuncSetAttribute(kQK,   cudaFuncAttributeMaxDynamicSharedMemorySize, SM_QK);
    cudaFuncSetAttribute(kV,    cudaFuncAttributeMaxDynamicSharedMemorySize, SM_F1);
    cudaFuncSetAttribute(kWO,   cudaFuncAttributeMaxDynamicSharedMemorySize, SM_N2);
    cudaFuncSetAttribute(kFFN1, cudaFuncAttributeMaxDynamicSharedMemorySize, SM_F1);
    cudaFuncSetAttribute(kFFN2, cudaFuncAttributeMaxDynamicSharedMemorySize, SM_N2);
    cudaFuncSetAttribute(flash_kernel, cudaFuncAttributeMaxDynamicSharedMemorySize, FSM);

    const float scale = 1.0f / sqrtf((float)DK);
    long n_elem = (long)MM * CC;
    int nb = (int)((n_elem + 255) / 256);

    shiftpos_kernel<<<nb, 256>>>(x, pos0, pos1, pos2, xf);
    wtrans_all_kernel<<<LL * TPL, dim3(32, 8)>>>(wq, wk, wv, wo, w1, w2, wth, wtl, fwh);

    dim3 gQK(QKN/128, MM/BM, 1);               // (9, 32) — 288 CTAs
    dim3 gV((CC + 127)/128, MM/BM, 1);         // (5, 32)
    dim3 gFlash(4, BB*NH);                     // (4, 32) — 128 CTAs, balanced pairs
    dim3 gN2(CC/64, MM/BM, 1);                 // (9, 32)
    dim3 gF1(FF/128, MM/BM, 1);                // (18, 32)

    for (int l = 0; l < LL; l++) {
        long wb = (long)l * WLAYER;
        long fb = (long)l * W2LAYER;
        // --- attention ---
        layernorm_kernel<true><<<MM/8, 256>>>(xf, ln1_g + l*CC, ln1_b + l*CC, hh, hl);
        kQK<<<gQK, 256, SM_QK>>>(
            (const uint16_t*)hh, (const uint16_t*)hl, CC,
            (const uint16_t*)(wth + wb), (const uint16_t*)(wtl + wb), CC,
            nullptr, qkh, qkl, QKN, nullptr, nullptr, MM, QKN, CC);
        kV<<<gV, 256, SM_F1>>>(
            (const uint16_t*)hh, nullptr, CC,
            (const uint16_t*)(fwh + fb + WV2_OFF), nullptr, CC,
            nullptr, vf, nullptr, CC, nullptr, nullptr, MM, CC, CC);
        flash_kernel<<<gFlash, 256, FSM>>>(qkh, qkl, vf, onesv, af, scale);
        kWO<<<gN2, 256, SM_N2>>>(
            (const uint16_t*)af, nullptr, CC,
            (const uint16_t*)(fwh + fb + WO2_OFF), nullptr, CC,
            xf, nullptr, nullptr, CC, wo_b + l*CC, xf, MM, CC, CC);

        // --- FFN ---
        layernorm_kernel<false><<<MM/8, 256>>>(xf, ln2_g + l*CC, ln2_b + l*CC, h2p, nullptr);
        kFFN1<<<gF1, 256, SM_F1>>>(
            (const uint16_t*)h2p, nullptr, CC,
            (const uint16_t*)(fwh + fb + W12_OFF), nullptr, CC,
            (float*)ffn, nullptr, nullptr, FF, b1 + (long)l*FF, nullptr, MM, FF, CC);
        float* outp = (l == LL - 1) ? (float*)d_out : xf;
        kFFN2<<<gN2, 256, SM_N2>>>(
            (const uint16_t*)ffn, nullptr, FF,
            (const uint16_t*)(fwh + fb + W22_OFF), nullptr, FF,
            outp, nullptr, nullptr, CC, b2 + (long)l*CC, xf, MM, CC, FF);
    }
}

// round 14
// speedup vs baseline: 12.2094x; 1.0082x over previous
#include <cuda_runtime.h>
#include <cuda_bf16.h>
#include <cuda_fp16.h>
#include <math.h>
#include <stdint.h>

#define BB 4
#define SS 1024
#define CC 576
#define NH 8
#define DK 72
#define LL 4
#define PD 192
#define FF 2304
#define MM (BB*SS)
#define QKN (2*CC)           // 1152

#define BM 128
#define BK 32
#define STAGES 3

// ---------------- scratch (device globals; no runtime allocation) ----------------
__device__ __align__(16) float g_xf[MM*CC];

__device__ __align__(16) __half g_hh[MM*CC],  g_hl[MM*CC];    // ln1 out (split fp16)
__device__ __align__(16) __half g_h2[MM*CC];                  // ln2 out (fp16)
__device__ __align__(16) __half g_qkh[(long)MM*QKN], g_qkl[(long)MM*QKN];
__device__ __align__(16) __half g_vf[MM*CC];                  // v (fp16)
__device__ __align__(16) __half g_af[MM*CC];                  // attention out (fp16)
__device__ __align__(16) __half g_ffn[(long)MM*FF];           // gelu out (fp16)

// ones vector for flash row-sum column (dim 72 = 1.0, 73..79 = 0)
__device__ __align__(16) unsigned short g_ones[8] = {0x3C00u, 0, 0, 0, 0, 0, 0, 0};

// wq,wk transposed [N][K] fp16 hi/lo (3-term path)
#define WLAYER  (2*CC*CC)
__device__ __align__(16) __half g_wth[(long)LL*WLAYER];
__device__ __align__(16) __half g_wtl[(long)LL*WLAYER];
// wo/wv/w1/w2 transposed single fp16 (1-term path)
#define WO2_OFF 0
#define WV2_OFF (CC*CC)
#define W12_OFF (2*CC*CC)
#define W22_OFF (2*CC*CC + CC*FF)
#define W2LAYER (2*CC*CC + 2*CC*FF)
__device__ __align__(16) __half g_fwh[(long)LL*W2LAYER];

// ================= PTX helpers =================
__device__ __forceinline__ uint32_t smem_u32(const void* p) {
    uint32_t a;
    asm("{ .reg .u64 t; cvta.to.shared.u64 t, %1; cvt.u32.u64 %0, t; }" : "=r"(a) : "l"(p));
    return a;
}
__device__ __forceinline__ void cpasync16(uint32_t dst, const void* src, int sz) {
    asm volatile("cp.async.cg.shared.global [%0], [%1], 16, %2;"
                 :: "r"(dst), "l"(src), "r"(sz) : "memory");
}
#define CP_COMMIT() asm volatile("cp.async.commit_group;" ::: "memory")
#define CP_WAIT(n)  asm volatile("cp.async.wait_group %0;" :: "n"(n) : "memory")

__device__ __forceinline__ void ldsm4(uint32_t (&r)[4], uint32_t addr) {
    asm volatile("ldmatrix.sync.aligned.m8n8.x4.shared.b16 {%0,%1,%2,%3}, [%4];"
        : "=r"(r[0]), "=r"(r[1]), "=r"(r[2]), "=r"(r[3]) : "r"(addr));
}
__device__ __forceinline__ void ldsm4t(uint32_t (&r)[4], uint32_t addr) {
    asm volatile("ldmatrix.sync.aligned.m8n8.x4.trans.shared.b16 {%0,%1,%2,%3}, [%4];"
        : "=r"(r[0]), "=r"(r[1]), "=r"(r[2]), "=r"(r[3]) : "r"(addr));
}
__device__ __forceinline__ void mma16816(float (&d)[4], const uint32_t (&a)[4],
                                         uint32_t b0, uint32_t b1) {
    asm volatile("mma.sync.aligned.m16n8k16.row.col.f32.f16.f16.f32 "
        "{%0,%1,%2,%3}, {%4,%5,%6,%7}, {%8,%9}, {%0,%1,%2,%3};"
        : "+f"(d[0]), "+f"(d[1]), "+f"(d[2]), "+f"(d[3])
        : "r"(a[0]), "r"(a[1]), "r"(a[2]), "r"(a[3]), "r"(b0), "r"(b1));
}
__device__ __forceinline__ uint32_t swz64(uint32_t o) { return o ^ ((o >> 3) & 0x30); }
__device__ __forceinline__ uint32_t ex2h2(float a, float b) {
    __half2 h = __floats2half2_rn(a, b);
    uint32_t in = *(uint32_t*)&h, out;
    asm("ex2.approx.f16x2 %0, %1;" : "=r"(out) : "r"(in));
    return out;
}
__device__ __forceinline__ float ex2f(float x) {
    float r;
    asm("ex2.approx.f32 %0, %1;" : "=f"(r) : "f"(x));
    return r;
}

// ---------------- shift + positional embedding ----------------
__global__ void shiftpos_kernel(const float* __restrict__ x,
                                const float* __restrict__ p0,
                                const float* __restrict__ p1,
                                const float* __restrict__ p2,
                                float* __restrict__ xf) {
    long idx = (long)blockIdx.x * blockDim.x + threadIdx.x;
    if (idx >= (long)MM*CC) return;
    int c = (int)(idx % CC);
    long bs = idx / CC;
    int s = (int)(bs % SS);
    float v = (s == 0) ? 0.f : x[idx - CC];
    int t = s >> 8, hh = (s >> 4) & 15, w = s & 15;
    float p;
    if (c < PD)          p = p0[t * PD + c];
    else if (c < 2 * PD) p = p1[hh * PD + (c - PD)];
    else                 p = p2[w * PD + (c - 2 * PD)];
    xf[idx] = v + p;
}

// ---------------- layernorm, warp-per-row (8 rows / 256-thr block) ----------------
template<bool SPLIT>
__global__ void layernorm_kernel(const float* __restrict__ x,
                                 const float* __restrict__ g,
                                 const float* __restrict__ b,
                                 __half* __restrict__ yh,
                                 __half* __restrict__ yl) {
    int warp = threadIdx.x >> 5, lane = threadIdx.x & 31;
    long row = (long)blockIdx.x * 8 + warp;
    const float* xr = x + row * CC;
    float v[18];
    float s = 0.f;
    #pragma unroll
    for (int i = 0; i < 18; i++) { v[i] = xr[lane + i * 32]; s += v[i]; }
    #pragma unroll
    for (int o = 16; o; o >>= 1) s += __shfl_xor_sync(0xffffffffu, s, o);
    float mu = s * (1.0f / CC);
    float s2 = 0.f;
    #pragma unroll
    for (int i = 0; i < 18; i++) { float d = v[i] - mu; s2 += d * d; }
    #pragma unroll
    for (int o = 16; o; o >>= 1) s2 += __shfl_xor_sync(0xffffffffu, s2, o);
    float mult = 1e-5f + rsqrtf(s2 * (1.0f / CC));
    #pragma unroll
    for (int i = 0; i < 18; i++) {
        int c = lane + i * 32;
        float y = (v[i] - mu) * mult * g[c] + b[c];
        __half h = __float2half_rn(y);
        yh[row * CC + c] = h;
        if (SPLIT) yl[row * CC + c] = __float2half_rn(y - __half2float(h));
    }
}

// ---------------- ALL weight transposes in one launch ----------------
#define TPL 3888
__global__ void wtrans_all_kernel(const float* __restrict__ wq, const float* __restrict__ wk,
                                  const float* __restrict__ wv, const float* __restrict__ wo,
                                  const float* __restrict__ w1, const float* __restrict__ w2,
                                  __half* __restrict__ qkTh, __half* __restrict__ qkTl,
                                  __half* __restrict__ fwh) {
    __shared__ float t[32][33];
    int bid = blockIdx.x;
    int layer = bid / TPL;
    int r = bid % TPL;
    const float* W; __half* Th; __half* Tl = nullptr;
    int Kd, Nd, n0, k0;
    if (r < 1296) {
        int widx = r / 324, tt = r % 324;
        Kd = CC; Nd = CC;
        n0 = (tt % 18) * 32; k0 = (tt / 18) * 32;
        const float* srcs0 = (widx == 0) ? wq : (widx == 1) ? wk : (widx == 2) ? wv : wo;
        W = srcs0 + (long)layer * CC * CC;
        if (widx < 2) {
            Th = qkTh + (long)layer * WLAYER + (long)widx * CC * CC;
            Tl = qkTl + (long)layer * WLAYER + (long)widx * CC * CC;
        } else if (widx == 2) {
            Th = fwh + (long)layer * W2LAYER + WV2_OFF;
        } else {
            Th = fwh + (long)layer * W2LAYER + WO2_OFF;
        }
    } else if (r < 2592) {
        int tt = r - 1296;
        Kd = CC; Nd = FF;
        n0 = (tt % 72) * 32; k0 = (tt / 72) * 32;
        W = w1 + (long)layer * CC * FF;
        Th = fwh + (long)layer * W2LAYER + W12_OFF;
    } else {
        int tt = r - 2592;
        Kd = FF; Nd = CC;
        n0 = (tt % 18) * 32; k0 = (tt / 18) * 32;
        W = w2 + (long)layer * CC * FF;
        Th = fwh + (long)layer * W2LAYER + W22_OFF;
    }
    int tx = threadIdx.x, ty = threadIdx.y;   // 32 x 8
    #pragma unroll
    for (int rr = 0; rr < 32; rr += 8)
        t[ty + rr][tx] = W[(long)(k0 + ty + rr) * Nd + (n0 + tx)];
    __syncthreads();
    #pragma unroll
    for (int rr = 0; rr < 32; rr += 8) {
        int nn = n0 + ty + rr, kk = k0 + tx;
        float xv = t[tx][ty + rr];
        __half h = __float2half_rn(xv);
        Th[(long)nn * Kd + kk] = h;
        if (Tl) Tl[(long)nn * Kd + kk] = __float2half_rn(xv - __half2float(h));
    }
}

// =================== fused flash attention v6 ===================
// grid (4, BB*NH): CTA pi handles q-tiles (7-pi) then (pi) -> uniform 9 KV-units/CTA.
// S = (qh+ql) @ kh^T in base-2 logits; P via ex2.approx.f16x2 (2 exps/MUFU op).
// V fp16 + ones column at dim 72 -> denominator from PV MMA. 3-stage KV ring,
// single barrier per iteration.
#define FQCH 8192u           // 128 rows x 64B chunk
#define FQB  24576u          // 3 chunks
#define FSTG (2u*FQB)        // 49152: KH VH
#define KVSTG 3
#define FSM  (2u*FQB + KVSTG*FSTG)   // 196608

__global__ void __launch_bounds__(256, 1)
flash_kernel(const __half* __restrict__ qkh,
             const __half* __restrict__ qkl,
             const __half* __restrict__ vf,
             const unsigned short* __restrict__ onesv,
             __half* __restrict__ af, float scale2) {   // scale2 = scale * log2(e)
    extern __shared__ char smem[];
    uint32_t sb = smem_u32(smem);
    int tid = threadIdx.x, lane = tid & 31, wid = tid >> 5;
    int z = blockIdx.y, zb = z / NH, zh = z % NH;

    const __half* khb = qkh + (long)(zb * SS) * QKN + CC + zh * DK;
    const __half* vhb = vf + (long)(zb * SS) * CC + zh * DK;

    auto load_kv = [&](int jt) {
        uint32_t st = sb + 2u*FQB + (uint32_t)(jt % KVSTG) * FSTG;
        int kbase = jt * 128;
        for (int idx = tid; idx < 1536; idx += 256) {
            int row = idx / 12, rem = idx % 12;
            int c = rem >> 2, g = rem & 3;
            int d0 = c * 32 + g * 8;
            int sz = (d0 + 8 <= DK) ? 16 : 0;
            uint32_t doff = (uint32_t)c * FQCH + swz64((uint32_t)row * 64u + (uint32_t)g * 16u);
            cpasync16(st + doff, khb + (long)(kbase + row) * QKN + d0, sz);
            if (d0 == 72)
                cpasync16(st + FQB + doff, onesv, 16);   // ones column for row-sum
            else
                cpasync16(st + FQB + doff, vhb + (long)(kbase + row) * CC + d0, sz);
        }
    };

    const int lr = lane & 15, lcq = lane >> 4;
    const float NEGINF = __int_as_float(0xff800000);

    #pragma unroll 1
    for (int half = 0; half < 2; half++) {
        int mi = half == 0 ? (7 - (int)blockIdx.x) : (int)blockIdx.x;   // heavy tile first
        int m0 = mi * 128;
        const __half* qhb = qkh + (long)(zb * SS + m0) * QKN + zh * DK;
        const __half* qlb = qkl + (long)(zb * SS + m0) * QKN + zh * DK;

        // ---- load Q (once per tile) ----
        for (int idx = tid; idx < 128 * 12; idx += 256) {
            int row = idx / 12, rem = idx % 12;
            int c = rem >> 2, g = rem & 3;
            int d0 = c * 32 + g * 8;
            int sz = (d0 + 8 <= DK) ? 16 : 0;
            uint32_t doff = (uint32_t)c * FQCH + swz64((uint32_t)row * 64u + (uint32_t)g * 16u);
            cpasync16(sb + doff, qhb + (long)row * QKN + d0, sz);
            cpasync16(sb + FQB + doff, qlb + (long)row * QKN + d0, sz);
        }
        load_kv(0);
        CP_COMMIT();

        float oacc[10][4] = {};
        float rm0 = NEGINF, rm1 = NEGINF;
        int qrow0 = m0 + wid * 16 + (lane >> 2);
        int qrow1 = qrow0 + 8;

        for (int jt = 0; jt <= mi; jt++) {
            if (jt < mi) { load_kv(jt + 1); CP_COMMIT(); CP_WAIT(1); }
            else CP_WAIT(0);
            __syncthreads();     // single barrier: data ready + stage jt-2 fully consumed

            uint32_t kst = sb + 2u*FQB + (uint32_t)(jt % KVSTG) * FSTG;
            uint32_t vst = kst + FQB;

            // ---- S = (qh+ql) @ kh^T (2-term fp16) ----
            float sacc[16][4] = {};
            #pragma unroll
            for (int c = 0; c < 3; c++) {
                #pragma unroll
                for (int ks = 0; ks < 2; ks++) {
                    if (c == 2 && ks == 1) continue;   // dims 80..95 all zero
                    uint32_t aoff = (uint32_t)c * FQCH
                        + swz64((uint32_t)(wid*16 + lr) * 64u + (uint32_t)(ks*32 + lcq*16));
                    uint32_t qh[4], ql[4];
                    ldsm4(qh, sb + aoff);
                    ldsm4(ql, sb + FQB + aoff);
                    #pragma unroll
                    for (int np = 0; np < 8; np++) {
                        uint32_t boff = (uint32_t)c * FQCH
                            + swz64((uint32_t)(np*16 + lr) * 64u + (uint32_t)(ks*32 + lcq*16));
                        uint32_t th[4];
                        ldsm4(th, kst + boff);
                        mma16816(sacc[2*np],   qh, th[0], th[2]);
                        mma16816(sacc[2*np+1], qh, th[1], th[3]);
                        mma16816(sacc[2*np],   ql, th[0], th[2]);
                        mma16816(sacc[2*np+1], ql, th[1], th[3]);
                    }
                }
            }

            // ---- base-2 scale + causal mask + online softmax ----
            bool diag = (jt == mi);
            int kb = jt * 128 + (lane & 3) * 2;
            float tm0 = NEGINF, tm1 = NEGINF;
            #pragma unroll
            for (int nt = 0; nt < 16; nt++) {
                int k0 = kb + nt * 8, k1 = k0 + 1;
                float s00 = sacc[nt][0] * scale2, s01 = sacc[nt][1] * scale2;
                float s10 = sacc[nt][2] * scale2, s11 = sacc[nt][3] * scale2;
                if (diag) {
                    if (k0 > qrow0) s00 = NEGINF;
                    if (k1 > qrow0) s01 = NEGINF;
                    if (k0 > qrow1) s10 = NEGINF;
                    if (k1 > qrow1) s11 = NEGINF;
                }
                sacc[nt][0] = s00; sacc[nt][1] = s01; sacc[nt][2] = s10; sacc[nt][3] = s11;
                tm0 = fmaxf(tm0, fmaxf(s00, s01));
                tm1 = fmaxf(tm1, fmaxf(s10, s11));
            }
            tm0 = fmaxf(tm0, __shfl_xor_sync(0xffffffffu, tm0, 1));
            tm0 = fmaxf(tm0, __shfl_xor_sync(0xffffffffu, tm0, 2));
            tm1 = fmaxf(tm1, __shfl_xor_sync(0xffffffffu, tm1, 1));
            tm1 = fmaxf(tm1, __shfl_xor_sync(0xffffffffu, tm1, 2));
            float nm0 = fmaxf(rm0, tm0), nm1 = fmaxf(rm1, tm1);
            float cor0 = ex2f(rm0 - nm0), cor1 = ex2f(rm1 - nm1);
            rm0 = nm0; rm1 = nm1;

            // P = 2^(s - m) computed pairwise in fp16 (ex2.approx.f16x2)
            uint32_t ph[16][2];
            #pragma unroll
            for (int nt = 0; nt < 16; nt++) {
                ph[nt][0] = ex2h2(sacc[nt][0] - nm0, sacc[nt][1] - nm0);
                ph[nt][1] = ex2h2(sacc[nt][2] - nm1, sacc[nt][3] - nm1);
            }
            #pragma unroll
            for (int nt = 0; nt < 10; nt++) {
                oacc[nt][0] *= cor0; oacc[nt][1] *= cor0;
                oacc[nt][2] *= cor1; oacc[nt][3] *= cor1;
            }

            // ---- O += P @ V (fp16; col 72 = ones -> row sum) ----
            #pragma unroll
            for (int kc = 0; kc < 8; kc++) {
                uint32_t pa[4] = { ph[2*kc][0], ph[2*kc][1], ph[2*kc+1][0], ph[2*kc+1][1] };
                #pragma unroll
                for (int dg = 0; dg < 5; dg++) {
                    uint32_t addr = vst + (uint32_t)(dg >> 1) * FQCH
                        + swz64((uint32_t)(kc*16 + lr) * 64u
                                + (uint32_t)((dg & 1) * 32 + lcq * 16));
                    uint32_t t[4];
                    ldsm4t(t, addr);
                    mma16816(oacc[2*dg], pa, t[0], t[1]);
                    mma16816(oacc[2*dg+1], pa, t[2], t[3]);
                }
            }
        }
        __syncthreads();   // protect Q buffer before next tile's loads

        // ---- finalize tile: denominator from ones column (col 72, c0==0 lanes) ----
        int qbase = lane & ~3;
        float rl0 = __shfl_sync(0xffffffffu, oacc[9][0], qbase);
        float rl1 = __shfl_sync(0xffffffffu, oacc[9][2], qbase);
        float inv0 = 1.0f / rl0, inv1 = 1.0f / rl1;
        long base0 = (long)(zb * SS + qrow0) * CC + zh * DK;
        int c0 = (lane & 3) * 2;
        #pragma unroll
        for (int nt = 0; nt < 9; nt++) {
            int d = nt * 8 + c0;
            *(__half2*)&af[base0 + d] =
                __floats2half2_rn(oacc[nt][0] * inv0, oacc[nt][1] * inv0);
            *(__half2*)&af[base0 + 8 * CC + d] =
                __floats2half2_rn(oacc[nt][2] * inv1, oacc[nt][3] * inv1);
        }
    }
}

// =================== HMMA split GEMM ===================
// EPI: 3 +bias+resid fp32 out, 4 plain fp16 out, 5 split-fp16 out, 6 +bias+GeLU2 fp16 out
template<int EPI, bool A2, bool B2, int NT>
__global__ void __launch_bounds__(256, 1)
hmma_gemm(const uint16_t* __restrict__ Ah, const uint16_t* __restrict__ Al, int lda,
          const uint16_t* __restrict__ Bh, const uint16_t* __restrict__ Bl, int ldb,
          float* __restrict__ C, __half* __restrict__ Ch, __half* __restrict__ Cl,
          int ldc,
          const float* __restrict__ bias, const float* __restrict__ resid,
          int M, int N, int K) {
    constexpr int BN = 32 * NT;
    constexpr uint32_t OPA = 8192;
    constexpr uint32_t OPB = (uint32_t)BN * 64;
    constexpr uint32_t OFF_AL = OPA;
    constexpr uint32_t OFF_BH = OPA * (A2 ? 2 : 1);
    constexpr uint32_t OFF_BL = OFF_BH + OPB;
    constexpr uint32_t STAGE = OFF_BH + OPB * (B2 ? 2 : 1);

    int m0 = blockIdx.y * BM, n0 = blockIdx.x * BN;

    extern __shared__ char smem[];
    uint32_t sb = smem_u32(smem);
    int tid = threadIdx.x;

    int nch = (K + BK - 1) / BK;

    auto fill = [&](int chunk) {
        int k0 = chunk * BK;
        uint32_t sbase = sb + (uint32_t)(chunk % STAGES) * STAGE;
        const int ATOT = BM * 4, BTOT = BN * 4;
        for (int idx = tid; idx < ATOT + BTOT; idx += 256) {
            if (idx < ATOT) {
                int row = idx >> 2, gr = idx & 3;
                int kk = k0 + gr * 8;
                int ksz = (kk + 8 <= K) ? 16 : 0;
                uint32_t doff = swz64((uint32_t)row * 64u + (uint32_t)gr * 16u);
                long aoff = (long)(m0 + row) * lda + kk;
                cpasync16(sbase + doff, Ah + aoff, ksz);
                if (A2) cpasync16(sbase + OFF_AL + doff, Al + aoff, ksz);
            } else {
                int j = idx - ATOT;
                int row = j >> 2, gr = j & 3;
                int kk = k0 + gr * 8;
                int nn = n0 + row;
                int bsz = (nn < N && kk + 8 <= K) ? 16 : 0;
                long boff = (long)min(nn, N - 1) * ldb + kk;
                uint32_t doff = swz64((uint32_t)row * 64u + (uint32_t)gr * 16u);
                cpasync16(sbase + OFF_BH + doff, Bh + boff, bsz);
                if (B2) cpasync16(sbase + OFF_BL + doff, Bl + boff, bsz);
            }
        }
    };

    fill(0); CP_COMMIT();
    if (nch > 1) fill(1);
    CP_COMMIT();

    int lane = tid & 31, wid = tid >> 5;
    int wm = wid & 1, wn = wid >> 1;
    int lr = lane & 15, lc = lane >> 4;

    float acc[4][NT][4] = {};

    for (int c = 0; c < nch; c++) {
        if (c + 2 < nch) fill(c + 2);
        CP_COMMIT();
        CP_WAIT(2);
        __syncthreads();
        uint32_t sbase = sb + (uint32_t)(c % STAGES) * STAGE;
        #pragma unroll
        for (int ks = 0; ks < 2; ks++) {
            uint32_t ah[4][4], al[4][4], bh[NT][2], bl[NT][2];
            #pragma unroll
            for (int mt = 0; mt < 4; mt++) {
                uint32_t off = swz64((uint32_t)(wm*64 + mt*16 + lr) * 64u
                                     + (uint32_t)(ks*32 + lc*16));
                ldsm4(ah[mt], sbase + off);
                if (A2) ldsm4(al[mt], sbase + OFF_AL + off);
            }
            #pragma unroll
            for (int np = 0; np < NT/2; np++) {
                uint32_t off = swz64((uint32_t)(wn*(8*NT) + np*16 + lr) * 64u
                                     + (uint32_t)(ks*32 + lc*16));
                uint32_t t[4];
                ldsm4(t, sbase + OFF_BH + off);
                bh[2*np][0] = t[0]; bh[2*np+1][0] = t[1];
                bh[2*np][1] = t[2]; bh[2*np+1][1] = t[3];
                if (B2) {
                    ldsm4(t, sbase + OFF_BL + off);
                    bl[2*np][0] = t[0]; bl[2*np+1][0] = t[1];
                    bl[2*np][1] = t[2]; bl[2*np+1][1] = t[3];
                }
            }
            #pragma unroll
            for (int mt = 0; mt < 4; mt++)
                #pragma unroll
                for (int nt = 0; nt < NT; nt++) {
                    mma16816(acc[mt][nt], ah[mt], bh[nt][0], bh[nt][1]);
                    if (B2) mma16816(acc[mt][nt], ah[mt], bl[nt][0], bl[nt][1]);
                    if (A2) mma16816(acc[mt][nt], al[mt], bh[nt][0], bh[nt][1]);
                }
        }
        __syncthreads();
    }

    int r0 = lane >> 2, c0 = (lane & 3) * 2;
    #pragma unroll
    for (int mt = 0; mt < 4; mt++) {
        #pragma unroll
        for (int nt = 0; nt < NT; nt++) {
            int gn = n0 + wn*(8*NT) + nt*8 + c0;
            if (gn >= N) continue;
            int gmb = m0 + wm*64 + mt*16 + r0;
            float* ac = acc[mt][nt];
            #pragma unroll
            for (int h2 = 0; h2 < 2; h2++) {
                int gm = gmb + h2 * 8;
                float v0 = ac[h2*2 + 0];
                float v1 = ac[h2*2 + 1];
                long off = (long)gm * ldc + gn;
                if (EPI == 3) {
                    float2 r = *(const float2*)&resid[off];
                    v0 += bias[gn] + r.x;
                    v1 += bias[gn + 1] + r.y;
                    *(float2*)&C[off] = make_float2(v0, v1);
                } else if (EPI == 4) {
                    __half2 o2;
                    o2.x = __float2half_rn(v0);
                    o2.y = __float2half_rn(v1);
                    *(__half2*)&Ch[off] = o2;
                } else if (EPI == 5) {
                    __half2 hv, lv;
                    hv.x = __float2half_rn(v0);
                    hv.y = __float2half_rn(v1);
                    lv.x = __float2half_rn(v0 - __half2float(hv.x));
                    lv.y = __float2half_rn(v1 - __half2float(hv.y));
                    *(__half2*)&Ch[off] = hv;
                    *(__half2*)&Cl[off] = lv;
                } else if (EPI == 6) {
                    v0 += bias[gn]; v1 += bias[gn + 1];
                    v0 = v0 / (1.f + __expf(-1.702f * v0));
                    v1 = v1 / (1.f + __expf(-1.702f * v1));
                    __half2 o2;
                    o2.x = __float2half_rn(v0);
                    o2.y = __float2half_rn(v1);
                    *(__half2*)&((__half*)C)[off] = o2;
                }
            }
        }
    }
}

#define SM_QK   98304   // 3*(2*8192 + 2*8192)    A2 B2 NT4
#define SM_N2   36864   // 3*(8192 + 4096)        A1 B1 NT2
#define SM_F1   49152   // 3*(8192 + 8192)        A1 B1 NT4

// ---------------- host orchestration ----------------
extern "C" void kernel_launch(void* const* d_in, const int* in_sizes, int n_in,
                              void* d_out, int out_size) {
    (void)in_sizes; (void)n_in; (void)out_size;
    const float* x     = (const float*)d_in[0];
    const float* pos0  = (const float*)d_in[1];
    const float* pos1  = (const float*)d_in[2];
    const float* pos2  = (const float*)d_in[3];
    const float* ln1_g = (const float*)d_in[4];
    const float* ln1_b = (const float*)d_in[5];
    const float* wq    = (const float*)d_in[6];
    const float* wk    = (const float*)d_in[7];
    const float* wv    = (const float*)d_in[8];
    const float* wo    = (const float*)d_in[9];
    const float* wo_b  = (const float*)d_in[10];
    const float* ln2_g = (const float*)d_in[11];
    const float* ln2_b = (const float*)d_in[12];
    const float* w1    = (const float*)d_in[13];
    const float* b1    = (const float*)d_in[14];
    const float* w2    = (const float*)d_in[15];
    const float* b2    = (const float*)d_in[16];

    float *xf;
    __half *hh,*hl,*h2p,*qkh,*qkl,*vf,*af,*ffn,*wth,*wtl,*fwh;
    unsigned short* onesv;
    cudaGetSymbolAddress((void**)&xf,   g_xf);
    cudaGetSymbolAddress((void**)&hh,   g_hh);   cudaGetSymbolAddress((void**)&hl,   g_hl);
    cudaGetSymbolAddress((void**)&h2p,  g_h2);
    cudaGetSymbolAddress((void**)&qkh,  g_qkh);  cudaGetSymbolAddress((void**)&qkl,  g_qkl);
    cudaGetSymbolAddress((void**)&vf,   g_vf);
    cudaGetSymbolAddress((void**)&af,   g_af);
    cudaGetSymbolAddress((void**)&ffn,  g_ffn);
    cudaGetSymbolAddress((void**)&wth,  g_wth);  cudaGetSymbolAddress((void**)&wtl,  g_wtl);
    cudaGetSymbolAddress((void**)&fwh,  g_fwh);
    cudaGetSymbolAddress((void**)&onesv, g_ones);

    auto kQK    = hmma_gemm<5,true ,true ,4>;   // split fp16 out, 3-term
    auto kV     = hmma_gemm<4,false,false,4>;   // fp16 out, 1-term
    auto kWO    = hmma_gemm<3,false,false,2>;   // fp32 +bias+resid, 1-term
    auto kFFN1  = hmma_gemm<6,false,false,4>;   // fp16 +bias+gelu, 1-term
    auto kFFN2  = hmma_gemm<3,false,false,2>;   // fp32 +bias+resid, 1-term

    cudaFuncSetAttribute(kQK,   cudaFuncAttributeMaxDynamicSharedMemorySize, SM_QK);
    cudaFuncSetAttribute(kV,    cudaFuncAttributeMaxDynamicSharedMemorySize, SM_F1);
    cudaFuncSetAttribute(kWO,   cudaFuncAttributeMaxDynamicSharedMemorySize, SM_N2);
    cudaFuncSetAttribute(kFFN1, cudaFuncAttributeMaxDynamicSharedMemorySize, SM_F1);
    cudaFuncSetAttribute(kFFN2, cudaFuncAttributeMaxDynamicSharedMemorySize, SM_N2);
    cudaFuncSetAttribute(flash_kernel, cudaFuncAttributeMaxDynamicSharedMemorySize, FSM);

    const float scale2 = (1.0f / sqrtf((float)DK)) * 1.4426950408889634f;
    long n_elem = (long)MM * CC;
    int nb = (int)((n_elem + 255) / 256);

    shiftpos_kernel<<<nb, 256>>>(x, pos0, pos1, pos2, xf);
    wtrans_all_kernel<<<LL * TPL, dim3(32, 8)>>>(wq, wk, wv, wo, w1, w2, wth, wtl, fwh);

    dim3 gQK(QKN/128, MM/BM, 1);               // (9, 32) — 288 CTAs
    dim3 gV((CC + 127)/128, MM/BM, 1);         // (5, 32)
    dim3 gFlash(4, BB*NH);                     // (4, 32) — 128 CTAs, balanced pairs
    dim3 gN2(CC/64, MM/BM, 1);                 // (9, 32)
    dim3 gF1(FF/128, MM/BM, 1);                // (18, 32)

    for (int l = 0; l < LL; l++) {
        long wb = (long)l * WLAYER;
        long fb = (long)l * W2LAYER;
        // --- attention ---
        layernorm_kernel<true><<<MM/8, 256>>>(xf, ln1_g + l*CC, ln1_b + l*CC, hh, hl);
        kQK<<<gQK, 256, SM_QK>>>(
            (const uint16_t*)hh, (const uint16_t*)hl, CC,
            (const uint16_t*)(wth + wb), (const uint16_t*)(wtl + wb), CC,
            nullptr, qkh, qkl, QKN, nullptr, nullptr, MM, QKN, CC);
        kV<<<gV, 256, SM_F1>>>(
            (const uint16_t*)hh, nullptr, CC,
            (const uint16_t*)(fwh + fb + WV2_OFF), nullptr, CC,
            nullptr, vf, nullptr, CC, nullptr, nullptr, MM, CC, CC);
        flash_kernel<<<gFlash, 256, FSM>>>(qkh, qkl, vf, onesv, af, scale2);
        kWO<<<gN2, 256, SM_N2>>>(
            (const uint16_t*)af, nullptr, CC,
            (const uint16_t*)(fwh + fb + WO2_OFF), nullptr, CC,
            xf, nullptr, nullptr, CC, wo_b + l*CC, xf, MM, CC, CC);

        // --- FFN ---
        layernorm_kernel<false><<<MM/8, 256>>>(xf, ln2_g + l*CC, ln2_b + l*CC, h2p, nullptr);
        kFFN1<<<gF1, 256, SM_F1>>>(
            (const uint16_t*)h2p, nullptr, CC,
            (const uint16_t*)(fwh + fb + W12_OFF), nullptr, CC,
            (float*)ffn, nullptr, nullptr, FF, b1 + (long)l*FF, nullptr, MM, FF, CC);
        float* outp = (l == LL - 1) ? (float*)d_out : xf;
        kFFN2<<<gN2, 256, SM_N2>>>(
            (const uint16_t*)ffn, nullptr, FF,
            (const uint16_t*)(fwh + fb + W22_OFF), nullptr, FF,
            outp, nullptr, nullptr, CC, b2 + (long)l*CC, xf, MM, CC, FF);
    }
}

// round 15
// speedup vs baseline: 13.1072x; 1.0735x over previous
#include <cuda_runtime.h>
#include <cuda_bf16.h>
#include <cuda_fp16.h>
#include <math.h>
#include <stdint.h>

#define BB 4
#define SS 1024
#define CC 576
#define NH 8
#define DK 72
#define LL 4
#define PD 192
#define FF 2304
#define MM (BB*SS)
#define QKN (2*CC)           // 1152

#define BM 128
#define BK 32
#define STAGES 3

// ---------------- scratch (device globals; no runtime allocation) ----------------
__device__ __align__(16) float g_xf[MM*CC];

__device__ __align__(16) __half g_hh[MM*CC];                  // ln out (fp16)
__device__ __align__(16) __half g_qkh[(long)MM*QKN];          // q,k (fp16)
__device__ __align__(16) __half g_vf[MM*CC];                  // v (fp16)
__device__ __align__(16) __half g_af[MM*CC];                  // attention out (fp16)
__device__ __align__(16) __half g_ffn[(long)MM*FF];           // gelu out (fp16)

// ones vector for flash row-sum column (dim 72 = 1.0, 73..79 = 0)
__device__ __align__(16) unsigned short g_ones[8] = {0x3C00u, 0, 0, 0, 0, 0, 0, 0};

// wq,wk transposed [N][K] fp16 hi/lo (2-term path)
#define WLAYER  (2*CC*CC)
__device__ __align__(16) __half g_wth[(long)LL*WLAYER];
__device__ __align__(16) __half g_wtl[(long)LL*WLAYER];
// wo/wv/w1/w2 transposed single fp16 (1-term path)
#define WO2_OFF 0
#define WV2_OFF (CC*CC)
#define W12_OFF (2*CC*CC)
#define W22_OFF (2*CC*CC + CC*FF)
#define W2LAYER (2*CC*CC + 2*CC*FF)
__device__ __align__(16) __half g_fwh[(long)LL*W2LAYER];

// ================= PTX helpers =================
__device__ __forceinline__ uint32_t smem_u32(const void* p) {
    uint32_t a;
    asm("{ .reg .u64 t; cvta.to.shared.u64 t, %1; cvt.u32.u64 %0, t; }" : "=r"(a) : "l"(p));
    return a;
}
__device__ __forceinline__ void cpasync16(uint32_t dst, const void* src, int sz) {
    asm volatile("cp.async.cg.shared.global [%0], [%1], 16, %2;"
                 :: "r"(dst), "l"(src), "r"(sz) : "memory");
}
#define CP_COMMIT() asm volatile("cp.async.commit_group;" ::: "memory")
#define CP_WAIT(n)  asm volatile("cp.async.wait_group %0;" :: "n"(n) : "memory")

__device__ __forceinline__ void ldsm4(uint32_t (&r)[4], uint32_t addr) {
    asm volatile("ldmatrix.sync.aligned.m8n8.x4.shared.b16 {%0,%1,%2,%3}, [%4];"
        : "=r"(r[0]), "=r"(r[1]), "=r"(r[2]), "=r"(r[3]) : "r"(addr));
}
__device__ __forceinline__ void ldsm4t(uint32_t (&r)[4], uint32_t addr) {
    asm volatile("ldmatrix.sync.aligned.m8n8.x4.trans.shared.b16 {%0,%1,%2,%3}, [%4];"
        : "=r"(r[0]), "=r"(r[1]), "=r"(r[2]), "=r"(r[3]) : "r"(addr));
}
__device__ __forceinline__ void mma16816(float (&d)[4], const uint32_t (&a)[4],
                                         uint32_t b0, uint32_t b1) {
    asm volatile("mma.sync.aligned.m16n8k16.row.col.f32.f16.f16.f32 "
        "{%0,%1,%2,%3}, {%4,%5,%6,%7}, {%8,%9}, {%0,%1,%2,%3};"
        : "+f"(d[0]), "+f"(d[1]), "+f"(d[2]), "+f"(d[3])
        : "r"(a[0]), "r"(a[1]), "r"(a[2]), "r"(a[3]), "r"(b0), "r"(b1));
}
__device__ __forceinline__ uint32_t swz64(uint32_t o) { return o ^ ((o >> 3) & 0x30); }
__device__ __forceinline__ uint32_t ex2h2(float a, float b) {
    __half2 h = __floats2half2_rn(a, b);
    uint32_t in = *(uint32_t*)&h, out;
    asm("ex2.approx.f16x2 %0, %1;" : "=r"(out) : "r"(in));
    return out;
}
__device__ __forceinline__ float ex2f(float x) {
    float r;
    asm("ex2.approx.f32 %0, %1;" : "=f"(r) : "f"(x));
    return r;
}

// ---------------- shift + positional embedding ----------------
__global__ void shiftpos_kernel(const float* __restrict__ x,
                                const float* __restrict__ p0,
                                const float* __restrict__ p1,
                                const float* __restrict__ p2,
                                float* __restrict__ xf) {
    long idx = (long)blockIdx.x * blockDim.x + threadIdx.x;
    if (idx >= (long)MM*CC) return;
    int c = (int)(idx % CC);
    long bs = idx / CC;
    int s = (int)(bs % SS);
    float v = (s == 0) ? 0.f : x[idx - CC];
    int t = s >> 8, hh = (s >> 4) & 15, w = s & 15;
    float p;
    if (c < PD)          p = p0[t * PD + c];
    else if (c < 2 * PD) p = p1[hh * PD + (c - PD)];
    else                 p = p2[w * PD + (c - 2 * PD)];
    xf[idx] = v + p;
}

// ---------------- layernorm, warp-per-row (8 rows / 256-thr block), fp16 out ----------------
__global__ void layernorm_kernel(const float* __restrict__ x,
                                 const float* __restrict__ g,
                                 const float* __restrict__ b,
                                 __half* __restrict__ yh) {
    int warp = threadIdx.x >> 5, lane = threadIdx.x & 31;
    long row = (long)blockIdx.x * 8 + warp;
    const float* xr = x + row * CC;
    float v[18];
    float s = 0.f;
    #pragma unroll
    for (int i = 0; i < 18; i++) { v[i] = xr[lane + i * 32]; s += v[i]; }
    #pragma unroll
    for (int o = 16; o; o >>= 1) s += __shfl_xor_sync(0xffffffffu, s, o);
    float mu = s * (1.0f / CC);
    float s2 = 0.f;
    #pragma unroll
    for (int i = 0; i < 18; i++) { float d = v[i] - mu; s2 += d * d; }
    #pragma unroll
    for (int o = 16; o; o >>= 1) s2 += __shfl_xor_sync(0xffffffffu, s2, o);
    float mult = 1e-5f + rsqrtf(s2 * (1.0f / CC));
    #pragma unroll
    for (int i = 0; i < 18; i++) {
        int c = lane + i * 32;
        yh[row * CC + c] = __float2half_rn((v[i] - mu) * mult * g[c] + b[c]);
    }
}

// ---------------- ALL weight transposes in one launch ----------------
#define TPL 3888
__global__ void wtrans_all_kernel(const float* __restrict__ wq, const float* __restrict__ wk,
                                  const float* __restrict__ wv, const float* __restrict__ wo,
                                  const float* __restrict__ w1, const float* __restrict__ w2,
                                  __half* __restrict__ qkTh, __half* __restrict__ qkTl,
                                  __half* __restrict__ fwh) {
    __shared__ float t[32][33];
    int bid = blockIdx.x;
    int layer = bid / TPL;
    int r = bid % TPL;
    const float* W; __half* Th; __half* Tl = nullptr;
    int Kd, Nd, n0, k0;
    if (r < 1296) {
        int widx = r / 324, tt = r % 324;
        Kd = CC; Nd = CC;
        n0 = (tt % 18) * 32; k0 = (tt / 18) * 32;
        const float* srcs0 = (widx == 0) ? wq : (widx == 1) ? wk : (widx == 2) ? wv : wo;
        W = srcs0 + (long)layer * CC * CC;
        if (widx < 2) {
            Th = qkTh + (long)layer * WLAYER + (long)widx * CC * CC;
            Tl = qkTl + (long)layer * WLAYER + (long)widx * CC * CC;
        } else if (widx == 2) {
            Th = fwh + (long)layer * W2LAYER + WV2_OFF;
        } else {
            Th = fwh + (long)layer * W2LAYER + WO2_OFF;
        }
    } else if (r < 2592) {
        int tt = r - 1296;
        Kd = CC; Nd = FF;
        n0 = (tt % 72) * 32; k0 = (tt / 72) * 32;
        W = w1 + (long)layer * CC * FF;
        Th = fwh + (long)layer * W2LAYER + W12_OFF;
    } else {
        int tt = r - 2592;
        Kd = FF; Nd = CC;
        n0 = (tt % 18) * 32; k0 = (tt / 18) * 32;
        W = w2 + (long)layer * CC * FF;
        Th = fwh + (long)layer * W2LAYER + W22_OFF;
    }
    int tx = threadIdx.x, ty = threadIdx.y;   // 32 x 8
    #pragma unroll
    for (int rr = 0; rr < 32; rr += 8)
        t[ty + rr][tx] = W[(long)(k0 + ty + rr) * Nd + (n0 + tx)];
    __syncthreads();
    #pragma unroll
    for (int rr = 0; rr < 32; rr += 8) {
        int nn = n0 + ty + rr, kk = k0 + tx;
        float xv = t[tx][ty + rr];
        __half h = __float2half_rn(xv);
        Th[(long)nn * Kd + kk] = h;
        if (Tl) Tl[(long)nn * Kd + kk] = __float2half_rn(xv - __half2float(h));
    }
}

// =================== fused flash attention v7 ===================
// grid (4, BB*NH): CTA pi handles q-tiles (7-pi) then (pi) -> uniform 9 KV-units/CTA.
// S = qh @ kh^T (1-term fp16), base-2 logits; P via ex2.approx.f16x2.
// V fp16 + ones column at dim 72 -> denominator from PV MMA. 3-stage KV ring.
#define FQCH 8192u           // 128 rows x 64B chunk
#define FQB  24576u          // 3 chunks
#define FSTG (2u*FQB)        // 49152: KH VH
#define KVSTG 3
#define FSM  (FQB + KVSTG*FSTG)   // 172032

__global__ void __launch_bounds__(256, 1)
flash_kernel(const __half* __restrict__ qkh,
             const __half* __restrict__ vf,
             const unsigned short* __restrict__ onesv,
             __half* __restrict__ af, float scale2) {   // scale2 = scale * log2(e)
    extern __shared__ char smem[];
    uint32_t sb = smem_u32(smem);
    int tid = threadIdx.x, lane = tid & 31, wid = tid >> 5;
    int z = blockIdx.y, zb = z / NH, zh = z % NH;

    const __half* khb = qkh + (long)(zb * SS) * QKN + CC + zh * DK;
    const __half* vhb = vf + (long)(zb * SS) * CC + zh * DK;

    auto load_kv = [&](int jt) {
        uint32_t st = sb + FQB + (uint32_t)(jt % KVSTG) * FSTG;
        int kbase = jt * 128;
        for (int idx = tid; idx < 1536; idx += 256) {
            int row = idx / 12, rem = idx % 12;
            int c = rem >> 2, g = rem & 3;
            int d0 = c * 32 + g * 8;
            int sz = (d0 + 8 <= DK) ? 16 : 0;
            uint32_t doff = (uint32_t)c * FQCH + swz64((uint32_t)row * 64u + (uint32_t)g * 16u);
            cpasync16(st + doff, khb + (long)(kbase + row) * QKN + d0, sz);
            if (d0 == 72)
                cpasync16(st + FQB + doff, onesv, 16);   // ones column for row-sum
            else
                cpasync16(st + FQB + doff, vhb + (long)(kbase + row) * CC + d0, sz);
        }
    };

    const int lr = lane & 15, lcq = lane >> 4;
    const float NEGINF = __int_as_float(0xff800000);

    #pragma unroll 1
    for (int half = 0; half < 2; half++) {
        int mi = half == 0 ? (7 - (int)blockIdx.x) : (int)blockIdx.x;   // heavy tile first
        int m0 = mi * 128;
        const __half* qhb = qkh + (long)(zb * SS + m0) * QKN + zh * DK;

        // ---- load Q (once per tile) ----
        for (int idx = tid; idx < 128 * 12; idx += 256) {
            int row = idx / 12, rem = idx % 12;
            int c = rem >> 2, g = rem & 3;
            int d0 = c * 32 + g * 8;
            int sz = (d0 + 8 <= DK) ? 16 : 0;
            uint32_t doff = (uint32_t)c * FQCH + swz64((uint32_t)row * 64u + (uint32_t)g * 16u);
            cpasync16(sb + doff, qhb + (long)row * QKN + d0, sz);
        }
        load_kv(0);
        CP_COMMIT();

        float oacc[10][4] = {};
        float rm0 = NEGINF, rm1 = NEGINF;
        int qrow0 = m0 + wid * 16 + (lane >> 2);
        int qrow1 = qrow0 + 8;

        for (int jt = 0; jt <= mi; jt++) {
            if (jt < mi) { load_kv(jt + 1); CP_COMMIT(); CP_WAIT(1); }
            else CP_WAIT(0);
            __syncthreads();     // data ready + stage jt-2 fully consumed

            uint32_t kst = sb + FQB + (uint32_t)(jt % KVSTG) * FSTG;
            uint32_t vst = kst + FQB;

            // ---- S = qh @ kh^T (1-term fp16) ----
            float sacc[16][4] = {};
            #pragma unroll
            for (int c = 0; c < 3; c++) {
                #pragma unroll
                for (int ks = 0; ks < 2; ks++) {
                    if (c == 2 && ks == 1) continue;   // dims 80..95 all zero
                    uint32_t aoff = (uint32_t)c * FQCH
                        + swz64((uint32_t)(wid*16 + lr) * 64u + (uint32_t)(ks*32 + lcq*16));
                    uint32_t qh[4];
                    ldsm4(qh, sb + aoff);
                    #pragma unroll
                    for (int np = 0; np < 8; np++) {
                        uint32_t boff = (uint32_t)c * FQCH
                            + swz64((uint32_t)(np*16 + lr) * 64u + (uint32_t)(ks*32 + lcq*16));
                        uint32_t th[4];
                        ldsm4(th, kst + boff);
                        mma16816(sacc[2*np],   qh, th[0], th[2]);
                        mma16816(sacc[2*np+1], qh, th[1], th[3]);
                    }
                }
            }

            // ---- base-2 scale + causal mask + online softmax ----
            bool diag = (jt == mi);
            int kb = jt * 128 + (lane & 3) * 2;
            float tm0 = NEGINF, tm1 = NEGINF;
            #pragma unroll
            for (int nt = 0; nt < 16; nt++) {
                int k0 = kb + nt * 8, k1 = k0 + 1;
                float s00 = sacc[nt][0] * scale2, s01 = sacc[nt][1] * scale2;
                float s10 = sacc[nt][2] * scale2, s11 = sacc[nt][3] * scale2;
                if (diag) {
                    if (k0 > qrow0) s00 = NEGINF;
                    if (k1 > qrow0) s01 = NEGINF;
                    if (k0 > qrow1) s10 = NEGINF;
                    if (k1 > qrow1) s11 = NEGINF;
                }
                sacc[nt][0] = s00; sacc[nt][1] = s01; sacc[nt][2] = s10; sacc[nt][3] = s11;
                tm0 = fmaxf(tm0, fmaxf(s00, s01));
                tm1 = fmaxf(tm1, fmaxf(s10, s11));
            }
            tm0 = fmaxf(tm0, __shfl_xor_sync(0xffffffffu, tm0, 1));
            tm0 = fmaxf(tm0, __shfl_xor_sync(0xffffffffu, tm0, 2));
            tm1 = fmaxf(tm1, __shfl_xor_sync(0xffffffffu, tm1, 1));
            tm1 = fmaxf(tm1, __shfl_xor_sync(0xffffffffu, tm1, 2));
            float nm0 = fmaxf(rm0, tm0), nm1 = fmaxf(rm1, tm1);
            float cor0 = ex2f(rm0 - nm0), cor1 = ex2f(rm1 - nm1);
            rm0 = nm0; rm1 = nm1;

            uint32_t ph[16][2];
            #pragma unroll
            for (int nt = 0; nt < 16; nt++) {
                ph[nt][0] = ex2h2(sacc[nt][0] - nm0, sacc[nt][1] - nm0);
                ph[nt][1] = ex2h2(sacc[nt][2] - nm1, sacc[nt][3] - nm1);
            }
            #pragma unroll
            for (int nt = 0; nt < 10; nt++) {
                oacc[nt][0] *= cor0; oacc[nt][1] *= cor0;
                oacc[nt][2] *= cor1; oacc[nt][3] *= cor1;
            }

            // ---- O += P @ V (fp16; col 72 = ones -> row sum) ----
            #pragma unroll
            for (int kc = 0; kc < 8; kc++) {
                uint32_t pa[4] = { ph[2*kc][0], ph[2*kc][1], ph[2*kc+1][0], ph[2*kc+1][1] };
                #pragma unroll
                for (int dg = 0; dg < 5; dg++) {
                    uint32_t addr = vst + (uint32_t)(dg >> 1) * FQCH
                        + swz64((uint32_t)(kc*16 + lr) * 64u
                                + (uint32_t)((dg & 1) * 32 + lcq * 16));
                    uint32_t t[4];
                    ldsm4t(t, addr);
                    mma16816(oacc[2*dg], pa, t[0], t[1]);
                    mma16816(oacc[2*dg+1], pa, t[2], t[3]);
                }
            }
        }
        __syncthreads();   // protect Q buffer before next tile's loads

        // ---- finalize: denominator from ones column ----
        int qbase = lane & ~3;
        float rl0 = __shfl_sync(0xffffffffu, oacc[9][0], qbase);
        float rl1 = __shfl_sync(0xffffffffu, oacc[9][2], qbase);
        float inv0 = 1.0f / rl0, inv1 = 1.0f / rl1;
        long base0 = (long)(zb * SS + qrow0) * CC + zh * DK;
        int c0 = (lane & 3) * 2;
        #pragma unroll
        for (int nt = 0; nt < 9; nt++) {
            int d = nt * 8 + c0;
            *(__half2*)&af[base0 + d] =
                __floats2half2_rn(oacc[nt][0] * inv0, oacc[nt][1] * inv0);
            *(__half2*)&af[base0 + 8 * CC + d] =
                __floats2half2_rn(oacc[nt][2] * inv1, oacc[nt][3] * inv1);
        }
    }
}

// =================== HMMA split GEMM ===================
// EPI: 3 +bias+resid fp32 out, 4 plain fp16 out, 6 +bias+GeLU2 fp16 out
template<int EPI, bool A2, bool B2, int NT>
__global__ void __launch_bounds__(256, 1)
hmma_gemm(const uint16_t* __restrict__ Ah, const uint16_t* __restrict__ Al, int lda,
          const uint16_t* __restrict__ Bh, const uint16_t* __restrict__ Bl, int ldb,
          float* __restrict__ C, __half* __restrict__ Ch,
          int ldc,
          const float* __restrict__ bias, const float* __restrict__ resid,
          int M, int N, int K) {
    constexpr int BN = 32 * NT;
    constexpr uint32_t OPA = 8192;
    constexpr uint32_t OPB = (uint32_t)BN * 64;
    constexpr uint32_t OFF_AL = OPA;
    constexpr uint32_t OFF_BH = OPA * (A2 ? 2 : 1);
    constexpr uint32_t OFF_BL = OFF_BH + OPB;
    constexpr uint32_t STAGE = OFF_BH + OPB * (B2 ? 2 : 1);

    int m0 = blockIdx.y * BM, n0 = blockIdx.x * BN;

    extern __shared__ char smem[];
    uint32_t sb = smem_u32(smem);
    int tid = threadIdx.x;

    int nch = (K + BK - 1) / BK;

    auto fill = [&](int chunk) {
        int k0 = chunk * BK;
        uint32_t sbase = sb + (uint32_t)(chunk % STAGES) * STAGE;
        const int ATOT = BM * 4, BTOT = BN * 4;
        for (int idx = tid; idx < ATOT + BTOT; idx += 256) {
            if (idx < ATOT) {
                int row = idx >> 2, gr = idx & 3;
                int kk = k0 + gr * 8;
                int ksz = (kk + 8 <= K) ? 16 : 0;
                uint32_t doff = swz64((uint32_t)row * 64u + (uint32_t)gr * 16u);
                long aoff = (long)(m0 + row) * lda + kk;
                cpasync16(sbase + doff, Ah + aoff, ksz);
                if (A2) cpasync16(sbase + OFF_AL + doff, Al + aoff, ksz);
            } else {
                int j = idx - ATOT;
                int row = j >> 2, gr = j & 3;
                int kk = k0 + gr * 8;
                int nn = n0 + row;
                int bsz = (nn < N && kk + 8 <= K) ? 16 : 0;
                long boff = (long)min(nn, N - 1) * ldb + kk;
                uint32_t doff = swz64((uint32_t)row * 64u + (uint32_t)gr * 16u);
                cpasync16(sbase + OFF_BH + doff, Bh + boff, bsz);
                if (B2) cpasync16(sbase + OFF_BL + doff, Bl + boff, bsz);
            }
        }
    };

    fill(0); CP_COMMIT();
    if (nch > 1) fill(1);
    CP_COMMIT();

    int lane = tid & 31, wid = tid >> 5;
    int wm = wid & 1, wn = wid >> 1;
    int lr = lane & 15, lc = lane >> 4;

    float acc[4][NT][4] = {};

    for (int c = 0; c < nch; c++) {
        if (c + 2 < nch) fill(c + 2);
        CP_COMMIT();
        CP_WAIT(2);
        __syncthreads();
        uint32_t sbase = sb + (uint32_t)(c % STAGES) * STAGE;
        #pragma unroll
        for (int ks = 0; ks < 2; ks++) {
            uint32_t ah[4][4], al[4][4], bh[NT][2], bl[NT][2];
            #pragma unroll
            for (int mt = 0; mt < 4; mt++) {
                uint32_t off = swz64((uint32_t)(wm*64 + mt*16 + lr) * 64u
                                     + (uint32_t)(ks*32 + lc*16));
                ldsm4(ah[mt], sbase + off);
                if (A2) ldsm4(al[mt], sbase + OFF_AL + off);
            }
            #pragma unroll
            for (int np = 0; np < NT/2; np++) {
                uint32_t off = swz64((uint32_t)(wn*(8*NT) + np*16 + lr) * 64u
                                     + (uint32_t)(ks*32 + lc*16));
                uint32_t t[4];
                ldsm4(t, sbase + OFF_BH + off);
                bh[2*np][0] = t[0]; bh[2*np+1][0] = t[1];
                bh[2*np][1] = t[2]; bh[2*np+1][1] = t[3];
                if (B2) {
                    ldsm4(t, sbase + OFF_BL + off);
                    bl[2*np][0] = t[0]; bl[2*np+1][0] = t[1];
                    bl[2*np][1] = t[2]; bl[2*np+1][1] = t[3];
                }
            }
            #pragma unroll
            for (int mt = 0; mt < 4; mt++)
                #pragma unroll
                for (int nt = 0; nt < NT; nt++) {
                    mma16816(acc[mt][nt], ah[mt], bh[nt][0], bh[nt][1]);
                    if (B2) mma16816(acc[mt][nt], ah[mt], bl[nt][0], bl[nt][1]);
                    if (A2) mma16816(acc[mt][nt], al[mt], bh[nt][0], bh[nt][1]);
                }
        }
        __syncthreads();
    }

    int r0 = lane >> 2, c0 = (lane & 3) * 2;
    #pragma unroll
    for (int mt = 0; mt < 4; mt++) {
        #pragma unroll
        for (int nt = 0; nt < NT; nt++) {
            int gn = n0 + wn*(8*NT) + nt*8 + c0;
            if (gn >= N) continue;
            int gmb = m0 + wm*64 + mt*16 + r0;
            float* ac = acc[mt][nt];
            #pragma unroll
            for (int h2 = 0; h2 < 2; h2++) {
                int gm = gmb + h2 * 8;
                float v0 = ac[h2*2 + 0];
                float v1 = ac[h2*2 + 1];
                long off = (long)gm * ldc + gn;
                if (EPI == 3) {
                    float2 r = *(const float2*)&resid[off];
                    v0 += bias[gn] + r.x;
                    v1 += bias[gn + 1] + r.y;
                    *(float2*)&C[off] = make_float2(v0, v1);
                } else if (EPI == 4) {
                    __half2 o2;
                    o2.x = __float2half_rn(v0);
                    o2.y = __float2half_rn(v1);
                    *(__half2*)&Ch[off] = o2;
                } else if (EPI == 6) {
                    v0 += bias[gn]; v1 += bias[gn + 1];
                    v0 = v0 / (1.f + __expf(-1.702f * v0));
                    v1 = v1 / (1.f + __expf(-1.702f * v1));
                    __half2 o2;
                    o2.x = __float2half_rn(v0);
                    o2.y = __float2half_rn(v1);
                    *(__half2*)&((__half*)C)[off] = o2;
                }
            }
        }
    }
}

#define SM_QK   73728   // 3*(8192 + 2*8192)      A1 B2 NT4
#define SM_N2   36864   // 3*(8192 + 4096)        A1 B1 NT2
#define SM_F1   49152   // 3*(8192 + 8192)        A1 B1 NT4

// ---------------- host orchestration ----------------
extern "C" void kernel_launch(void* const* d_in, const int* in_sizes, int n_in,
                              void* d_out, int out_size) {
    (void)in_sizes; (void)n_in; (void)out_size;
    const float* x     = (const float*)d_in[0];
    const float* pos0  = (const float*)d_in[1];
    const float* pos1  = (const float*)d_in[2];
    const float* pos2  = (const float*)d_in[3];
    const float* ln1_g = (const float*)d_in[4];
    const float* ln1_b = (const float*)d_in[5];
    const float* wq    = (const float*)d_in[6];
    const float* wk    = (const float*)d_in[7];
    const float* wv    = (const float*)d_in[8];
    const float* wo    = (const float*)d_in[9];
    const float* wo_b  = (const float*)d_in[10];
    const float* ln2_g = (const float*)d_in[11];
    const float* ln2_b = (const float*)d_in[12];
    const float* w1    = (const float*)d_in[13];
    const float* b1    = (const float*)d_in[14];
    const float* w2    = (const float*)d_in[15];
    const float* b2    = (const float*)d_in[16];

    float *xf;
    __half *hh,*qkh,*vf,*af,*ffn,*wth,*wtl,*fwh;
    unsigned short* onesv;
    cudaGetSymbolAddress((void**)&xf,   g_xf);
    cudaGetSymbolAddress((void**)&hh,   g_hh);
    cudaGetSymbolAddress((void**)&qkh,  g_qkh);
    cudaGetSymbolAddress((void**)&vf,   g_vf);
    cudaGetSymbolAddress((void**)&af,   g_af);
    cudaGetSymbolAddress((void**)&ffn,  g_ffn);
    cudaGetSymbolAddress((void**)&wth,  g_wth);  cudaGetSymbolAddress((void**)&wtl,  g_wtl);
    cudaGetSymbolAddress((void**)&fwh,  g_fwh);
    cudaGetSymbolAddress((void**)&onesv, g_ones);

    auto kQK    = hmma_gemm<4,false,true ,4>;   // fp16 out, 2-term (weights split)
    auto kV     = hmma_gemm<4,false,false,4>;   // fp16 out, 1-term
    auto kWO    = hmma_gemm<3,false,false,2>;   // fp32 +bias+resid, 1-term
    auto kFFN1  = hmma_gemm<6,false,false,4>;   // fp16 +bias+gelu, 1-term
    auto kFFN2  = hmma_gemm<3,false,false,2>;   // fp32 +bias+resid, 1-term

    cudaFuncSetAttribute(kQK,   cudaFuncAttributeMaxDynamicSharedMemorySize, SM_QK);
    cudaFuncSetAttribute(kV,    cudaFuncAttributeMaxDynamicSharedMemorySize, SM_F1);
    cudaFuncSetAttribute(kWO,   cudaFuncAttributeMaxDynamicSharedMemorySize, SM_N2);
    cudaFuncSetAttribute(kFFN1, cudaFuncAttributeMaxDynamicSharedMemorySize, SM_F1);
    cudaFuncSetAttribute(kFFN2, cudaFuncAttributeMaxDynamicSharedMemorySize, SM_N2);
    cudaFuncSetAttribute(flash_kernel, cudaFuncAttributeMaxDynamicSharedMemorySize, FSM);

    const float scale2 = (1.0f / sqrtf((float)DK)) * 1.4426950408889634f;
    long n_elem = (long)MM * CC;
    int nb = (int)((n_elem + 255) / 256);

    shiftpos_kernel<<<nb, 256>>>(x, pos0, pos1, pos2, xf);
    wtrans_all_kernel<<<LL * TPL, dim3(32, 8)>>>(wq, wk, wv, wo, w1, w2, wth, wtl, fwh);

    dim3 gQK(QKN/128, MM/BM, 1);               // (9, 32) — 288 CTAs
    dim3 gV((CC + 127)/128, MM/BM, 1);         // (5, 32)
    dim3 gFlash(4, BB*NH);                     // (4, 32) — 128 CTAs, balanced pairs
    dim3 gN2(CC/64, MM/BM, 1);                 // (9, 32)
    dim3 gF1(FF/128, MM/BM, 1);                // (18, 32)

    for (int l = 0; l < LL; l++) {
        long wb = (long)l * WLAYER;
        long fb = (long)l * W2LAYER;
        // --- attention ---
        layernorm_kernel<<<MM/8, 256>>>(xf, ln1_g + l*CC, ln1_b + l*CC, hh);
        kQK<<<gQK, 256, SM_QK>>>(
            (const uint16_t*)hh, nullptr, CC,
            (const uint16_t*)(wth + wb), (const uint16_t*)(wtl + wb), CC,
            nullptr, qkh, QKN, nullptr, nullptr, MM, QKN, CC);
        kV<<<gV, 256, SM_F1>>>(
            (const uint16_t*)hh, nullptr, CC,
            (const uint16_t*)(fwh + fb + WV2_OFF), nullptr, CC,
            nullptr, vf, CC, nullptr, nullptr, MM, CC, CC);
        flash_kernel<<<gFlash, 256, FSM>>>(qkh, vf, onesv, af, scale2);
        kWO<<<gN2, 256, SM_N2>>>(
            (const uint16_t*)af, nullptr, CC,
            (const uint16_t*)(fwh + fb + WO2_OFF), nullptr, CC,
            xf, nullptr, CC, wo_b + l*CC, xf, MM, CC, CC);

        // --- FFN ---
        layernorm_kernel<<<MM/8, 256>>>(xf, ln2_g + l*CC, ln2_b + l*CC, hh);
        kFFN1<<<gF1, 256, SM_F1>>>(
            (const uint16_t*)hh, nullptr, CC,
            (const uint16_t*)(fwh + fb + W12_OFF), nullptr, CC,
            (float*)ffn, nullptr, FF, b1 + (long)l*FF, nullptr, MM, FF, CC);
        float* outp = (l == LL - 1) ? (float*)d_out : xf;
        kFFN2<<<gN2, 256, SM_N2>>>(
            (const uint16_t*)ffn, nullptr, FF,
            (const uint16_t*)(fwh + fb + W22_OFF), nullptr, FF,
            outp, nullptr, CC, b2 + (long)l*CC, xf, MM, CC, FF);
    }
}